// round 6
// baseline (speedup 1.0000x reference)
#include <cuda_runtime.h>
#include <math.h>
#include <float.h>
#include <stdint.h>

#define BSZ 8192
#define FDIM 2048
#define DDIM 1024
#define HDIM 3072

// ---------------- scratch ------------------------------------------------------
__device__ float g_proj[(size_t)3 * BSZ * DDIM];
__device__ float g_Qn[(size_t)BSZ * DDIM];
__device__ float g_Cn[(size_t)BSZ * DDIM];
__device__ float g_S[16777216ull];
__device__ float g_h[(size_t)BSZ * DDIM];
__device__ float g_Wt[(size_t)3 * DDIM * FDIM];    // W^T per modality [1024][2048]
__device__ float g_W1t[(size_t)DDIM * HDIM];       // W1^T [1024][3072]
__device__ float g_nrm[BSZ];
__device__ int   g_glist[3][BSZ];
__device__ int   g_qidx[3][BSZ];
__device__ int   g_qrow[3][BSZ];
__device__ int   g_cidx[3][BSZ];
__device__ int   g_crow[3][BSZ];
__device__ int   g_cnt[3][4];

// ---------------- tf32 helpers ---------------------------------------------------
__device__ __forceinline__ float tf32hi(float x) {
    uint32_t u;
    asm("cvt.rna.tf32.f32 %0, %1;" : "=r"(u) : "f"(x));
    return __uint_as_float(u);
}
__device__ __forceinline__ void mma8(float* d, const uint32_t* a, const uint32_t* b) {
    asm volatile(
        "mma.sync.aligned.m16n8k8.row.col.f32.tf32.tf32.f32 "
        "{%0,%1,%2,%3}, {%4,%5,%6,%7}, {%8,%9}, {%0,%1,%2,%3};"
        : "+f"(d[0]), "+f"(d[1]), "+f"(d[2]), "+f"(d[3])
        : "r"(a[0]), "r"(a[1]), "r"(a[2]), "r"(a[3]), "r"(b[0]), "r"(b[1]));
}

// ---------------- GEMM core: CTA 128x64, 512 threads, warp tile 32x16 ------------
// k-chunk 16, 2-stage smem, fragment-permuted layout, hi/lo split at STS.
// LIMBS=2: 3-term tf32 emulation (Ah*Bl + Al*Bh + Ah*Bh). LIMBS=1: raw 1-pass.
template<int LIMBS>
__device__ __forceinline__ void gemm_core(
    const float* __restrict__ A, int ldA, int projA,
    const float* __restrict__ Bt, int ldB,
    int m0, int n0, int Mlim, int Nlim, int K, float acc[2][2][4])
{
    __shared__ float sA[2][LIMBS][2048];
    __shared__ float sB[2][LIMBS][1024];
    const int tid = threadIdx.x;
    const int lane = tid & 31, wid = tid >> 5;
    const int wr = wid & 3, wc = wid >> 2;           // warp m-block, n-block
    const int am = tid >> 2, akq = tid & 3;          // A staging: m 0..127
    const int bn = (tid & 255) >> 2, bkq = tid & 3;  // B staging: n 0..63
    const bool doB = tid < 256;
    // fragment-permuted store bases (float index); j stride = 4 (A), 2 (B)
    const int aBase = (((akq >> 1) * 8 + (am >> 4)) * 32 + (am & 7) * 4) * 4
                    + (akq & 1) * 2 + ((am >> 3) & 1);
    const int bBase = (((bkq >> 1) * 8 + (bn >> 3)) * 32 + (bn & 7) * 4) * 2
                    + (bkq & 1);
    const float4 z4 = make_float4(0.f, 0.f, 0.f, 0.f);
    float4 va, vb;
    const int nch = K / 16;

    auto load = [&](int ic) {
        const int kc = ic * 16;
        const float* Ab = projA
            ? g_proj + (size_t)(kc >> 10) * BSZ * DDIM + (kc & 1023)
            : A + kc;
        va = (m0 + am < Mlim)
            ? *(const float4*)(Ab + (size_t)(m0 + am) * ldA + akq * 4) : z4;
        if (doB)
            vb = (n0 + bn < Nlim)
                ? *(const float4*)(Bt + (size_t)(n0 + bn) * ldB + kc + bkq * 4) : z4;
    };
    auto sts = [&](int buf) {
        float* pa = &sA[buf][0][aBase];
        if (LIMBS == 2) {
            const float hx = tf32hi(va.x), hy = tf32hi(va.y);
            const float hz = tf32hi(va.z), hw = tf32hi(va.w);
            pa[0] = hx; pa[4] = hy; pa[8] = hz; pa[12] = hw;
            float* pl = &sA[buf][1][aBase];
            pl[0] = va.x - hx; pl[4] = va.y - hy; pl[8] = va.z - hz; pl[12] = va.w - hw;
        } else {
            pa[0] = va.x; pa[4] = va.y; pa[8] = va.z; pa[12] = va.w;
        }
        if (doB) {
            float* pb = &sB[buf][0][bBase];
            if (LIMBS == 2) {
                const float hx = tf32hi(vb.x), hy = tf32hi(vb.y);
                const float hz = tf32hi(vb.z), hw = tf32hi(vb.w);
                pb[0] = hx; pb[2] = hy; pb[4] = hz; pb[6] = hw;
                float* pl = &sB[buf][1][bBase];
                pl[0] = vb.x - hx; pl[2] = vb.y - hy; pl[4] = vb.z - hz; pl[6] = vb.w - hw;
            } else {
                pb[0] = vb.x; pb[2] = vb.y; pb[4] = vb.z; pb[6] = vb.w;
            }
        }
    };

    load(0); sts(0); __syncthreads();
    for (int ic = 0; ic < nch; ic++) {
        const int buf = ic & 1;
        const bool more = (ic + 1) < nch;
        if (more) load(ic + 1);
        #pragma unroll
        for (int s = 0; s < 2; s++) {
            float4 Ah[2], Al[2];
            float2 Bh[2], Bl[2];
            #pragma unroll
            for (int mt = 0; mt < 2; mt++) {
                Ah[mt] = *(const float4*)&sA[buf][0][((s * 8 + wr * 2 + mt) * 32 + lane) * 4];
                if (LIMBS == 2)
                    Al[mt] = *(const float4*)&sA[buf][1][((s * 8 + wr * 2 + mt) * 32 + lane) * 4];
            }
            #pragma unroll
            for (int nt = 0; nt < 2; nt++) {
                Bh[nt] = *(const float2*)&sB[buf][0][((s * 8 + wc * 2 + nt) * 32 + lane) * 2];
                if (LIMBS == 2)
                    Bl[nt] = *(const float2*)&sB[buf][1][((s * 8 + wc * 2 + nt) * 32 + lane) * 2];
            }
            #pragma unroll
            for (int mt = 0; mt < 2; mt++)
                #pragma unroll
                for (int nt = 0; nt < 2; nt++) {
                    if (LIMBS == 2) {
                        mma8(acc[mt][nt], (const uint32_t*)&Ah[mt], (const uint32_t*)&Bl[nt]);
                        mma8(acc[mt][nt], (const uint32_t*)&Al[mt], (const uint32_t*)&Bh[nt]);
                    }
                    mma8(acc[mt][nt], (const uint32_t*)&Ah[mt], (const uint32_t*)&Bh[nt]);
                }
        }
        if (more) { sts(buf ^ 1); __syncthreads(); }
    }
}

// ---------------- proj GEMM (3-term): C = X @ Wt^T + b ---------------------------
__global__ void __launch_bounds__(512) tgemm_proj(
    int mode, const float* __restrict__ A, const float* __restrict__ bias)
{
    const int m0 = blockIdx.y * 128, n0 = blockIdx.x * 64;
    float acc[2][2][4] = {};
    gemm_core<2>(A, FDIM, 0, g_Wt + (size_t)mode * DDIM * FDIM, FDIM,
                 m0, n0, 1 << 30, 1 << 30, FDIM, acc);
    float* __restrict__ out = g_proj + (size_t)mode * BSZ * DDIM;
    const int lane = threadIdx.x & 31, wid = threadIdx.x >> 5;
    const int wr = wid & 3, wc = wid >> 2;
    #pragma unroll
    for (int mt = 0; mt < 2; mt++) {
        const int r = m0 + wr * 32 + mt * 16 + (lane >> 2);
        #pragma unroll
        for (int nt = 0; nt < 2; nt++) {
            const int c = n0 + wc * 16 + nt * 8 + (lane & 3) * 2;
            const float2 bv = *(const float2*)(bias + c);
            *(float2*)(out + (size_t)r * DDIM + c) =
                make_float2(acc[mt][nt][0] + bv.x, acc[mt][nt][1] + bv.y);
            *(float2*)(out + (size_t)(r + 8) * DDIM + c) =
                make_float2(acc[mt][nt][2] + bv.x, acc[mt][nt][3] + bv.y);
        }
    }
}

// ---------------- mlp1 GEMM (1-pass tf32): h = relu(concat(proj) @ W1 + b1) ------
__global__ void __launch_bounds__(512) tgemm_mlp1(const float* __restrict__ bias)
{
    const int m0 = blockIdx.y * 128, n0 = blockIdx.x * 64;
    float acc[2][2][4] = {};
    gemm_core<1>(nullptr, DDIM, 1, g_W1t, HDIM,
                 m0, n0, 1 << 30, 1 << 30, HDIM, acc);
    const int lane = threadIdx.x & 31, wid = threadIdx.x >> 5;
    const int wr = wid & 3, wc = wid >> 2;
    #pragma unroll
    for (int mt = 0; mt < 2; mt++) {
        const int r = m0 + wr * 32 + mt * 16 + (lane >> 2);
        #pragma unroll
        for (int nt = 0; nt < 2; nt++) {
            const int c = n0 + wc * 16 + nt * 8 + (lane & 3) * 2;
            const float2 bv = *(const float2*)(bias + c);
            *(float2*)(g_h + (size_t)r * DDIM + c) =
                make_float2(fmaxf(acc[mt][nt][0] + bv.x, 0.f),
                            fmaxf(acc[mt][nt][1] + bv.y, 0.f));
            *(float2*)(g_h + (size_t)(r + 8) * DDIM + c) =
                make_float2(fmaxf(acc[mt][nt][2] + bv.x, 0.f),
                            fmaxf(acc[mt][nt][3] + bv.y, 0.f));
        }
    }
}

// ---------------- sim GEMM (3-term): S[nq,nc] = Qn @ Cn^T -------------------------
__global__ void __launch_bounds__(512) tgemm_sim(int m) {
    const int M = g_cnt[m][1], N = g_cnt[m][2];
    const int m0 = blockIdx.y * 128, n0 = blockIdx.x * 64;
    if (m0 >= M || n0 >= N) return;
    float acc[2][2][4] = {};
    gemm_core<2>(g_Qn, DDIM, 0, g_Cn, DDIM, m0, n0, M, N, DDIM, acc);
    const int lane = threadIdx.x & 31, wid = threadIdx.x >> 5;
    const int wr = wid & 3, wc = wid >> 2;
    #pragma unroll
    for (int mt = 0; mt < 2; mt++) {
        const int r0 = m0 + wr * 32 + mt * 16 + (lane >> 2);
        const int r1 = r0 + 8;
        #pragma unroll
        for (int nt = 0; nt < 2; nt++) {
            const int c = n0 + wc * 16 + nt * 8 + (lane & 3) * 2;
            if (r0 < M) {
                if (c < N)     g_S[(size_t)r0 * N + c]     = acc[mt][nt][0];
                if (c + 1 < N) g_S[(size_t)r0 * N + c + 1] = acc[mt][nt][1];
            }
            if (r1 < M) {
                if (c < N)     g_S[(size_t)r1 * N + c]     = acc[mt][nt][2];
                if (c + 1 < N) g_S[(size_t)r1 * N + c + 1] = acc[mt][nt][3];
            }
        }
    }
}

// ---------------- transpose weights: W[K][1024] -> Wt[1024][K] --------------------
__global__ void __launch_bounds__(256) transW(
    const float* __restrict__ W, float* __restrict__ Wt, int K)
{
    __shared__ float t[32][33];
    const int n0 = blockIdx.x * 32, k0 = blockIdx.y * 32;
    const int tx = threadIdx.x & 31, ty = threadIdx.x >> 5;
    #pragma unroll
    for (int j = 0; j < 4; j++)
        t[ty + j * 8][tx] = W[(size_t)(k0 + ty + j * 8) * DDIM + n0 + tx];
    __syncthreads();
    #pragma unroll
    for (int j = 0; j < 4; j++) {
        const int row = ty + j * 8;
        Wt[(size_t)(n0 + row) * K + k0 + tx] = t[tx][row];
    }
}

// ---------------- setup: masks, scans, compacted index lists ---------------------
__global__ void __launch_bounds__(1024) setup_kernel(const int* __restrict__ missing) {
    __shared__ int sh[1024];
    const int t = threadIdx.x;
    const int base = t * 8;
    for (int m = 0; m < 3; m++) {
        const int tag = m + 1;
        int a[8];
        int cnt = 0;
        #pragma unroll
        for (int j = 0; j < 8; j++) { a[j] = (missing[base + j] != tag) ? 1 : 0; cnt += a[j]; }
        sh[t] = cnt; __syncthreads();
        for (int off = 1; off < 1024; off <<= 1) {
            int v = (t >= off) ? sh[t - off] : 0; __syncthreads();
            sh[t] += v; __syncthreads();
        }
        const int Nb = sh[1023];
        int pos = sh[t] - cnt;
        #pragma unroll
        for (int j = 0; j < 8; j++) if (a[j]) g_glist[m][pos++] = base + j;
        if (t == 0) g_cnt[m][0] = Nb;
        __syncthreads();
        int qf[8]; cnt = 0;
        #pragma unroll
        for (int j = 0; j < 8; j++) {
            qf[j] = ((missing[base + j] == tag) && (base + j < Nb)) ? 1 : 0; cnt += qf[j];
        }
        sh[t] = cnt; __syncthreads();
        for (int off = 1; off < 1024; off <<= 1) {
            int v = (t >= off) ? sh[t - off] : 0; __syncthreads();
            sh[t] += v; __syncthreads();
        }
        const int nq = sh[1023];
        pos = sh[t] - cnt;
        #pragma unroll
        for (int j = 0; j < 8; j++) if (qf[j]) {
            g_qidx[m][pos] = base + j;
            g_qrow[m][pos] = g_glist[m][base + j];
            pos++;
        }
        if (t == 0) g_cnt[m][1] = nq;
        __syncthreads();
        int cf[8]; cnt = 0;
        #pragma unroll
        for (int j = 0; j < 8; j++) { cf[j] = (a[j] && (base + j < Nb)) ? 1 : 0; cnt += cf[j]; }
        sh[t] = cnt; __syncthreads();
        for (int off = 1; off < 1024; off <<= 1) {
            int v = (t >= off) ? sh[t - off] : 0; __syncthreads();
            sh[t] += v; __syncthreads();
        }
        const int nc = sh[1023];
        pos = sh[t] - cnt;
        #pragma unroll
        for (int j = 0; j < 8; j++) if (cf[j]) {
            g_cidx[m][pos] = base + j;
            g_crow[m][pos] = g_glist[m][base + j];
            pos++;
        }
        if (t == 0) g_cnt[m][2] = nc;
        __syncthreads();
    }
}

// ---------------- per-bank-row L2 norms --------------------------------------------
__global__ void __launch_bounds__(256) knorm(int m) {
    const int i = blockIdx.x;
    if (i >= g_cnt[m][0]) return;
    const int row = g_glist[m][i];
    const float4* p = reinterpret_cast<const float4*>(
        g_proj + (size_t)m * BSZ * DDIM + (size_t)row * DDIM);
    float4 v = p[threadIdx.x];
    float s = v.x * v.x + v.y * v.y + v.z * v.z + v.w * v.w;
    #pragma unroll
    for (int off = 16; off > 0; off >>= 1) s += __shfl_down_sync(0xffffffffu, s, off);
    __shared__ float red[8];
    if ((threadIdx.x & 31) == 0) red[threadIdx.x >> 5] = s;
    __syncthreads();
    if (threadIdx.x == 0) {
        float tot = 0.f;
        #pragma unroll
        for (int w = 0; w < 8; w++) tot += red[w];
        g_nrm[i] = fmaxf(__fsqrt_rn(tot), 1e-8f);
    }
}

// ---------------- gather normalized query / candidate matrices ---------------------
__global__ void __launch_bounds__(256) kgather(int m) {
    const int i = blockIdx.x, t = threadIdx.x;
    const float* __restrict__ projm = g_proj + (size_t)m * BSZ * DDIM;
    if (i < g_cnt[m][1]) {
        const float nr = g_nrm[g_qidx[m][i]];
        float4 v = reinterpret_cast<const float4*>(projm + (size_t)g_qrow[m][i] * DDIM)[t];
        float4 o = make_float4(__fdiv_rn(v.x, nr), __fdiv_rn(v.y, nr),
                               __fdiv_rn(v.z, nr), __fdiv_rn(v.w, nr));
        reinterpret_cast<float4*>(g_Qn + (size_t)i * DDIM)[t] = o;
    }
    if (i < g_cnt[m][2]) {
        const float nr = g_nrm[g_cidx[m][i]];
        float4 v = reinterpret_cast<const float4*>(projm + (size_t)g_crow[m][i] * DDIM)[t];
        float4 o = make_float4(__fdiv_rn(v.x, nr), __fdiv_rn(v.y, nr),
                               __fdiv_rn(v.z, nr), __fdiv_rn(v.w, nr));
        reinterpret_cast<float4*>(g_Cn + (size_t)i * DDIM)[t] = o;
    }
}

// ---------------- zero rows: missing && b >= Nb -------------------------------------
__global__ void __launch_bounds__(256) kzero(const int* __restrict__ missing, int m) {
    const int b = blockIdx.x;
    if (missing[b] != m + 1) return;
    if (b < g_cnt[m][0]) return;
    reinterpret_cast<float4*>(g_proj + (size_t)m * BSZ * DDIM + (size_t)b * DDIM)[threadIdx.x] =
        make_float4(0.f, 0.f, 0.f, 0.f);
}

// ---------------- top-3 + softmax + weighted gather, in-place fill ------------------
__global__ void __launch_bounds__(256) ktopk(int m) {
    const int q = blockIdx.x;
    const int nq = g_cnt[m][1];
    if (q >= nq) return;
    const int nc = g_cnt[m][2];
    const int t = threadIdx.x;
    float* __restrict__ projm = g_proj + (size_t)m * BSZ * DDIM;
    float* __restrict__ dst = projm + (size_t)g_qidx[m][q] * DDIM;
    if (nc == 0) {
        reinterpret_cast<float4*>(dst)[t] = make_float4(0.f, 0.f, 0.f, 0.f);
        return;
    }
    const float NEGINF = -INFINITY;
    const float* __restrict__ Srow = g_S + (size_t)q * nc;
    float v0 = NEGINF, v1 = NEGINF, v2 = NEGINF;
    int   i0 = 0x7fffffff, i1 = 0x7fffffff, i2 = 0x7fffffff;
    for (int c = t; c < nc; c += 256) {
        float v = Srow[c];
        if (v > v2) {
            if (v > v1) {
                if (v > v0) { v2 = v1; i2 = i1; v1 = v0; i1 = i0; v0 = v; i0 = c; }
                else        { v2 = v1; i2 = i1; v1 = v;  i1 = c; }
            } else          { v2 = v;  i2 = c; }
        }
    }
    __shared__ float sv[768];
    __shared__ int   si[768];
    sv[t] = v0; sv[256 + t] = v1; sv[512 + t] = v2;
    si[t] = i0; si[256 + t] = i1; si[512 + t] = i2;
    __syncthreads();
    __shared__ float fw[3];
    __shared__ int   fr[3];
    if (t == 0) {
        float b0 = NEGINF, b1 = NEGINF, b2 = NEGINF;
        int   j0 = 0x7fffffff, j1 = 0x7fffffff, j2 = 0x7fffffff;
        for (int e = 0; e < 768; e++) {
            float v = sv[e]; int c = si[e];
            if ((v > b2) || (v == b2 && c < j2)) {
                if ((v > b1) || (v == b1 && c < j1)) {
                    if ((v > b0) || (v == b0 && c < j0)) {
                        b2 = b1; j2 = j1; b1 = b0; j1 = j0; b0 = v; j0 = c;
                    } else { b2 = b1; j2 = j1; b1 = v; j1 = c; }
                } else     { b2 = v; j2 = c; }
            }
        }
        float w0 = 1.0f;
        float w1 = (b1 == NEGINF) ? 0.f : expf(b1 - b0);
        float w2 = (b2 == NEGINF) ? 0.f : expf(b2 - b0);
        float ws = w0 + w1 + w2;
        fw[0] = __fdiv_rn(w0, ws); fw[1] = __fdiv_rn(w1, ws); fw[2] = __fdiv_rn(w2, ws);
        fr[0] = (j0 == 0x7fffffff) ? 0 : g_crow[m][j0];
        fr[1] = (j1 == 0x7fffffff) ? 0 : g_crow[m][j1];
        fr[2] = (j2 == 0x7fffffff) ? 0 : g_crow[m][j2];
    }
    __syncthreads();
    const float w0 = fw[0], w1 = fw[1], w2 = fw[2];
    float4 a = reinterpret_cast<const float4*>(projm + (size_t)fr[0] * DDIM)[t];
    float4 b = reinterpret_cast<const float4*>(projm + (size_t)fr[1] * DDIM)[t];
    float4 c = reinterpret_cast<const float4*>(projm + (size_t)fr[2] * DDIM)[t];
    float4 o;
    o.x = w0 * a.x + w1 * b.x + w2 * c.x;
    o.y = w0 * a.y + w1 * b.y + w2 * c.y;
    o.z = w0 * a.z + w1 * b.z + w2 * c.z;
    o.w = w0 * a.w + w1 * b.w + w2 * c.w;
    reinterpret_cast<float4*>(dst)[t] = o;
}

// ---------------- MLP layer 2: out = h @ W2 + b2 -----------------------------------
__global__ void __launch_bounds__(256) kmlp2(
    const float* __restrict__ W2, const float* __restrict__ b2, float* __restrict__ out)
{
    const int b = blockIdx.x, t = threadIdx.x;
    float4 h = reinterpret_cast<const float4*>(g_h + (size_t)b * DDIM)[t];
    float4 w = reinterpret_cast<const float4*>(W2)[t];
    float s = h.x * w.x + h.y * w.y + h.z * w.z + h.w * w.w;
    #pragma unroll
    for (int off = 16; off > 0; off >>= 1) s += __shfl_down_sync(0xffffffffu, s, off);
    __shared__ float red[8];
    if ((t & 31) == 0) red[t >> 5] = s;
    __syncthreads();
    if (t == 0) {
        float tot = 0.f;
        #pragma unroll
        for (int wq = 0; wq < 8; wq++) tot += red[wq];
        out[b] = tot + b2[0];
    }
}

// ---------------- launch -------------------------------------------------------------
extern "C" void kernel_launch(void* const* d_in, const int* in_sizes, int n_in,
                              void* d_out, int out_size) {
    const float* x[3]  = { (const float*)d_in[0], (const float*)d_in[1], (const float*)d_in[2] };
    const int* missing = (const int*)d_in[3];
    const float* W[3]  = { (const float*)d_in[4], (const float*)d_in[6], (const float*)d_in[8] };
    const float* bb[3] = { (const float*)d_in[5], (const float*)d_in[7], (const float*)d_in[9] };
    const float* W1 = (const float*)d_in[10];
    const float* b1 = (const float*)d_in[11];
    const float* W2 = (const float*)d_in[12];
    const float* b2 = (const float*)d_in[13];
    float* out = (float*)d_out;

    float* wtd = nullptr;
    cudaGetSymbolAddress((void**)&wtd, g_Wt);
    float* w1td = nullptr;
    cudaGetSymbolAddress((void**)&w1td, g_W1t);
    // transW first so ncu -s 5 lands on a big GEMM launch
    for (int m = 0; m < 3; m++)
        transW<<<dim3(32, FDIM / 32), 256>>>(W[m], wtd + (size_t)m * DDIM * FDIM, FDIM);
    transW<<<dim3(32, HDIM / 32), 256>>>(W1, w1td, HDIM);

    setup_kernel<<<1, 1024>>>(missing);

    dim3 gp(DDIM / 64, BSZ / 128);                  // (16, 64)
    for (int m = 0; m < 3; m++)
        tgemm_proj<<<gp, 512>>>(m, x[m], bb[m]);

    dim3 gs(128, 64);                               // early-exit on runtime dims
    for (int m = 0; m < 3; m++) {
        knorm<<<BSZ, 256>>>(m);
        kgather<<<BSZ, 256>>>(m);
        kzero<<<BSZ, 256>>>(missing, m);
        tgemm_sim<<<gs, 512>>>(m);
        ktopk<<<BSZ, 256>>>(m);
    }

    tgemm_mlp1<<<gp, 512>>>(b1);
    kmlp2<<<BSZ, 256>>>(W2, b2, out);
}

// round 7
// speedup vs baseline: 1.3268x; 1.3268x over previous
#include <cuda_runtime.h>
#include <math.h>
#include <float.h>
#include <stdint.h>

#define BSZ 8192
#define FDIM 2048
#define DDIM 1024
#define HDIM 3072

// ---------------- scratch ------------------------------------------------------
__device__ float g_proj[(size_t)3 * BSZ * DDIM];
__device__ float g_Qn[(size_t)BSZ * DDIM];
__device__ float g_Cn[(size_t)BSZ * DDIM];
__device__ float g_S[16777216ull];
__device__ float g_h[(size_t)BSZ * DDIM];
__device__ float g_Wt[(size_t)3 * DDIM * FDIM];    // W^T per modality [1024][2048]
__device__ float g_W1t[(size_t)DDIM * HDIM];       // W1^T [1024][3072]
__device__ float g_nrm[BSZ];
__device__ int   g_glist[3][BSZ];
__device__ int   g_qidx[3][BSZ];
__device__ int   g_qrow[3][BSZ];
__device__ int   g_cidx[3][BSZ];
__device__ int   g_crow[3][BSZ];
__device__ int   g_cnt[3][4];

// ---------------- tf32 helpers ---------------------------------------------------
__device__ __forceinline__ float tf32hi(float x) {
    uint32_t u;
    asm("cvt.rna.tf32.f32 %0, %1;" : "=r"(u) : "f"(x));
    return __uint_as_float(u);
}
__device__ __forceinline__ void mma8(float* d, const float* a, const float* b) {
    asm volatile(
        "mma.sync.aligned.m16n8k8.row.col.f32.tf32.tf32.f32 "
        "{%0,%1,%2,%3}, {%4,%5,%6,%7}, {%8,%9}, {%0,%1,%2,%3};"
        : "+f"(d[0]), "+f"(d[1]), "+f"(d[2]), "+f"(d[3])
        : "r"(__float_as_uint(a[0])), "r"(__float_as_uint(a[1])),
          "r"(__float_as_uint(a[2])), "r"(__float_as_uint(a[3])),
          "r"(__float_as_uint(b[0])), "r"(__float_as_uint(b[1])));
}

// ---------------- GEMM core: CTA 128x128, 256 threads, warp tile 64x32 -----------
// k-chunk 8, double-buffered smem, fragment-permuted layout, hi/lo split at STS.
// 3-term tf32 emulation: Ah*Bl + Al*Bh + Ah*Bh (lo limbs stored as raw residuals;
// tf32 HW truncation of lo costs only ~2^-24 relative).
// A layout: float idx = ((m>>4)*32 + (m&7)*4 + (k&3))*4 + (k>>2)*2 + ((m>>3)&1)
// B layout: float idx = ((n>>3)*32 + (n&7)*4 + (k&3))*2 + (k>>2)
__device__ __forceinline__ void gemm_core(
    const float* __restrict__ A, int ldA, int projA,
    const float* __restrict__ Bt, int ldB,
    int m0, int n0, int Mlim, int Nlim, int K, float acc[4][4][4])
{
    __shared__ float sA[2][2][1024];
    __shared__ float sB[2][2][1024];
    const int tid = threadIdx.x;
    const int lane = tid & 31, wid = tid >> 5;
    const int wr = wid & 1, wc = wid >> 1;      // warp m-half (x64), n-quarter (x32)
    const int sm = tid >> 1, skq = tid & 1;     // staging: row 0..127, k-quad 0..1
    const float4 z4 = make_float4(0.f, 0.f, 0.f, 0.f);
    float4 va, vb;
    const int nch = K / 8;

    auto load = [&](int ic) {
        const int kc = ic * 8;
        const float* Ab = projA
            ? g_proj + (size_t)(kc >> 10) * BSZ * DDIM + (kc & 1023)
            : A + kc;
        va = (m0 + sm < Mlim)
            ? *(const float4*)(Ab + (size_t)(m0 + sm) * ldA + skq * 4) : z4;
        vb = (n0 + sm < Nlim)
            ? *(const float4*)(Bt + (size_t)(n0 + sm) * ldB + kc + skq * 4) : z4;
    };
    auto sts = [&](int buf) {
        const int abase = ((sm >> 4) * 32 + (sm & 7) * 4) * 4 + skq * 2 + ((sm >> 3) & 1);
        float h;
        h = tf32hi(va.x); sA[buf][0][abase + 0]  = h; sA[buf][1][abase + 0]  = va.x - h;
        h = tf32hi(va.y); sA[buf][0][abase + 4]  = h; sA[buf][1][abase + 4]  = va.y - h;
        h = tf32hi(va.z); sA[buf][0][abase + 8]  = h; sA[buf][1][abase + 8]  = va.z - h;
        h = tf32hi(va.w); sA[buf][0][abase + 12] = h; sA[buf][1][abase + 12] = va.w - h;
        const int bbase = ((sm >> 3) * 32 + (sm & 7) * 4) * 2 + skq;
        h = tf32hi(vb.x); sB[buf][0][bbase + 0] = h; sB[buf][1][bbase + 0] = vb.x - h;
        h = tf32hi(vb.y); sB[buf][0][bbase + 2] = h; sB[buf][1][bbase + 2] = vb.y - h;
        h = tf32hi(vb.z); sB[buf][0][bbase + 4] = h; sB[buf][1][bbase + 4] = vb.z - h;
        h = tf32hi(vb.w); sB[buf][0][bbase + 6] = h; sB[buf][1][bbase + 6] = vb.w - h;
    };

    load(0); sts(0); __syncthreads();
    for (int ic = 0; ic < nch; ic++) {
        const int buf = ic & 1;
        const bool more = (ic + 1) < nch;
        if (more) load(ic + 1);
        float4 Ah[4], Al[4];
        float2 Bh[4], Bl[4];
        #pragma unroll
        for (int i = 0; i < 4; i++) {
            Ah[i] = *(const float4*)&sA[buf][0][((wr * 4 + i) * 32 + lane) * 4];
            Al[i] = *(const float4*)&sA[buf][1][((wr * 4 + i) * 32 + lane) * 4];
        }
        #pragma unroll
        for (int j = 0; j < 4; j++) {
            Bh[j] = *(const float2*)&sB[buf][0][((wc * 4 + j) * 32 + lane) * 2];
            Bl[j] = *(const float2*)&sB[buf][1][((wc * 4 + j) * 32 + lane) * 2];
        }
        #pragma unroll
        for (int i = 0; i < 4; i++)
            #pragma unroll
            for (int j = 0; j < 4; j++) {
                mma8(acc[i][j], (const float*)&Ah[i], (const float*)&Bl[j]);
                mma8(acc[i][j], (const float*)&Al[i], (const float*)&Bh[j]);
                mma8(acc[i][j], (const float*)&Ah[i], (const float*)&Bh[j]);
            }
        if (more) sts(buf ^ 1);
        __syncthreads();
    }
}

// ---------------- GEMM + bias(+relu): modes 0..2 = proj[m], 3 = mlp1 -------------
__global__ void __launch_bounds__(256) tgemm_bias(
    int mode, const float* __restrict__ A, const float* __restrict__ bias)
{
    const int m0 = blockIdx.y * 128, n0 = blockIdx.x * 128;
    const float* Bt;
    float* out;
    int K, ldA, projA, relu;
    if (mode < 3) {
        Bt = g_Wt + (size_t)mode * DDIM * FDIM;
        out = g_proj + (size_t)mode * BSZ * DDIM;
        K = FDIM; ldA = FDIM; projA = 0; relu = 0;
    } else {
        Bt = g_W1t; out = g_h; K = HDIM; ldA = DDIM; projA = 1; relu = 1;
    }
    float acc[4][4][4] = {};
    gemm_core(A, ldA, projA, Bt, K, m0, n0, 1 << 30, 1 << 30, K, acc);

    const int lane = threadIdx.x & 31, wid = threadIdx.x >> 5;
    const int wr = wid & 1, wc = wid >> 1;
    #pragma unroll
    for (int i = 0; i < 4; i++) {
        const int r = m0 + wr * 64 + i * 16 + (lane >> 2);
        #pragma unroll
        for (int j = 0; j < 4; j++) {
            const int c = n0 + wc * 32 + j * 8 + (lane & 3) * 2;
            const float2 bv = *(const float2*)(bias + c);
            float2 o0 = make_float2(acc[i][j][0] + bv.x, acc[i][j][1] + bv.y);
            float2 o1 = make_float2(acc[i][j][2] + bv.x, acc[i][j][3] + bv.y);
            if (relu) {
                o0.x = fmaxf(o0.x, 0.f); o0.y = fmaxf(o0.y, 0.f);
                o1.x = fmaxf(o1.x, 0.f); o1.y = fmaxf(o1.y, 0.f);
            }
            *(float2*)(out + (size_t)r * DDIM + c) = o0;
            *(float2*)(out + (size_t)(r + 8) * DDIM + c) = o1;
        }
    }
}

// ---------------- sim GEMM: S[nq,nc] = Qn @ Cn^T ----------------------------------
__global__ void __launch_bounds__(256) tgemm_sim(int m) {
    const int M = g_cnt[m][1], N = g_cnt[m][2];
    const int m0 = blockIdx.y * 128, n0 = blockIdx.x * 128;
    if (m0 >= M || n0 >= N) return;
    float acc[4][4][4] = {};
    gemm_core(g_Qn, DDIM, 0, g_Cn, DDIM, m0, n0, M, N, DDIM, acc);

    const int lane = threadIdx.x & 31, wid = threadIdx.x >> 5;
    const int wr = wid & 1, wc = wid >> 1;
    #pragma unroll
    for (int i = 0; i < 4; i++) {
        const int r0 = m0 + wr * 64 + i * 16 + (lane >> 2);
        const int r1 = r0 + 8;
        #pragma unroll
        for (int j = 0; j < 4; j++) {
            const int c = n0 + wc * 32 + j * 8 + (lane & 3) * 2;
            if (r0 < M) {
                if (c < N)     g_S[(size_t)r0 * N + c]     = acc[i][j][0];
                if (c + 1 < N) g_S[(size_t)r0 * N + c + 1] = acc[i][j][1];
            }
            if (r1 < M) {
                if (c < N)     g_S[(size_t)r1 * N + c]     = acc[i][j][2];
                if (c + 1 < N) g_S[(size_t)r1 * N + c + 1] = acc[i][j][3];
            }
        }
    }
}

// ---------------- transpose weights: W[K][1024] -> Wt[1024][K] --------------------
__global__ void __launch_bounds__(256) transW(
    const float* __restrict__ W, float* __restrict__ Wt, int K)
{
    __shared__ float t[32][33];
    const int n0 = blockIdx.x * 32, k0 = blockIdx.y * 32;
    const int tx = threadIdx.x & 31, ty = threadIdx.x >> 5;
    #pragma unroll
    for (int j = 0; j < 4; j++)
        t[ty + j * 8][tx] = W[(size_t)(k0 + ty + j * 8) * DDIM + n0 + tx];
    __syncthreads();
    #pragma unroll
    for (int j = 0; j < 4; j++) {
        const int row = ty + j * 8;
        Wt[(size_t)(n0 + row) * K + k0 + tx] = t[tx][row];
    }
}

// ---------------- setup: masks, scans, compacted index lists ---------------------
__global__ void __launch_bounds__(1024) setup_kernel(const int* __restrict__ missing) {
    __shared__ int sh[1024];
    const int t = threadIdx.x;
    const int base = t * 8;
    for (int m = 0; m < 3; m++) {
        const int tag = m + 1;
        int a[8];
        int cnt = 0;
        #pragma unroll
        for (int j = 0; j < 8; j++) { a[j] = (missing[base + j] != tag) ? 1 : 0; cnt += a[j]; }
        sh[t] = cnt; __syncthreads();
        for (int off = 1; off < 1024; off <<= 1) {
            int v = (t >= off) ? sh[t - off] : 0; __syncthreads();
            sh[t] += v; __syncthreads();
        }
        const int Nb = sh[1023];
        int pos = sh[t] - cnt;
        #pragma unroll
        for (int j = 0; j < 8; j++) if (a[j]) g_glist[m][pos++] = base + j;
        if (t == 0) g_cnt[m][0] = Nb;
        __syncthreads();
        int qf[8]; cnt = 0;
        #pragma unroll
        for (int j = 0; j < 8; j++) {
            qf[j] = ((missing[base + j] == tag) && (base + j < Nb)) ? 1 : 0; cnt += qf[j];
        }
        sh[t] = cnt; __syncthreads();
        for (int off = 1; off < 1024; off <<= 1) {
            int v = (t >= off) ? sh[t - off] : 0; __syncthreads();
            sh[t] += v; __syncthreads();
        }
        const int nq = sh[1023];
        pos = sh[t] - cnt;
        #pragma unroll
        for (int j = 0; j < 8; j++) if (qf[j]) {
            g_qidx[m][pos] = base + j;
            g_qrow[m][pos] = g_glist[m][base + j];
            pos++;
        }
        if (t == 0) g_cnt[m][1] = nq;
        __syncthreads();
        int cf[8]; cnt = 0;
        #pragma unroll
        for (int j = 0; j < 8; j++) { cf[j] = (a[j] && (base + j < Nb)) ? 1 : 0; cnt += cf[j]; }
        sh[t] = cnt; __syncthreads();
        for (int off = 1; off < 1024; off <<= 1) {
            int v = (t >= off) ? sh[t - off] : 0; __syncthreads();
            sh[t] += v; __syncthreads();
        }
        const int nc = sh[1023];
        pos = sh[t] - cnt;
        #pragma unroll
        for (int j = 0; j < 8; j++) if (cf[j]) {
            g_cidx[m][pos] = base + j;
            g_crow[m][pos] = g_glist[m][base + j];
            pos++;
        }
        if (t == 0) g_cnt[m][2] = nc;
        __syncthreads();
    }
}

// ---------------- per-bank-row L2 norms --------------------------------------------
__global__ void __launch_bounds__(256) knorm(int m) {
    const int i = blockIdx.x;
    if (i >= g_cnt[m][0]) return;
    const int row = g_glist[m][i];
    const float4* p = reinterpret_cast<const float4*>(
        g_proj + (size_t)m * BSZ * DDIM + (size_t)row * DDIM);
    float4 v = p[threadIdx.x];
    float s = v.x * v.x + v.y * v.y + v.z * v.z + v.w * v.w;
    #pragma unroll
    for (int off = 16; off > 0; off >>= 1) s += __shfl_down_sync(0xffffffffu, s, off);
    __shared__ float red[8];
    if ((threadIdx.x & 31) == 0) red[threadIdx.x >> 5] = s;
    __syncthreads();
    if (threadIdx.x == 0) {
        float tot = 0.f;
        #pragma unroll
        for (int w = 0; w < 8; w++) tot += red[w];
        g_nrm[i] = fmaxf(__fsqrt_rn(tot), 1e-8f);
    }
}

// ---------------- gather normalized query / candidate matrices ---------------------
__global__ void __launch_bounds__(256) kgather(int m) {
    const int i = blockIdx.x, t = threadIdx.x;
    const float* __restrict__ projm = g_proj + (size_t)m * BSZ * DDIM;
    if (i < g_cnt[m][1]) {
        const float nr = g_nrm[g_qidx[m][i]];
        float4 v = reinterpret_cast<const float4*>(projm + (size_t)g_qrow[m][i] * DDIM)[t];
        float4 o = make_float4(__fdiv_rn(v.x, nr), __fdiv_rn(v.y, nr),
                               __fdiv_rn(v.z, nr), __fdiv_rn(v.w, nr));
        reinterpret_cast<float4*>(g_Qn + (size_t)i * DDIM)[t] = o;
    }
    if (i < g_cnt[m][2]) {
        const float nr = g_nrm[g_cidx[m][i]];
        float4 v = reinterpret_cast<const float4*>(projm + (size_t)g_crow[m][i] * DDIM)[t];
        float4 o = make_float4(__fdiv_rn(v.x, nr), __fdiv_rn(v.y, nr),
                               __fdiv_rn(v.z, nr), __fdiv_rn(v.w, nr));
        reinterpret_cast<float4*>(g_Cn + (size_t)i * DDIM)[t] = o;
    }
}

// ---------------- zero rows: missing && b >= Nb -------------------------------------
__global__ void __launch_bounds__(256) kzero(const int* __restrict__ missing, int m) {
    const int b = blockIdx.x;
    if (missing[b] != m + 1) return;
    if (b < g_cnt[m][0]) return;
    reinterpret_cast<float4*>(g_proj + (size_t)m * BSZ * DDIM + (size_t)b * DDIM)[threadIdx.x] =
        make_float4(0.f, 0.f, 0.f, 0.f);
}

// ---------------- top-3 + softmax + weighted gather, in-place fill ------------------
__global__ void __launch_bounds__(256) ktopk(int m) {
    const int q = blockIdx.x;
    const int nq = g_cnt[m][1];
    if (q >= nq) return;
    const int nc = g_cnt[m][2];
    const int t = threadIdx.x;
    float* __restrict__ projm = g_proj + (size_t)m * BSZ * DDIM;
    float* __restrict__ dst = projm + (size_t)g_qidx[m][q] * DDIM;
    if (nc == 0) {
        reinterpret_cast<float4*>(dst)[t] = make_float4(0.f, 0.f, 0.f, 0.f);
        return;
    }
    const float NEGINF = -INFINITY;
    const float* __restrict__ Srow = g_S + (size_t)q * nc;
    float v0 = NEGINF, v1 = NEGINF, v2 = NEGINF;
    int   i0 = 0x7fffffff, i1 = 0x7fffffff, i2 = 0x7fffffff;
    for (int c = t; c < nc; c += 256) {
        float v = Srow[c];
        if (v > v2) {
            if (v > v1) {
                if (v > v0) { v2 = v1; i2 = i1; v1 = v0; i1 = i0; v0 = v; i0 = c; }
                else        { v2 = v1; i2 = i1; v1 = v;  i1 = c; }
            } else          { v2 = v;  i2 = c; }
        }
    }
    __shared__ float sv[768];
    __shared__ int   si[768];
    sv[t] = v0; sv[256 + t] = v1; sv[512 + t] = v2;
    si[t] = i0; si[256 + t] = i1; si[512 + t] = i2;
    __syncthreads();
    __shared__ float fw[3];
    __shared__ int   fr[3];
    if (t == 0) {
        float b0 = NEGINF, b1 = NEGINF, b2 = NEGINF;
        int   j0 = 0x7fffffff, j1 = 0x7fffffff, j2 = 0x7fffffff;
        for (int e = 0; e < 768; e++) {
            float v = sv[e]; int c = si[e];
            if ((v > b2) || (v == b2 && c < j2)) {
                if ((v > b1) || (v == b1 && c < j1)) {
                    if ((v > b0) || (v == b0 && c < j0)) {
                        b2 = b1; j2 = j1; b1 = b0; j1 = j0; b0 = v; j0 = c;
                    } else { b2 = b1; j2 = j1; b1 = v; j1 = c; }
                } else     { b2 = v; j2 = c; }
            }
        }
        float w0 = 1.0f;
        float w1 = (b1 == NEGINF) ? 0.f : expf(b1 - b0);
        float w2 = (b2 == NEGINF) ? 0.f : expf(b2 - b0);
        float ws = w0 + w1 + w2;
        fw[0] = __fdiv_rn(w0, ws); fw[1] = __fdiv_rn(w1, ws); fw[2] = __fdiv_rn(w2, ws);
        fr[0] = (j0 == 0x7fffffff) ? 0 : g_crow[m][j0];
        fr[1] = (j1 == 0x7fffffff) ? 0 : g_crow[m][j1];
        fr[2] = (j2 == 0x7fffffff) ? 0 : g_crow[m][j2];
    }
    __syncthreads();
    const float w0 = fw[0], w1 = fw[1], w2 = fw[2];
    float4 a = reinterpret_cast<const float4*>(projm + (size_t)fr[0] * DDIM)[t];
    float4 b = reinterpret_cast<const float4*>(projm + (size_t)fr[1] * DDIM)[t];
    float4 c = reinterpret_cast<const float4*>(projm + (size_t)fr[2] * DDIM)[t];
    float4 o;
    o.x = w0 * a.x + w1 * b.x + w2 * c.x;
    o.y = w0 * a.y + w1 * b.y + w2 * c.y;
    o.z = w0 * a.z + w1 * b.z + w2 * c.z;
    o.w = w0 * a.w + w1 * b.w + w2 * c.w;
    reinterpret_cast<float4*>(dst)[t] = o;
}

// ---------------- MLP layer 2: out = h @ W2 + b2 -----------------------------------
__global__ void __launch_bounds__(256) kmlp2(
    const float* __restrict__ W2, const float* __restrict__ b2, float* __restrict__ out)
{
    const int b = blockIdx.x, t = threadIdx.x;
    float4 h = reinterpret_cast<const float4*>(g_h + (size_t)b * DDIM)[t];
    float4 w = reinterpret_cast<const float4*>(W2)[t];
    float s = h.x * w.x + h.y * w.y + h.z * w.z + h.w * w.w;
    #pragma unroll
    for (int off = 16; off > 0; off >>= 1) s += __shfl_down_sync(0xffffffffu, s, off);
    __shared__ float red[8];
    if ((t & 31) == 0) red[t >> 5] = s;
    __syncthreads();
    if (t == 0) {
        float tot = 0.f;
        #pragma unroll
        for (int wq = 0; wq < 8; wq++) tot += red[wq];
        out[b] = tot + b2[0];
    }
}

// ---------------- launch -------------------------------------------------------------
extern "C" void kernel_launch(void* const* d_in, const int* in_sizes, int n_in,
                              void* d_out, int out_size) {
    const float* x[3]  = { (const float*)d_in[0], (const float*)d_in[1], (const float*)d_in[2] };
    const int* missing = (const int*)d_in[3];
    const float* W[3]  = { (const float*)d_in[4], (const float*)d_in[6], (const float*)d_in[8] };
    const float* bb[3] = { (const float*)d_in[5], (const float*)d_in[7], (const float*)d_in[9] };
    const float* W1 = (const float*)d_in[10];
    const float* b1 = (const float*)d_in[11];
    const float* W2 = (const float*)d_in[12];
    const float* b2 = (const float*)d_in[13];
    float* out = (float*)d_out;

    float* wtd = nullptr;
    cudaGetSymbolAddress((void**)&wtd, g_Wt);
    float* w1td = nullptr;
    cudaGetSymbolAddress((void**)&w1td, g_W1t);
    // 5 launches before the first big GEMM so ncu -s 5 lands on tgemm_bias
    for (int m = 0; m < 3; m++)
        transW<<<dim3(32, FDIM / 32), 256>>>(W[m], wtd + (size_t)m * DDIM * FDIM, FDIM);
    transW<<<dim3(32, HDIM / 32), 256>>>(W1, w1td, HDIM);
    setup_kernel<<<1, 1024>>>(missing);

    dim3 gp(DDIM / 128, BSZ / 128);                 // (8, 64)
    for (int m = 0; m < 3; m++)
        tgemm_bias<<<gp, 256>>>(m, x[m], bb[m]);

    dim3 gs(64, 64);                                // early-exit on runtime dims
    for (int m = 0; m < 3; m++) {
        knorm<<<BSZ, 256>>>(m);
        kgather<<<BSZ, 256>>>(m);
        kzero<<<BSZ, 256>>>(missing, m);
        tgemm_sim<<<gs, 256>>>(m);
        ktopk<<<BSZ, 256>>>(m);
    }

    tgemm_bias<<<gp, 256>>>(3, nullptr, b1);
    kmlp2<<<BSZ, 256>>>(W2, b2, out);
}

// round 8
// speedup vs baseline: 2.0927x; 1.5773x over previous
#include <cuda_runtime.h>
#include <cuda_bf16.h>
#include <math.h>
#include <float.h>
#include <stdint.h>

#define BSZ 8192
#define FDIM 2048
#define DDIM 1024
#define HDIM 3072

// ---------------- scratch ------------------------------------------------------
__device__ float g_proj[(size_t)3 * BSZ * DDIM];
__device__ float g_Qn[(size_t)BSZ * DDIM];
__device__ float g_Cn[(size_t)BSZ * DDIM];
__device__ float g_S[16777216ull];
__device__ float g_h[(size_t)BSZ * DDIM];
__device__ float g_Wt[(size_t)3 * DDIM * FDIM];    // W^T per modality [1024][2048]
__device__ float g_W1t[(size_t)DDIM * HDIM];       // W1^T [1024][3072]
__device__ float g_nrm[BSZ];
__device__ int   g_glist[3][BSZ];
__device__ int   g_qidx[3][BSZ];
__device__ int   g_qrow[3][BSZ];
__device__ int   g_cidx[3][BSZ];
__device__ int   g_crow[3][BSZ];
__device__ int   g_cnt[3][4];

// ---------------- bf16 MMA helpers ------------------------------------------------
__device__ __forceinline__ void mma16(float* d, const uint32_t* a, const uint32_t* b) {
    asm volatile(
        "mma.sync.aligned.m16n8k16.row.col.f32.bf16.bf16.f32 "
        "{%0,%1,%2,%3}, {%4,%5,%6,%7}, {%8,%9}, {%0,%1,%2,%3};"
        : "+f"(d[0]), "+f"(d[1]), "+f"(d[2]), "+f"(d[3])
        : "r"(a[0]), "r"(a[1]), "r"(a[2]), "r"(a[3]), "r"(b[0]), "r"(b[1]));
}
// split two fp32 into packed bf16 hi-limb and bf16 lo-limb (residual)
__device__ __forceinline__ void split2(float x, float y, uint32_t& hi, uint32_t& lo) {
    __nv_bfloat16 hx = __float2bfloat16_rn(x), hy = __float2bfloat16_rn(y);
    float rx = x - __bfloat162float(hx);
    float ry = y - __bfloat162float(hy);
    __nv_bfloat16 lx = __float2bfloat16_rn(rx), ly = __float2bfloat16_rn(ry);
    hi = ((uint32_t)__bfloat16_as_ushort(hy) << 16) | (uint32_t)__bfloat16_as_ushort(hx);
    lo = ((uint32_t)__bfloat16_as_ushort(ly) << 16) | (uint32_t)__bfloat16_as_ushort(lx);
}

// ---------------- GEMM core: CTA 128x128, 256 threads, warp tile 64x32 -----------
// k-chunk 16, double-buffered smem, fragment-permuted bf16x2 layout, split at STS.
// 3-term bf16 emulation: Ah*Bl + Al*Bh + Ah*Bh with fp32 accumulators.
// A frag (m16n8k16): lane reads uint4 at ((mtile*32+lane)*4); regs = (rowsel, khalf).
// B frag: lane reads uint2 at ((ntile*32+lane)*2); regs = khalf.
__device__ __forceinline__ void gemm_core(
    const float* __restrict__ A, int ldA, int projA,
    const float* __restrict__ Bt, int ldB,
    int m0, int n0, int Mlim, int Nlim, int K, float acc[4][4][4])
{
    __shared__ uint32_t sA[2][2][1024];   // [buf][limb][...]
    __shared__ uint32_t sB[2][2][1024];
    const int tid = threadIdx.x;
    const int lane = tid & 31, wid = tid >> 5;
    const int wr = wid & 1, wc = wid >> 1;      // warp m-half (x64), n-quarter (x32)
    const int sm = tid >> 1, h = tid & 1;       // staging: row 0..127, k-half 0..1
    const float4 z4 = make_float4(0.f, 0.f, 0.f, 0.f);
    float4 va0, va1, vb0, vb1;
    const int nch = K / 16;
    // store bases (uint32 index); j advances lane slot
    const int aB = ((sm >> 4) * 32 + (sm & 7) * 4) * 4 + h * 2 + ((sm >> 3) & 1);
    const int bB = ((sm >> 3) * 32 + (sm & 7) * 4) * 2 + h;

    auto load = [&](int ic) {
        const int kc = ic * 16 + h * 8;
        const float* Ab = projA
            ? g_proj + (size_t)(kc >> 10) * BSZ * DDIM + (kc & 1023)
            : A + kc;
        if (m0 + sm < Mlim) {
            const float* p = Ab + (size_t)(m0 + sm) * ldA;
            va0 = *(const float4*)(p);
            va1 = *(const float4*)(p + 4);
        } else { va0 = z4; va1 = z4; }
        if (n0 + sm < Nlim) {
            const float* p = Bt + (size_t)(n0 + sm) * ldB + kc;
            vb0 = *(const float4*)(p);
            vb1 = *(const float4*)(p + 4);
        } else { vb0 = z4; vb1 = z4; }
    };
    auto sts = [&](int buf) {
        uint32_t hi, lo;
        split2(va0.x, va0.y, hi, lo); sA[buf][0][aB + 0]  = hi; sA[buf][1][aB + 0]  = lo;
        split2(va0.z, va0.w, hi, lo); sA[buf][0][aB + 4]  = hi; sA[buf][1][aB + 4]  = lo;
        split2(va1.x, va1.y, hi, lo); sA[buf][0][aB + 8]  = hi; sA[buf][1][aB + 8]  = lo;
        split2(va1.z, va1.w, hi, lo); sA[buf][0][aB + 12] = hi; sA[buf][1][aB + 12] = lo;
        split2(vb0.x, vb0.y, hi, lo); sB[buf][0][bB + 0] = hi; sB[buf][1][bB + 0] = lo;
        split2(vb0.z, vb0.w, hi, lo); sB[buf][0][bB + 2] = hi; sB[buf][1][bB + 2] = lo;
        split2(vb1.x, vb1.y, hi, lo); sB[buf][0][bB + 4] = hi; sB[buf][1][bB + 4] = lo;
        split2(vb1.z, vb1.w, hi, lo); sB[buf][0][bB + 6] = hi; sB[buf][1][bB + 6] = lo;
    };

    load(0); sts(0); __syncthreads();
    for (int ic = 0; ic < nch; ic++) {
        const int buf = ic & 1;
        const bool more = (ic + 1) < nch;
        if (more) load(ic + 1);
        uint2 Bh[4], Bl[4];
        #pragma unroll
        for (int j = 0; j < 4; j++) {
            Bh[j] = *(const uint2*)&sB[buf][0][((wc * 4 + j) * 32 + lane) * 2];
            Bl[j] = *(const uint2*)&sB[buf][1][((wc * 4 + j) * 32 + lane) * 2];
        }
        #pragma unroll
        for (int i = 0; i < 4; i++) {
            const uint4 Ah = *(const uint4*)&sA[buf][0][((wr * 4 + i) * 32 + lane) * 4];
            const uint4 Al = *(const uint4*)&sA[buf][1][((wr * 4 + i) * 32 + lane) * 4];
            #pragma unroll
            for (int j = 0; j < 4; j++) {
                mma16(acc[i][j], (const uint32_t*)&Ah, (const uint32_t*)&Bl[j]);
                mma16(acc[i][j], (const uint32_t*)&Al, (const uint32_t*)&Bh[j]);
                mma16(acc[i][j], (const uint32_t*)&Ah, (const uint32_t*)&Bh[j]);
            }
        }
        if (more) sts(buf ^ 1);
        __syncthreads();
    }
}

// ---------------- GEMM + bias(+relu): modes 0..2 = proj[m], 3 = mlp1 -------------
__global__ void __launch_bounds__(256, 2) tgemm_bias(
    int mode, const float* __restrict__ A, const float* __restrict__ bias)
{
    const int m0 = blockIdx.y * 128, n0 = blockIdx.x * 128;
    const float* Bt;
    float* out;
    int K, ldA, projA, relu;
    if (mode < 3) {
        Bt = g_Wt + (size_t)mode * DDIM * FDIM;
        out = g_proj + (size_t)mode * BSZ * DDIM;
        K = FDIM; ldA = FDIM; projA = 0; relu = 0;
    } else {
        Bt = g_W1t; out = g_h; K = HDIM; ldA = DDIM; projA = 1; relu = 1;
    }
    float acc[4][4][4] = {};
    gemm_core(A, ldA, projA, Bt, K, m0, n0, 1 << 30, 1 << 30, K, acc);

    const int lane = threadIdx.x & 31, wid = threadIdx.x >> 5;
    const int wr = wid & 1, wc = wid >> 1;
    #pragma unroll
    for (int i = 0; i < 4; i++) {
        const int r = m0 + wr * 64 + i * 16 + (lane >> 2);
        #pragma unroll
        for (int j = 0; j < 4; j++) {
            const int c = n0 + wc * 32 + j * 8 + (lane & 3) * 2;
            const float2 bv = *(const float2*)(bias + c);
            float2 o0 = make_float2(acc[i][j][0] + bv.x, acc[i][j][1] + bv.y);
            float2 o1 = make_float2(acc[i][j][2] + bv.x, acc[i][j][3] + bv.y);
            if (relu) {
                o0.x = fmaxf(o0.x, 0.f); o0.y = fmaxf(o0.y, 0.f);
                o1.x = fmaxf(o1.x, 0.f); o1.y = fmaxf(o1.y, 0.f);
            }
            *(float2*)(out + (size_t)r * DDIM + c) = o0;
            *(float2*)(out + (size_t)(r + 8) * DDIM + c) = o1;
        }
    }
}

// ---------------- sim GEMM: S[nq,nc] = Qn @ Cn^T ----------------------------------
__global__ void __launch_bounds__(256, 2) tgemm_sim(int m) {
    const int M = g_cnt[m][1], N = g_cnt[m][2];
    const int m0 = blockIdx.y * 128, n0 = blockIdx.x * 128;
    if (m0 >= M || n0 >= N) return;
    float acc[4][4][4] = {};
    gemm_core(g_Qn, DDIM, 0, g_Cn, DDIM, m0, n0, M, N, DDIM, acc);

    const int lane = threadIdx.x & 31, wid = threadIdx.x >> 5;
    const int wr = wid & 1, wc = wid >> 1;
    #pragma unroll
    for (int i = 0; i < 4; i++) {
        const int r0 = m0 + wr * 64 + i * 16 + (lane >> 2);
        const int r1 = r0 + 8;
        #pragma unroll
        for (int j = 0; j < 4; j++) {
            const int c = n0 + wc * 32 + j * 8 + (lane & 3) * 2;
            if (r0 < M) {
                if (c < N)     g_S[(size_t)r0 * N + c]     = acc[i][j][0];
                if (c + 1 < N) g_S[(size_t)r0 * N + c + 1] = acc[i][j][1];
            }
            if (r1 < M) {
                if (c < N)     g_S[(size_t)r1 * N + c]     = acc[i][j][2];
                if (c + 1 < N) g_S[(size_t)r1 * N + c + 1] = acc[i][j][3];
            }
        }
    }
}

// ---------------- transpose weights: W[K][1024] -> Wt[1024][K] --------------------
__global__ void __launch_bounds__(256) transW(
    const float* __restrict__ W, float* __restrict__ Wt, int K)
{
    __shared__ float t[32][33];
    const int n0 = blockIdx.x * 32, k0 = blockIdx.y * 32;
    const int tx = threadIdx.x & 31, ty = threadIdx.x >> 5;
    #pragma unroll
    for (int j = 0; j < 4; j++)
        t[ty + j * 8][tx] = W[(size_t)(k0 + ty + j * 8) * DDIM + n0 + tx];
    __syncthreads();
    #pragma unroll
    for (int j = 0; j < 4; j++) {
        const int row = ty + j * 8;
        Wt[(size_t)(n0 + row) * K + k0 + tx] = t[tx][row];
    }
}

// ---------------- setup: masks, scans, compacted index lists ---------------------
__global__ void __launch_bounds__(1024) setup_kernel(const int* __restrict__ missing) {
    __shared__ int sh[1024];
    const int t = threadIdx.x;
    const int base = t * 8;
    for (int m = 0; m < 3; m++) {
        const int tag = m + 1;
        int a[8];
        int cnt = 0;
        #pragma unroll
        for (int j = 0; j < 8; j++) { a[j] = (missing[base + j] != tag) ? 1 : 0; cnt += a[j]; }
        sh[t] = cnt; __syncthreads();
        for (int off = 1; off < 1024; off <<= 1) {
            int v = (t >= off) ? sh[t - off] : 0; __syncthreads();
            sh[t] += v; __syncthreads();
        }
        const int Nb = sh[1023];
        int pos = sh[t] - cnt;
        #pragma unroll
        for (int j = 0; j < 8; j++) if (a[j]) g_glist[m][pos++] = base + j;
        if (t == 0) g_cnt[m][0] = Nb;
        __syncthreads();
        int qf[8]; cnt = 0;
        #pragma unroll
        for (int j = 0; j < 8; j++) {
            qf[j] = ((missing[base + j] == tag) && (base + j < Nb)) ? 1 : 0; cnt += qf[j];
        }
        sh[t] = cnt; __syncthreads();
        for (int off = 1; off < 1024; off <<= 1) {
            int v = (t >= off) ? sh[t - off] : 0; __syncthreads();
            sh[t] += v; __syncthreads();
        }
        const int nq = sh[1023];
        pos = sh[t] - cnt;
        #pragma unroll
        for (int j = 0; j < 8; j++) if (qf[j]) {
            g_qidx[m][pos] = base + j;
            g_qrow[m][pos] = g_glist[m][base + j];
            pos++;
        }
        if (t == 0) g_cnt[m][1] = nq;
        __syncthreads();
        int cf[8]; cnt = 0;
        #pragma unroll
        for (int j = 0; j < 8; j++) { cf[j] = (a[j] && (base + j < Nb)) ? 1 : 0; cnt += cf[j]; }
        sh[t] = cnt; __syncthreads();
        for (int off = 1; off < 1024; off <<= 1) {
            int v = (t >= off) ? sh[t - off] : 0; __syncthreads();
            sh[t] += v; __syncthreads();
        }
        const int nc = sh[1023];
        pos = sh[t] - cnt;
        #pragma unroll
        for (int j = 0; j < 8; j++) if (cf[j]) {
            g_cidx[m][pos] = base + j;
            g_crow[m][pos] = g_glist[m][base + j];
            pos++;
        }
        if (t == 0) g_cnt[m][2] = nc;
        __syncthreads();
    }
}

// ---------------- per-bank-row L2 norms --------------------------------------------
__global__ void __launch_bounds__(256) knorm(int m) {
    const int i = blockIdx.x;
    if (i >= g_cnt[m][0]) return;
    const int row = g_glist[m][i];
    const float4* p = reinterpret_cast<const float4*>(
        g_proj + (size_t)m * BSZ * DDIM + (size_t)row * DDIM);
    float4 v = p[threadIdx.x];
    float s = v.x * v.x + v.y * v.y + v.z * v.z + v.w * v.w;
    #pragma unroll
    for (int off = 16; off > 0; off >>= 1) s += __shfl_down_sync(0xffffffffu, s, off);
    __shared__ float red[8];
    if ((threadIdx.x & 31) == 0) red[threadIdx.x >> 5] = s;
    __syncthreads();
    if (threadIdx.x == 0) {
        float tot = 0.f;
        #pragma unroll
        for (int w = 0; w < 8; w++) tot += red[w];
        g_nrm[i] = fmaxf(__fsqrt_rn(tot), 1e-8f);
    }
}

// ---------------- gather normalized query / candidate matrices ---------------------
__global__ void __launch_bounds__(256) kgather(int m) {
    const int i = blockIdx.x, t = threadIdx.x;
    const float* __restrict__ projm = g_proj + (size_t)m * BSZ * DDIM;
    if (i < g_cnt[m][1]) {
        const float nr = g_nrm[g_qidx[m][i]];
        float4 v = reinterpret_cast<const float4*>(projm + (size_t)g_qrow[m][i] * DDIM)[t];
        float4 o = make_float4(__fdiv_rn(v.x, nr), __fdiv_rn(v.y, nr),
                               __fdiv_rn(v.z, nr), __fdiv_rn(v.w, nr));
        reinterpret_cast<float4*>(g_Qn + (size_t)i * DDIM)[t] = o;
    }
    if (i < g_cnt[m][2]) {
        const float nr = g_nrm[g_cidx[m][i]];
        float4 v = reinterpret_cast<const float4*>(projm + (size_t)g_crow[m][i] * DDIM)[t];
        float4 o = make_float4(__fdiv_rn(v.x, nr), __fdiv_rn(v.y, nr),
                               __fdiv_rn(v.z, nr), __fdiv_rn(v.w, nr));
        reinterpret_cast<float4*>(g_Cn + (size_t)i * DDIM)[t] = o;
    }
}

// ---------------- zero rows: missing && b >= Nb -------------------------------------
__global__ void __launch_bounds__(256) kzero(const int* __restrict__ missing, int m) {
    const int b = blockIdx.x;
    if (missing[b] != m + 1) return;
    if (b < g_cnt[m][0]) return;
    reinterpret_cast<float4*>(g_proj + (size_t)m * BSZ * DDIM + (size_t)b * DDIM)[threadIdx.x] =
        make_float4(0.f, 0.f, 0.f, 0.f);
}

// ---------------- top-3 + softmax + weighted gather, in-place fill ------------------
__global__ void __launch_bounds__(256) ktopk(int m) {
    const int q = blockIdx.x;
    const int nq = g_cnt[m][1];
    if (q >= nq) return;
    const int nc = g_cnt[m][2];
    const int t = threadIdx.x;
    float* __restrict__ projm = g_proj + (size_t)m * BSZ * DDIM;
    float* __restrict__ dst = projm + (size_t)g_qidx[m][q] * DDIM;
    if (nc == 0) {
        reinterpret_cast<float4*>(dst)[t] = make_float4(0.f, 0.f, 0.f, 0.f);
        return;
    }
    const float NEGINF = -INFINITY;
    const float* __restrict__ Srow = g_S + (size_t)q * nc;
    float v0 = NEGINF, v1 = NEGINF, v2 = NEGINF;
    int   i0 = 0x7fffffff, i1 = 0x7fffffff, i2 = 0x7fffffff;
    for (int c = t; c < nc; c += 256) {
        float v = Srow[c];
        if (v > v2) {
            if (v > v1) {
                if (v > v0) { v2 = v1; i2 = i1; v1 = v0; i1 = i0; v0 = v; i0 = c; }
                else        { v2 = v1; i2 = i1; v1 = v;  i1 = c; }
            } else          { v2 = v;  i2 = c; }
        }
    }
    __shared__ float sv[768];
    __shared__ int   si[768];
    sv[t] = v0; sv[256 + t] = v1; sv[512 + t] = v2;
    si[t] = i0; si[256 + t] = i1; si[512 + t] = i2;
    __syncthreads();
    __shared__ float fw[3];
    __shared__ int   fr[3];
    if (t == 0) {
        float b0 = NEGINF, b1 = NEGINF, b2 = NEGINF;
        int   j0 = 0x7fffffff, j1 = 0x7fffffff, j2 = 0x7fffffff;
        for (int e = 0; e < 768; e++) {
            float v = sv[e]; int c = si[e];
            if ((v > b2) || (v == b2 && c < j2)) {
                if ((v > b1) || (v == b1 && c < j1)) {
                    if ((v > b0) || (v == b0 && c < j0)) {
                        b2 = b1; j2 = j1; b1 = b0; j1 = j0; b0 = v; j0 = c;
                    } else { b2 = b1; j2 = j1; b1 = v; j1 = c; }
                } else     { b2 = v; j2 = c; }
            }
        }
        float w0 = 1.0f;
        float w1 = (b1 == NEGINF) ? 0.f : expf(b1 - b0);
        float w2 = (b2 == NEGINF) ? 0.f : expf(b2 - b0);
        float ws = w0 + w1 + w2;
        fw[0] = __fdiv_rn(w0, ws); fw[1] = __fdiv_rn(w1, ws); fw[2] = __fdiv_rn(w2, ws);
        fr[0] = (j0 == 0x7fffffff) ? 0 : g_crow[m][j0];
        fr[1] = (j1 == 0x7fffffff) ? 0 : g_crow[m][j1];
        fr[2] = (j2 == 0x7fffffff) ? 0 : g_crow[m][j2];
    }
    __syncthreads();
    const float w0 = fw[0], w1 = fw[1], w2 = fw[2];
    float4 a = reinterpret_cast<const float4*>(projm + (size_t)fr[0] * DDIM)[t];
    float4 b = reinterpret_cast<const float4*>(projm + (size_t)fr[1] * DDIM)[t];
    float4 c = reinterpret_cast<const float4*>(projm + (size_t)fr[2] * DDIM)[t];
    float4 o;
    o.x = w0 * a.x + w1 * b.x + w2 * c.x;
    o.y = w0 * a.y + w1 * b.y + w2 * c.y;
    o.z = w0 * a.z + w1 * b.z + w2 * c.z;
    o.w = w0 * a.w + w1 * b.w + w2 * c.w;
    reinterpret_cast<float4*>(dst)[t] = o;
}

// ---------------- MLP layer 2: out = h @ W2 + b2 -----------------------------------
__global__ void __launch_bounds__(256) kmlp2(
    const float* __restrict__ W2, const float* __restrict__ b2, float* __restrict__ out)
{
    const int b = blockIdx.x, t = threadIdx.x;
    float4 h = reinterpret_cast<const float4*>(g_h + (size_t)b * DDIM)[t];
    float4 w = reinterpret_cast<const float4*>(W2)[t];
    float s = h.x * w.x + h.y * w.y + h.z * w.z + h.w * w.w;
    #pragma unroll
    for (int off = 16; off > 0; off >>= 1) s += __shfl_down_sync(0xffffffffu, s, off);
    __shared__ float red[8];
    if ((t & 31) == 0) red[t >> 5] = s;
    __syncthreads();
    if (t == 0) {
        float tot = 0.f;
        #pragma unroll
        for (int wq = 0; wq < 8; wq++) tot += red[wq];
        out[b] = tot + b2[0];
    }
}

// ---------------- launch -------------------------------------------------------------
extern "C" void kernel_launch(void* const* d_in, const int* in_sizes, int n_in,
                              void* d_out, int out_size) {
    const float* x[3]  = { (const float*)d_in[0], (const float*)d_in[1], (const float*)d_in[2] };
    const int* missing = (const int*)d_in[3];
    const float* W[3]  = { (const float*)d_in[4], (const float*)d_in[6], (const float*)d_in[8] };
    const float* bb[3] = { (const float*)d_in[5], (const float*)d_in[7], (const float*)d_in[9] };
    const float* W1 = (const float*)d_in[10];
    const float* b1 = (const float*)d_in[11];
    const float* W2 = (const float*)d_in[12];
    const float* b2 = (const float*)d_in[13];
    float* out = (float*)d_out;

    float* wtd = nullptr;
    cudaGetSymbolAddress((void**)&wtd, g_Wt);
    float* w1td = nullptr;
    cudaGetSymbolAddress((void**)&w1td, g_W1t);
    for (int m = 0; m < 3; m++)
        transW<<<dim3(32, FDIM / 32), 256>>>(W[m], wtd + (size_t)m * DDIM * FDIM, FDIM);
    transW<<<dim3(32, HDIM / 32), 256>>>(W1, w1td, HDIM);
    setup_kernel<<<1, 1024>>>(missing);

    dim3 gp(DDIM / 128, BSZ / 128);                 // (8, 64)
    for (int m = 0; m < 3; m++)
        tgemm_bias<<<gp, 256>>>(m, x[m], bb[m]);

    dim3 gs(64, 64);                                // early-exit on runtime dims
    for (int m = 0; m < 3; m++) {
        knorm<<<BSZ, 256>>>(m);
        kgather<<<BSZ, 256>>>(m);
        kzero<<<BSZ, 256>>>(missing, m);
        tgemm_sim<<<gs, 256>>>(m);
        ktopk<<<BSZ, 256>>>(m);
    }

    tgemm_bias<<<gp, 256>>>(3, nullptr, b1);
    kmlp2<<<BSZ, 256>>>(W2, b2, out);
}

// round 9
// speedup vs baseline: 2.1173x; 1.0118x over previous
#include <cuda_runtime.h>
#include <cuda_bf16.h>
#include <math.h>
#include <float.h>
#include <stdint.h>

#define BSZ 8192
#define FDIM 2048
#define DDIM 1024
#define HDIM 3072

// ---------------- scratch ------------------------------------------------------
__device__ float g_proj[(size_t)3 * BSZ * DDIM];
__device__ float g_S[16777216ull];
__device__ float g_h[(size_t)BSZ * DDIM];
__device__ float g_Wt[(size_t)3 * DDIM * FDIM];    // W^T per modality [1024][2048]
__device__ float g_W1t[(size_t)DDIM * HDIM];       // W1^T [1024][3072]
__device__ float g_nrm[BSZ];
__device__ int   g_glist[3][BSZ];
__device__ int   g_qidx[3][BSZ];
__device__ int   g_qrow[3][BSZ];
__device__ int   g_cidx[3][BSZ];
__device__ int   g_crow[3][BSZ];
__device__ int   g_cnt[3][4];

// ---------------- bf16 MMA helpers ------------------------------------------------
__device__ __forceinline__ void mma16(float* d, const uint32_t* a, const uint32_t* b) {
    asm("mma.sync.aligned.m16n8k16.row.col.f32.bf16.bf16.f32 "
        "{%0,%1,%2,%3}, {%4,%5,%6,%7}, {%8,%9}, {%0,%1,%2,%3};"
        : "+f"(d[0]), "+f"(d[1]), "+f"(d[2]), "+f"(d[3])
        : "r"(a[0]), "r"(a[1]), "r"(a[2]), "r"(a[3]), "r"(b[0]), "r"(b[1]));
}
__device__ __forceinline__ void split2(float x, float y, uint32_t& hi, uint32_t& lo) {
    __nv_bfloat16 hx = __float2bfloat16_rn(x), hy = __float2bfloat16_rn(y);
    float rx = x - __bfloat162float(hx);
    float ry = y - __bfloat162float(hy);
    __nv_bfloat16 lx = __float2bfloat16_rn(rx), ly = __float2bfloat16_rn(ry);
    hi = ((uint32_t)__bfloat16_as_ushort(hy) << 16) | (uint32_t)__bfloat16_as_ushort(hx);
    lo = ((uint32_t)__bfloat16_as_ushort(ly) << 16) | (uint32_t)__bfloat16_as_ushort(lx);
}

// ---------------- GEMM core: CTA 128x128, 256 threads, warp tile 64x32 -----------
// k-chunk 16, double-buffered smem, fragment-permuted bf16x2, split(+scale) at STS.
// 3-term bf16 emulation, term-major issue order (same-acc MMAs 16 apart).
// Arow/Brow: per-thread row pointers (fixed across chunks; gather+scale supported).
// projA: A rows live in concat(g_proj); rowmA = global row.
__device__ __forceinline__ void gemm_core(
    const float* __restrict__ Arow, int rowmA, int projA, float aSc,
    const float* __restrict__ Brow, float bSc,
    int K, float acc[4][4][4])
{
    __shared__ uint32_t sA[2][2][1024];
    __shared__ uint32_t sB[2][2][1024];
    const int tid = threadIdx.x;
    const int lane = tid & 31, wid = tid >> 5;
    const int wr = wid & 1, wc = wid >> 1;
    const int sm = tid >> 1, h = tid & 1;
    float4 va0, va1, vb0, vb1;
    const int nch = K / 16;
    const int aB = ((sm >> 4) * 32 + (sm & 7) * 4) * 4 + h * 2 + ((sm >> 3) & 1);
    const int bB = ((sm >> 3) * 32 + (sm & 7) * 4) * 2 + h;

    auto load = [&](int ic) {
        const int kc = ic * 16 + h * 8;
        const float* pa = projA
            ? g_proj + (size_t)(kc >> 10) * BSZ * DDIM + (size_t)rowmA * DDIM + (kc & 1023)
            : Arow + kc;
        va0 = *(const float4*)(pa);
        va1 = *(const float4*)(pa + 4);
        const float* pb = Brow + kc;
        vb0 = *(const float4*)(pb);
        vb1 = *(const float4*)(pb + 4);
    };
    auto sts = [&](int buf) {
        uint32_t hi, lo;
        split2(aSc * va0.x, aSc * va0.y, hi, lo); sA[buf][0][aB + 0]  = hi; sA[buf][1][aB + 0]  = lo;
        split2(aSc * va0.z, aSc * va0.w, hi, lo); sA[buf][0][aB + 4]  = hi; sA[buf][1][aB + 4]  = lo;
        split2(aSc * va1.x, aSc * va1.y, hi, lo); sA[buf][0][aB + 8]  = hi; sA[buf][1][aB + 8]  = lo;
        split2(aSc * va1.z, aSc * va1.w, hi, lo); sA[buf][0][aB + 12] = hi; sA[buf][1][aB + 12] = lo;
        split2(bSc * vb0.x, bSc * vb0.y, hi, lo); sB[buf][0][bB + 0] = hi; sB[buf][1][bB + 0] = lo;
        split2(bSc * vb0.z, bSc * vb0.w, hi, lo); sB[buf][0][bB + 2] = hi; sB[buf][1][bB + 2] = lo;
        split2(bSc * vb1.x, bSc * vb1.y, hi, lo); sB[buf][0][bB + 4] = hi; sB[buf][1][bB + 4] = lo;
        split2(bSc * vb1.z, bSc * vb1.w, hi, lo); sB[buf][0][bB + 6] = hi; sB[buf][1][bB + 6] = lo;
    };

    load(0); sts(0); __syncthreads();
    for (int ic = 0; ic < nch; ic++) {
        const int buf = ic & 1;
        const bool more = (ic + 1) < nch;
        if (more) load(ic + 1);
        uint4 Ah[4], Al[4];
        uint2 Bh[4], Bl[4];
        #pragma unroll
        for (int i = 0; i < 4; i++) {
            Ah[i] = *(const uint4*)&sA[buf][0][((wr * 4 + i) * 32 + lane) * 4];
            Al[i] = *(const uint4*)&sA[buf][1][((wr * 4 + i) * 32 + lane) * 4];
        }
        #pragma unroll
        for (int j = 0; j < 4; j++) {
            Bh[j] = *(const uint2*)&sB[buf][0][((wc * 4 + j) * 32 + lane) * 2];
            Bl[j] = *(const uint2*)&sB[buf][1][((wc * 4 + j) * 32 + lane) * 2];
        }
        // term-major: same-accumulator MMAs are 16 apart
        #pragma unroll
        for (int i = 0; i < 4; i++)
            #pragma unroll
            for (int j = 0; j < 4; j++)
                mma16(acc[i][j], (const uint32_t*)&Ah[i], (const uint32_t*)&Bl[j]);
        #pragma unroll
        for (int i = 0; i < 4; i++)
            #pragma unroll
            for (int j = 0; j < 4; j++)
                mma16(acc[i][j], (const uint32_t*)&Al[i], (const uint32_t*)&Bh[j]);
        #pragma unroll
        for (int i = 0; i < 4; i++)
            #pragma unroll
            for (int j = 0; j < 4; j++)
                mma16(acc[i][j], (const uint32_t*)&Ah[i], (const uint32_t*)&Bh[j]);
        if (more) sts(buf ^ 1);
        __syncthreads();
    }
}

// ---------------- GEMM + bias(+relu): modes 0..2 = proj[m], 3 = mlp1 -------------
__global__ void __launch_bounds__(256, 2) tgemm_bias(
    int mode, const float* __restrict__ A, const float* __restrict__ bias)
{
    const int m0 = blockIdx.y * 128, n0 = blockIdx.x * 128;
    const int sm = threadIdx.x >> 1;
    const float* Bt;
    float* out;
    int K, projA, relu;
    if (mode < 3) {
        Bt = g_Wt + (size_t)mode * DDIM * FDIM;
        out = g_proj + (size_t)mode * BSZ * DDIM;
        K = FDIM; projA = 0; relu = 0;
    } else {
        Bt = g_W1t; out = g_h; K = HDIM; projA = 1; relu = 1;
    }
    const float* Arow = projA ? nullptr : A + (size_t)(m0 + sm) * K;
    const float* Brow = Bt + (size_t)(n0 + sm) * K;
    float acc[4][4][4] = {};
    gemm_core(Arow, m0 + sm, projA, 1.0f, Brow, 1.0f, K, acc);

    const int lane = threadIdx.x & 31, wid = threadIdx.x >> 5;
    const int wr = wid & 1, wc = wid >> 1;
    #pragma unroll
    for (int i = 0; i < 4; i++) {
        const int r = m0 + wr * 64 + i * 16 + (lane >> 2);
        #pragma unroll
        for (int j = 0; j < 4; j++) {
            const int c = n0 + wc * 32 + j * 8 + (lane & 3) * 2;
            const float2 bv = *(const float2*)(bias + c);
            float2 o0 = make_float2(acc[i][j][0] + bv.x, acc[i][j][1] + bv.y);
            float2 o1 = make_float2(acc[i][j][2] + bv.x, acc[i][j][3] + bv.y);
            if (relu) {
                o0.x = fmaxf(o0.x, 0.f); o0.y = fmaxf(o0.y, 0.f);
                o1.x = fmaxf(o1.x, 0.f); o1.y = fmaxf(o1.y, 0.f);
            }
            *(float2*)(out + (size_t)r * DDIM + c) = o0;
            *(float2*)(out + (size_t)(r + 8) * DDIM + c) = o1;
        }
    }
}

// ---------------- sim GEMM: S = Qn @ Cn^T, rows gathered+normalized inline --------
__global__ void __launch_bounds__(256, 2) tgemm_sim(int m) {
    const int M = g_cnt[m][1], N = g_cnt[m][2];
    const int m0 = blockIdx.y * 128, n0 = blockIdx.x * 128;
    if (m0 >= M || n0 >= N) return;
    const int sm = threadIdx.x >> 1;
    const float* __restrict__ projm = g_proj + (size_t)m * BSZ * DDIM;

    const int qi = m0 + sm, ci = n0 + sm;
    const float* Arow;
    float aSc;
    if (qi < M) {
        Arow = projm + (size_t)g_qrow[m][qi] * DDIM;
        aSc = __fdiv_rn(1.0f, g_nrm[g_qidx[m][qi]]);
    } else { Arow = projm; aSc = 0.0f; }
    const float* Brow;
    float bSc;
    if (ci < N) {
        Brow = projm + (size_t)g_crow[m][ci] * DDIM;
        bSc = __fdiv_rn(1.0f, g_nrm[g_cidx[m][ci]]);
    } else { Brow = projm; bSc = 0.0f; }

    float acc[4][4][4] = {};
    gemm_core(Arow, 0, 0, aSc, Brow, bSc, DDIM, acc);

    const int lane = threadIdx.x & 31, wid = threadIdx.x >> 5;
    const int wr = wid & 1, wc = wid >> 1;
    #pragma unroll
    for (int i = 0; i < 4; i++) {
        const int r0 = m0 + wr * 64 + i * 16 + (lane >> 2);
        const int r1 = r0 + 8;
        #pragma unroll
        for (int j = 0; j < 4; j++) {
            const int c = n0 + wc * 32 + j * 8 + (lane & 3) * 2;
            if (r0 < M) {
                if (c < N)     g_S[(size_t)r0 * N + c]     = acc[i][j][0];
                if (c + 1 < N) g_S[(size_t)r0 * N + c + 1] = acc[i][j][1];
            }
            if (r1 < M) {
                if (c < N)     g_S[(size_t)r1 * N + c]     = acc[i][j][2];
                if (c + 1 < N) g_S[(size_t)r1 * N + c + 1] = acc[i][j][3];
            }
        }
    }
}

// ---------------- transpose weights: W[K][1024] -> Wt[1024][K] --------------------
__global__ void __launch_bounds__(256) transW(
    const float* __restrict__ W, float* __restrict__ Wt, int K)
{
    __shared__ float t[32][33];
    const int n0 = blockIdx.x * 32, k0 = blockIdx.y * 32;
    const int tx = threadIdx.x & 31, ty = threadIdx.x >> 5;
    #pragma unroll
    for (int j = 0; j < 4; j++)
        t[ty + j * 8][tx] = W[(size_t)(k0 + ty + j * 8) * DDIM + n0 + tx];
    __syncthreads();
    #pragma unroll
    for (int j = 0; j < 4; j++) {
        const int row = ty + j * 8;
        Wt[(size_t)(n0 + row) * K + k0 + tx] = t[tx][row];
    }
}

// ---------------- setup: masks, scans, compacted index lists ---------------------
__global__ void __launch_bounds__(1024) setup_kernel(const int* __restrict__ missing) {
    __shared__ int sh[1024];
    const int t = threadIdx.x;
    const int base = t * 8;
    for (int m = 0; m < 3; m++) {
        const int tag = m + 1;
        int a[8];
        int cnt = 0;
        #pragma unroll
        for (int j = 0; j < 8; j++) { a[j] = (missing[base + j] != tag) ? 1 : 0; cnt += a[j]; }
        sh[t] = cnt; __syncthreads();
        for (int off = 1; off < 1024; off <<= 1) {
            int v = (t >= off) ? sh[t - off] : 0; __syncthreads();
            sh[t] += v; __syncthreads();
        }
        const int Nb = sh[1023];
        int pos = sh[t] - cnt;
        #pragma unroll
        for (int j = 0; j < 8; j++) if (a[j]) g_glist[m][pos++] = base + j;
        if (t == 0) g_cnt[m][0] = Nb;
        __syncthreads();
        int qf[8]; cnt = 0;
        #pragma unroll
        for (int j = 0; j < 8; j++) {
            qf[j] = ((missing[base + j] == tag) && (base + j < Nb)) ? 1 : 0; cnt += qf[j];
        }
        sh[t] = cnt; __syncthreads();
        for (int off = 1; off < 1024; off <<= 1) {
            int v = (t >= off) ? sh[t - off] : 0; __syncthreads();
            sh[t] += v; __syncthreads();
        }
        const int nq = sh[1023];
        pos = sh[t] - cnt;
        #pragma unroll
        for (int j = 0; j < 8; j++) if (qf[j]) {
            g_qidx[m][pos] = base + j;
            g_qrow[m][pos] = g_glist[m][base + j];
            pos++;
        }
        if (t == 0) g_cnt[m][1] = nq;
        __syncthreads();
        int cf[8]; cnt = 0;
        #pragma unroll
        for (int j = 0; j < 8; j++) { cf[j] = (a[j] && (base + j < Nb)) ? 1 : 0; cnt += cf[j]; }
        sh[t] = cnt; __syncthreads();
        for (int off = 1; off < 1024; off <<= 1) {
            int v = (t >= off) ? sh[t - off] : 0; __syncthreads();
            sh[t] += v; __syncthreads();
        }
        const int nc = sh[1023];
        pos = sh[t] - cnt;
        #pragma unroll
        for (int j = 0; j < 8; j++) if (cf[j]) {
            g_cidx[m][pos] = base + j;
            g_crow[m][pos] = g_glist[m][base + j];
            pos++;
        }
        if (t == 0) g_cnt[m][2] = nc;
        __syncthreads();
    }
}

// ---------------- per-bank-row L2 norms --------------------------------------------
__global__ void __launch_bounds__(256) knorm(int m) {
    const int i = blockIdx.x;
    if (i >= g_cnt[m][0]) return;
    const int row = g_glist[m][i];
    const float4* p = reinterpret_cast<const float4*>(
        g_proj + (size_t)m * BSZ * DDIM + (size_t)row * DDIM);
    float4 v = p[threadIdx.x];
    float s = v.x * v.x + v.y * v.y + v.z * v.z + v.w * v.w;
    #pragma unroll
    for (int off = 16; off > 0; off >>= 1) s += __shfl_down_sync(0xffffffffu, s, off);
    __shared__ float red[8];
    if ((threadIdx.x & 31) == 0) red[threadIdx.x >> 5] = s;
    __syncthreads();
    if (threadIdx.x == 0) {
        float tot = 0.f;
        #pragma unroll
        for (int w = 0; w < 8; w++) tot += red[w];
        g_nrm[i] = fmaxf(__fsqrt_rn(tot), 1e-8f);
    }
}

// ---------------- zero rows: missing && b >= Nb -------------------------------------
__global__ void __launch_bounds__(256) kzero(const int* __restrict__ missing, int m) {
    const int b = blockIdx.x;
    if (missing[b] != m + 1) return;
    if (b < g_cnt[m][0]) return;
    reinterpret_cast<float4*>(g_proj + (size_t)m * BSZ * DDIM + (size_t)b * DDIM)[threadIdx.x] =
        make_float4(0.f, 0.f, 0.f, 0.f);
}

// ---------------- top-3 + softmax + weighted gather, in-place fill ------------------
__global__ void __launch_bounds__(256) ktopk(int m) {
    const int q = blockIdx.x;
    const int nq = g_cnt[m][1];
    if (q >= nq) return;
    const int nc = g_cnt[m][2];
    const int t = threadIdx.x;
    float* __restrict__ projm = g_proj + (size_t)m * BSZ * DDIM;
    float* __restrict__ dst = projm + (size_t)g_qidx[m][q] * DDIM;
    if (nc == 0) {
        reinterpret_cast<float4*>(dst)[t] = make_float4(0.f, 0.f, 0.f, 0.f);
        return;
    }
    const float NEGINF = -INFINITY;
    const float* __restrict__ Srow = g_S + (size_t)q * nc;
    float v0 = NEGINF, v1 = NEGINF, v2 = NEGINF;
    int   i0 = 0x7fffffff, i1 = 0x7fffffff, i2 = 0x7fffffff;
    for (int c = t; c < nc; c += 256) {
        float v = Srow[c];
        if (v > v2) {
            if (v > v1) {
                if (v > v0) { v2 = v1; i2 = i1; v1 = v0; i1 = i0; v0 = v; i0 = c; }
                else        { v2 = v1; i2 = i1; v1 = v;  i1 = c; }
            } else          { v2 = v;  i2 = c; }
        }
    }
    __shared__ float sv[768];
    __shared__ int   si[768];
    sv[t] = v0; sv[256 + t] = v1; sv[512 + t] = v2;
    si[t] = i0; si[256 + t] = i1; si[512 + t] = i2;
    __syncthreads();
    __shared__ float fw[3];
    __shared__ int   fr[3];
    if (t == 0) {
        float b0 = NEGINF, b1 = NEGINF, b2 = NEGINF;
        int   j0 = 0x7fffffff, j1 = 0x7fffffff, j2 = 0x7fffffff;
        for (int e = 0; e < 768; e++) {
            float v = sv[e]; int c = si[e];
            if ((v > b2) || (v == b2 && c < j2)) {
                if ((v > b1) || (v == b1 && c < j1)) {
                    if ((v > b0) || (v == b0 && c < j0)) {
                        b2 = b1; j2 = j1; b1 = b0; j1 = j0; b0 = v; j0 = c;
                    } else { b2 = b1; j2 = j1; b1 = v; j1 = c; }
                } else     { b2 = v; j2 = c; }
            }
        }
        float w0 = 1.0f;
        float w1 = (b1 == NEGINF) ? 0.f : expf(b1 - b0);
        float w2 = (b2 == NEGINF) ? 0.f : expf(b2 - b0);
        float ws = w0 + w1 + w2;
        fw[0] = __fdiv_rn(w0, ws); fw[1] = __fdiv_rn(w1, ws); fw[2] = __fdiv_rn(w2, ws);
        fr[0] = (j0 == 0x7fffffff) ? 0 : g_crow[m][j0];
        fr[1] = (j1 == 0x7fffffff) ? 0 : g_crow[m][j1];
        fr[2] = (j2 == 0x7fffffff) ? 0 : g_crow[m][j2];
    }
    __syncthreads();
    const float w0 = fw[0], w1 = fw[1], w2 = fw[2];
    float4 a = reinterpret_cast<const float4*>(projm + (size_t)fr[0] * DDIM)[t];
    float4 b = reinterpret_cast<const float4*>(projm + (size_t)fr[1] * DDIM)[t];
    float4 c = reinterpret_cast<const float4*>(projm + (size_t)fr[2] * DDIM)[t];
    float4 o;
    o.x = w0 * a.x + w1 * b.x + w2 * c.x;
    o.y = w0 * a.y + w1 * b.y + w2 * c.y;
    o.z = w0 * a.z + w1 * b.z + w2 * c.z;
    o.w = w0 * a.w + w1 * b.w + w2 * c.w;
    reinterpret_cast<float4*>(dst)[t] = o;
}

// ---------------- MLP layer 2: out = h @ W2 + b2 -----------------------------------
__global__ void __launch_bounds__(256) kmlp2(
    const float* __restrict__ W2, const float* __restrict__ b2, float* __restrict__ out)
{
    const int b = blockIdx.x, t = threadIdx.x;
    float4 h = reinterpret_cast<const float4*>(g_h + (size_t)b * DDIM)[t];
    float4 w = reinterpret_cast<const float4*>(W2)[t];
    float s = h.x * w.x + h.y * w.y + h.z * w.z + h.w * w.w;
    #pragma unroll
    for (int off = 16; off > 0; off >>= 1) s += __shfl_down_sync(0xffffffffu, s, off);
    __shared__ float red[8];
    if ((t & 31) == 0) red[t >> 5] = s;
    __syncthreads();
    if (t == 0) {
        float tot = 0.f;
        #pragma unroll
        for (int wq = 0; wq < 8; wq++) tot += red[wq];
        out[b] = tot + b2[0];
    }
}

// ---------------- launch -------------------------------------------------------------
extern "C" void kernel_launch(void* const* d_in, const int* in_sizes, int n_in,
                              void* d_out, int out_size) {
    const float* x[3]  = { (const float*)d_in[0], (const float*)d_in[1], (const float*)d_in[2] };
    const int* missing = (const int*)d_in[3];
    const float* W[3]  = { (const float*)d_in[4], (const float*)d_in[6], (const float*)d_in[8] };
    const float* bb[3] = { (const float*)d_in[5], (const float*)d_in[7], (const float*)d_in[9] };
    const float* W1 = (const float*)d_in[10];
    const float* b1 = (const float*)d_in[11];
    const float* W2 = (const float*)d_in[12];
    const float* b2 = (const float*)d_in[13];
    float* out = (float*)d_out;

    float* wtd = nullptr;
    cudaGetSymbolAddress((void**)&wtd, g_Wt);
    float* w1td = nullptr;
    cudaGetSymbolAddress((void**)&w1td, g_W1t);
    for (int m = 0; m < 3; m++)
        transW<<<dim3(32, FDIM / 32), 256>>>(W[m], wtd + (size_t)m * DDIM * FDIM, FDIM);
    transW<<<dim3(32, HDIM / 32), 256>>>(W1, w1td, HDIM);
    setup_kernel<<<1, 1024>>>(missing);

    dim3 gp(DDIM / 128, BSZ / 128);                 // (8, 64)
    for (int m = 0; m < 3; m++)
        tgemm_bias<<<gp, 256>>>(m, x[m], bb[m]);

    dim3 gs(64, 64);                                // early-exit on runtime dims
    for (int m = 0; m < 3; m++) {
        knorm<<<BSZ, 256>>>(m);
        kzero<<<BSZ, 256>>>(missing, m);
        tgemm_sim<<<gs, 256>>>(m);
        ktopk<<<BSZ, 256>>>(m);
    }

    tgemm_bias<<<gp, 256>>>(3, nullptr, b1);
    kmlp2<<<BSZ, 256>>>(W2, b2, out);
}

// round 10
// speedup vs baseline: 2.2453x; 1.0604x over previous
#include <cuda_runtime.h>
#include <cuda_bf16.h>
#include <math.h>
#include <float.h>
#include <stdint.h>

#define BSZ 8192
#define FDIM 2048
#define DDIM 1024
#define HDIM 3072

typedef __nv_bfloat16 bf16;
typedef __nv_bfloat162 bf162;

// ---------------- scratch ------------------------------------------------------
__device__ float g_proj[(size_t)3 * BSZ * DDIM];             // fp32 proj, filled in place
__device__ __align__(16) bf16 g_Pjh[(size_t)3 * BSZ * DDIM]; // proj hi limbs (kept coherent)
__device__ __align__(16) bf16 g_Pjl[(size_t)3 * BSZ * DDIM]; // proj lo limbs
__device__ __align__(16) bf16 g_Xh[(size_t)3 * BSZ * FDIM];
__device__ __align__(16) bf16 g_Xl[(size_t)3 * BSZ * FDIM];
__device__ __align__(16) bf16 g_Wth[(size_t)3 * DDIM * FDIM]; // W^T limbs [1024][2048]
__device__ __align__(16) bf16 g_Wtl[(size_t)3 * DDIM * FDIM];
__device__ __align__(16) bf16 g_W1th[(size_t)DDIM * HDIM];    // W1^T limbs [1024][3072]
__device__ __align__(16) bf16 g_W1tl[(size_t)DDIM * HDIM];
__device__ float g_S[16777216ull];
__device__ float g_h[(size_t)BSZ * DDIM];
__device__ float g_nrm[BSZ];
__device__ int   g_glist[3][BSZ];
__device__ int   g_qidx[3][BSZ];
__device__ int   g_qrow[3][BSZ];
__device__ int   g_cidx[3][BSZ];
__device__ int   g_crow[3][BSZ];
__device__ int   g_cnt[3][4];

// ---------------- PTX helpers ------------------------------------------------------
__device__ __forceinline__ uint32_t smem_u32(const void* p) {
    uint32_t a;
    asm("{ .reg .u64 t; cvta.to.shared.u64 t, %1; cvt.u32.u64 %0, t; }" : "=r"(a) : "l"(p));
    return a;
}
__device__ __forceinline__ void cpa16(uint32_t dst, const void* src) {
    asm volatile("cp.async.cg.shared.global [%0], [%1], 16;" :: "r"(dst), "l"(src));
}
#define CP_COMMIT() asm volatile("cp.async.commit_group;" ::: "memory")
#define CP_WAIT1()  asm volatile("cp.async.wait_group 1;" ::: "memory")
__device__ __forceinline__ void ldsm4(uint32_t* r, uint32_t addr) {
    asm volatile("ldmatrix.sync.aligned.m8n8.x4.shared.b16 {%0,%1,%2,%3}, [%4];"
                 : "=r"(r[0]), "=r"(r[1]), "=r"(r[2]), "=r"(r[3]) : "r"(addr));
}
__device__ __forceinline__ void mma16(float* d, const uint32_t* a, uint32_t b0, uint32_t b1) {
    asm("mma.sync.aligned.m16n8k16.row.col.f32.bf16.bf16.f32 "
        "{%0,%1,%2,%3}, {%4,%5,%6,%7}, {%8,%9}, {%0,%1,%2,%3};"
        : "+f"(d[0]), "+f"(d[1]), "+f"(d[2]), "+f"(d[3])
        : "r"(a[0]), "r"(a[1]), "r"(a[2]), "r"(a[3]), "r"(b0), "r"(b1));
}
__device__ __forceinline__ bf162 splitlo2(float x, float y, bf162 h) {
    return bf162(__float2bfloat16_rn(x - __bfloat162float(h.x)),
                 __float2bfloat16_rn(y - __bfloat162float(h.y)));
}

// swizzled granule byte offset for (row, 16B-chunk) in a 128row x 32B tile
__device__ __forceinline__ uint32_t gran(int row, int ch) {
    return (uint32_t)((row * 2 + (ch ^ ((row >> 2) & 1))) * 16);
}

// ---------------- GEMM core: CTA 128x128, 8 warps (warp 64x32), k-chunk 16 --------
// cp.async double-buffered (lookahead 2), ldmatrix fragments, 3-term bf16 limbs.
// smem: A [2 stage][2 limb][4KB] = 16KB at smA; B same at smA+16384. Total 32KB.
// aHi/aLo: per-thread A row base (byte ptr). mlp1A: A rows hop modality slabs.
__device__ __forceinline__ void gemm_core(
    const char* aHi, const char* aLo, size_t aRowOff, int mlp1A,
    const char* bHi, const char* bLo,
    int K, float acc[4][4][4], uint32_t smA)
{
    const uint32_t smB = smA + 16384;
    const int tid = threadIdx.x, lane = tid & 31, wid = tid >> 5;
    const int wr = wid & 1, wc = wid >> 1;
    // staging: thread -> (row, chunk)
    const int sr = tid >> 1, sc = tid & 1;
    const uint32_t gOff = gran(sr, sc);
    const uint32_t cB = (uint32_t)sc * 16;          // byte offset of chunk within k16
    // ldmatrix per-lane offsets
    const int sub = lane >> 3, rl = lane & 7;
    const int lch = sub >> 1, lr8 = (sub & 1) * 8;
    uint32_t ag[4], bg[2];
    #pragma unroll
    for (int i = 0; i < 4; i++) ag[i] = gran(wr * 64 + i * 16 + lr8 + rl, lch);
    #pragma unroll
    for (int g = 0; g < 2; g++) bg[g] = gran(wc * 32 + g * 16 + lr8 + rl, lch);

    const int nch = K / 16;
    auto issue = [&](int ic) {
        const int kc = ic * 16;
        const uint32_t st = (uint32_t)(ic & 1) * 8192;
        const char *pa0, *pa1;
        if (!mlp1A) {
            pa0 = aHi + (size_t)kc * 2 + cB;
            pa1 = aLo + (size_t)kc * 2 + cB;
        } else {
            const size_t off = ((size_t)(kc >> 10) * BSZ * DDIM + (size_t)(kc & 1023)) * 2
                             + aRowOff + cB;
            pa0 = aHi + off;
            pa1 = aLo + off;
        }
        cpa16(smA + st + gOff, pa0);
        cpa16(smA + st + 4096 + gOff, pa1);
        cpa16(smB + st + gOff, bHi + (size_t)kc * 2 + cB);
        cpa16(smB + st + 4096 + gOff, bLo + (size_t)kc * 2 + cB);
        CP_COMMIT();
    };

    issue(0);
    issue(1);
    for (int ic = 0; ic < nch; ic++) {
        const uint32_t st = (uint32_t)(ic & 1) * 8192;
        CP_WAIT1();
        __syncthreads();
        uint32_t A[4][4], B[2][4];
        // B-lo
        ldsm4(B[0], smB + st + 4096 + bg[0]);
        ldsm4(B[1], smB + st + 4096 + bg[1]);
        // A-hi
        #pragma unroll
        for (int i = 0; i < 4; i++) ldsm4(A[i], smA + st + ag[i]);
        #pragma unroll
        for (int i = 0; i < 4; i++)
            #pragma unroll
            for (int j = 0; j < 4; j++)
                mma16(acc[i][j], A[i], B[j >> 1][j & 1], B[j >> 1][(j & 1) + 2]);
        // B-hi (overwrite)
        ldsm4(B[0], smB + st + bg[0]);
        ldsm4(B[1], smB + st + bg[1]);
        #pragma unroll
        for (int i = 0; i < 4; i++)
            #pragma unroll
            for (int j = 0; j < 4; j++)
                mma16(acc[i][j], A[i], B[j >> 1][j & 1], B[j >> 1][(j & 1) + 2]);
        // A-lo (overwrite)
        #pragma unroll
        for (int i = 0; i < 4; i++) ldsm4(A[i], smA + st + 4096 + ag[i]);
        #pragma unroll
        for (int i = 0; i < 4; i++)
            #pragma unroll
            for (int j = 0; j < 4; j++)
                mma16(acc[i][j], A[i], B[j >> 1][j & 1], B[j >> 1][(j & 1) + 2]);
        __syncthreads();
        if (ic + 2 < nch) issue(ic + 2);
    }
}

// ---------------- GEMM + bias(+relu): modes 0..2 = proj[m], 3 = mlp1 -------------
__global__ void __launch_bounds__(256, 2) tgemm_bias(
    int mode, const float* __restrict__ bias)
{
    __shared__ __align__(16) char smraw[32768];
    const uint32_t smA = smem_u32(smraw);
    const int m0 = blockIdx.y * 128, n0 = blockIdx.x * 128;
    const int sr = threadIdx.x >> 1;

    const char *aHi, *aLo, *bHi, *bLo;
    size_t aRowOff = 0;
    float* out;
    int K, mlp1A, relu;
    if (mode < 3) {
        const size_t xs = (size_t)mode * BSZ * FDIM + (size_t)(m0 + sr) * FDIM;
        aHi = (const char*)(g_Xh + xs);
        aLo = (const char*)(g_Xl + xs);
        const size_t ws = (size_t)mode * DDIM * FDIM + (size_t)(n0 + sr) * FDIM;
        bHi = (const char*)(g_Wth + ws);
        bLo = (const char*)(g_Wtl + ws);
        out = g_proj + (size_t)mode * BSZ * DDIM;
        K = FDIM; mlp1A = 0; relu = 0;
    } else {
        aHi = (const char*)g_Pjh;
        aLo = (const char*)g_Pjl;
        aRowOff = (size_t)(m0 + sr) * DDIM * 2;
        const size_t ws = (size_t)(n0 + sr) * HDIM;
        bHi = (const char*)(g_W1th + ws);
        bLo = (const char*)(g_W1tl + ws);
        out = g_h;
        K = HDIM; mlp1A = 1; relu = 1;
    }
    float acc[4][4][4] = {};
    gemm_core(aHi, aLo, aRowOff, mlp1A, bHi, bLo, K, acc, smA);

    const int lane = threadIdx.x & 31, wid = threadIdx.x >> 5;
    const int wr = wid & 1, wc = wid >> 1;
    bf16* ph = g_Pjh + (size_t)mode * BSZ * DDIM;  // unused if mode==3
    bf16* pl = g_Pjl + (size_t)mode * BSZ * DDIM;
    #pragma unroll
    for (int i = 0; i < 4; i++) {
        const int r0 = m0 + wr * 64 + i * 16 + (lane >> 2);
        #pragma unroll
        for (int j = 0; j < 4; j++) {
            const int c = n0 + wc * 32 + j * 8 + (lane & 3) * 2;
            const float2 bv = *(const float2*)(bias + c);
            float2 o0 = make_float2(acc[i][j][0] + bv.x, acc[i][j][1] + bv.y);
            float2 o1 = make_float2(acc[i][j][2] + bv.x, acc[i][j][3] + bv.y);
            if (relu) {
                o0.x = fmaxf(o0.x, 0.f); o0.y = fmaxf(o0.y, 0.f);
                o1.x = fmaxf(o1.x, 0.f); o1.y = fmaxf(o1.y, 0.f);
            }
            *(float2*)(out + (size_t)r0 * DDIM + c) = o0;
            *(float2*)(out + (size_t)(r0 + 8) * DDIM + c) = o1;
            if (mode < 3) {
                bf162 h0(__float2bfloat16_rn(o0.x), __float2bfloat16_rn(o0.y));
                bf162 h1(__float2bfloat16_rn(o1.x), __float2bfloat16_rn(o1.y));
                *(bf162*)(ph + (size_t)r0 * DDIM + c) = h0;
                *(bf162*)(ph + (size_t)(r0 + 8) * DDIM + c) = h1;
                *(bf162*)(pl + (size_t)r0 * DDIM + c) = splitlo2(o0.x, o0.y, h0);
                *(bf162*)(pl + (size_t)(r0 + 8) * DDIM + c) = splitlo2(o1.x, o1.y, h1);
            }
        }
    }
}

// ---------------- sim GEMM: S = (Pq @ Pc^T) scaled by 1/(|q||c|) in epilogue -------
__global__ void __launch_bounds__(256, 2) tgemm_sim(int m) {
    const int M = g_cnt[m][1], N = g_cnt[m][2];
    const int m0 = blockIdx.y * 128, n0 = blockIdx.x * 128;
    if (m0 >= M || n0 >= N) return;
    __shared__ __align__(16) char smraw[32768];
    __shared__ float rs[128], cs[128];
    const uint32_t smA = smem_u32(smraw);
    const int tid = threadIdx.x;
    const int sr = tid >> 1;
    const size_t slab = (size_t)m * BSZ * DDIM;

    // per-output-row/col scales (1/norm); OOB -> 0
    if (tid < 128) {
        const int qi = m0 + tid;
        rs[tid] = (qi < M) ? __fdiv_rn(1.0f, g_nrm[g_qidx[m][qi]]) : 0.0f;
    } else {
        const int ci = n0 + tid - 128;
        cs[tid - 128] = (ci < N) ? __fdiv_rn(1.0f, g_nrm[g_cidx[m][ci]]) : 0.0f;
    }
    // per-thread gathered row pointers (OOB -> row 0 of slab, zeroed by scale)
    const int qi = m0 + sr, ci = n0 + sr;
    const size_t ar = slab + ((qi < M) ? (size_t)g_qrow[m][qi] * DDIM : 0);
    const size_t br = slab + ((ci < N) ? (size_t)g_crow[m][ci] * DDIM : 0);

    float acc[4][4][4] = {};
    gemm_core((const char*)(g_Pjh + ar), (const char*)(g_Pjl + ar), 0, 0,
              (const char*)(g_Pjh + br), (const char*)(g_Pjl + br), DDIM, acc, smA);

    const int lane = tid & 31, wid = tid >> 5;
    const int wr = wid & 1, wc = wid >> 1;
    #pragma unroll
    for (int i = 0; i < 4; i++) {
        const int lr0 = wr * 64 + i * 16 + (lane >> 2);
        const int r0 = m0 + lr0, r1 = r0 + 8;
        const float s0 = rs[lr0], s1 = rs[lr0 + 8];
        #pragma unroll
        for (int j = 0; j < 4; j++) {
            const int lc = wc * 32 + j * 8 + (lane & 3) * 2;
            const int c = n0 + lc;
            const float c0 = cs[lc], c1 = cs[lc + 1];
            if (r0 < M) {
                if (c < N)     g_S[(size_t)r0 * N + c]     = acc[i][j][0] * s0 * c0;
                if (c + 1 < N) g_S[(size_t)r0 * N + c + 1] = acc[i][j][1] * s0 * c1;
            }
            if (r1 < M) {
                if (c < N)     g_S[(size_t)r1 * N + c]     = acc[i][j][2] * s1 * c0;
                if (c + 1 < N) g_S[(size_t)r1 * N + c + 1] = acc[i][j][3] * s1 * c1;
            }
        }
    }
}

// ---------------- split X into bf16 hi/lo limbs ------------------------------------
__global__ void __launch_bounds__(256) splitX(
    const float* __restrict__ x0, const float* __restrict__ x1, const float* __restrict__ x2)
{
    const int m = blockIdx.y;
    const float* X = (m == 0) ? x0 : ((m == 1) ? x1 : x2);
    const size_t i = (size_t)blockIdx.x * 256 + threadIdx.x;   // float4 index
    float4 v = ((const float4*)X)[i];
    bf162 h0(__float2bfloat16_rn(v.x), __float2bfloat16_rn(v.y));
    bf162 h1(__float2bfloat16_rn(v.z), __float2bfloat16_rn(v.w));
    bf162 l0 = splitlo2(v.x, v.y, h0);
    bf162 l1 = splitlo2(v.z, v.w, h1);
    bf162* dh = (bf162*)(g_Xh + (size_t)m * BSZ * FDIM) + i * 2;
    bf162* dl = (bf162*)(g_Xl + (size_t)m * BSZ * FDIM) + i * 2;
    dh[0] = h0; dh[1] = h1;
    dl[0] = l0; dl[1] = l1;
}

// ---------------- transpose+split weights: W[K][1024] -> Wt limbs [1024][K] --------
__global__ void __launch_bounds__(256) transW(
    const float* __restrict__ W, bf16* __restrict__ Th, bf16* __restrict__ Tl, int K)
{
    __shared__ float t[32][33];
    const int n0 = blockIdx.x * 32, k0 = blockIdx.y * 32;
    const int tx = threadIdx.x & 31, ty = threadIdx.x >> 5;
    #pragma unroll
    for (int j = 0; j < 4; j++)
        t[ty + j * 8][tx] = W[(size_t)(k0 + ty + j * 8) * DDIM + n0 + tx];
    __syncthreads();
    #pragma unroll
    for (int j = 0; j < 4; j++) {
        const int row = ty + j * 8;
        const float v = t[tx][row];
        const bf16 h = __float2bfloat16_rn(v);
        Th[(size_t)(n0 + row) * K + k0 + tx] = h;
        Tl[(size_t)(n0 + row) * K + k0 + tx] =
            __float2bfloat16_rn(v - __bfloat162float(h));
    }
}

// ---------------- setup: masks, scans, compacted index lists -----------------------
__global__ void __launch_bounds__(1024) setup_kernel(const int* __restrict__ missing) {
    __shared__ int sh[1024];
    const int t = threadIdx.x;
    const int base = t * 8;
    for (int m = 0; m < 3; m++) {
        const int tag = m + 1;
        int a[8];
        int cnt = 0;
        #pragma unroll
        for (int j = 0; j < 8; j++) { a[j] = (missing[base + j] != tag) ? 1 : 0; cnt += a[j]; }
        sh[t] = cnt; __syncthreads();
        for (int off = 1; off < 1024; off <<= 1) {
            int v = (t >= off) ? sh[t - off] : 0; __syncthreads();
            sh[t] += v; __syncthreads();
        }
        const int Nb = sh[1023];
        int pos = sh[t] - cnt;
        #pragma unroll
        for (int j = 0; j < 8; j++) if (a[j]) g_glist[m][pos++] = base + j;
        if (t == 0) g_cnt[m][0] = Nb;
        __syncthreads();
        int qf[8]; cnt = 0;
        #pragma unroll
        for (int j = 0; j < 8; j++) {
            qf[j] = ((missing[base + j] == tag) && (base + j < Nb)) ? 1 : 0; cnt += qf[j];
        }
        sh[t] = cnt; __syncthreads();
        for (int off = 1; off < 1024; off <<= 1) {
            int v = (t >= off) ? sh[t - off] : 0; __syncthreads();
            sh[t] += v; __syncthreads();
        }
        const int nq = sh[1023];
        pos = sh[t] - cnt;
        #pragma unroll
        for (int j = 0; j < 8; j++) if (qf[j]) {
            g_qidx[m][pos] = base + j;
            g_qrow[m][pos] = g_glist[m][base + j];
            pos++;
        }
        if (t == 0) g_cnt[m][1] = nq;
        __syncthreads();
        int cf[8]; cnt = 0;
        #pragma unroll
        for (int j = 0; j < 8; j++) { cf[j] = (a[j] && (base + j < Nb)) ? 1 : 0; cnt += cf[j]; }
        sh[t] = cnt; __syncthreads();
        for (int off = 1; off < 1024; off <<= 1) {
            int v = (t >= off) ? sh[t - off] : 0; __syncthreads();
            sh[t] += v; __syncthreads();
        }
        const int nc = sh[1023];
        pos = sh[t] - cnt;
        #pragma unroll
        for (int j = 0; j < 8; j++) if (cf[j]) {
            g_cidx[m][pos] = base + j;
            g_crow[m][pos] = g_glist[m][base + j];
            pos++;
        }
        if (t == 0) g_cnt[m][2] = nc;
        __syncthreads();
    }
}

// ---------------- per-bank-row L2 norms ----------------------------------------------
__global__ void __launch_bounds__(256) knorm(int m) {
    const int i = blockIdx.x;
    if (i >= g_cnt[m][0]) return;
    const int row = g_glist[m][i];
    const float4* p = reinterpret_cast<const float4*>(
        g_proj + (size_t)m * BSZ * DDIM + (size_t)row * DDIM);
    float4 v = p[threadIdx.x];
    float s = v.x * v.x + v.y * v.y + v.z * v.z + v.w * v.w;
    #pragma unroll
    for (int off = 16; off > 0; off >>= 1) s += __shfl_down_sync(0xffffffffu, s, off);
    __shared__ float red[8];
    if ((threadIdx.x & 31) == 0) red[threadIdx.x >> 5] = s;
    __syncthreads();
    if (threadIdx.x == 0) {
        float tot = 0.f;
        #pragma unroll
        for (int w = 0; w < 8; w++) tot += red[w];
        g_nrm[i] = fmaxf(__fsqrt_rn(tot), 1e-8f);
    }
}

// ---------------- zero rows: missing && b >= Nb (fp32 + limbs) ------------------------
__global__ void __launch_bounds__(256) kzero(const int* __restrict__ missing, int m) {
    const int b = blockIdx.x;
    if (missing[b] != m + 1) return;
    if (b < g_cnt[m][0]) return;
    const size_t off = (size_t)m * BSZ * DDIM + (size_t)b * DDIM;
    const int t = threadIdx.x;
    reinterpret_cast<float4*>(g_proj + off)[t] = make_float4(0.f, 0.f, 0.f, 0.f);
    ((uint2*)(g_Pjh + off))[t] = make_uint2(0u, 0u);
    ((uint2*)(g_Pjl + off))[t] = make_uint2(0u, 0u);
}

// ---------------- top-3 + softmax + weighted gather fill (fp32 + limbs) ---------------
__global__ void __launch_bounds__(256) ktopk(int m) {
    const int q = blockIdx.x;
    const int nq = g_cnt[m][1];
    if (q >= nq) return;
    const int nc = g_cnt[m][2];
    const int t = threadIdx.x;
    const size_t slab = (size_t)m * BSZ * DDIM;
    float* __restrict__ projm = g_proj + slab;
    const int qb = g_qidx[m][q];
    float* __restrict__ dst = projm + (size_t)qb * DDIM;
    bf162* __restrict__ dsth = (bf162*)(g_Pjh + slab + (size_t)qb * DDIM);
    bf162* __restrict__ dstl = (bf162*)(g_Pjl + slab + (size_t)qb * DDIM);
    if (nc == 0) {
        reinterpret_cast<float4*>(dst)[t] = make_float4(0.f, 0.f, 0.f, 0.f);
        bf162 z(__float2bfloat16_rn(0.f), __float2bfloat16_rn(0.f));
        dsth[t * 2] = z; dsth[t * 2 + 1] = z;
        dstl[t * 2] = z; dstl[t * 2 + 1] = z;
        return;
    }
    const float NEGINF = -INFINITY;
    const float* __restrict__ Srow = g_S + (size_t)q * nc;
    float v0 = NEGINF, v1 = NEGINF, v2 = NEGINF;
    int   i0 = 0x7fffffff, i1 = 0x7fffffff, i2 = 0x7fffffff;
    for (int c = t; c < nc; c += 256) {
        float v = Srow[c];
        if (v > v2) {
            if (v > v1) {
                if (v > v0) { v2 = v1; i2 = i1; v1 = v0; i1 = i0; v0 = v; i0 = c; }
                else        { v2 = v1; i2 = i1; v1 = v;  i1 = c; }
            } else          { v2 = v;  i2 = c; }
        }
    }
    __shared__ float sv[768];
    __shared__ int   si[768];
    sv[t] = v0; sv[256 + t] = v1; sv[512 + t] = v2;
    si[t] = i0; si[256 + t] = i1; si[512 + t] = i2;
    __syncthreads();
    __shared__ float fw[3];
    __shared__ int   fr[3];
    if (t == 0) {
        float b0 = NEGINF, b1 = NEGINF, b2 = NEGINF;
        int   j0 = 0x7fffffff, j1 = 0x7fffffff, j2 = 0x7fffffff;
        for (int e = 0; e < 768; e++) {
            float v = sv[e]; int c = si[e];
            if ((v > b2) || (v == b2 && c < j2)) {
                if ((v > b1) || (v == b1 && c < j1)) {
                    if ((v > b0) || (v == b0 && c < j0)) {
                        b2 = b1; j2 = j1; b1 = b0; j1 = j0; b0 = v; j0 = c;
                    } else { b2 = b1; j2 = j1; b1 = v; j1 = c; }
                } else     { b2 = v; j2 = c; }
            }
        }
        float w0 = 1.0f;
        float w1 = (b1 == NEGINF) ? 0.f : expf(b1 - b0);
        float w2 = (b2 == NEGINF) ? 0.f : expf(b2 - b0);
        float ws = w0 + w1 + w2;
        fw[0] = __fdiv_rn(w0, ws); fw[1] = __fdiv_rn(w1, ws); fw[2] = __fdiv_rn(w2, ws);
        fr[0] = (j0 == 0x7fffffff) ? 0 : g_crow[m][j0];
        fr[1] = (j1 == 0x7fffffff) ? 0 : g_crow[m][j1];
        fr[2] = (j2 == 0x7fffffff) ? 0 : g_crow[m][j2];
    }
    __syncthreads();
    const float w0 = fw[0], w1 = fw[1], w2 = fw[2];
    float4 a = reinterpret_cast<const float4*>(projm + (size_t)fr[0] * DDIM)[t];
    float4 b = reinterpret_cast<const float4*>(projm + (size_t)fr[1] * DDIM)[t];
    float4 c = reinterpret_cast<const float4*>(projm + (size_t)fr[2] * DDIM)[t];
    float4 o;
    o.x = w0 * a.x + w1 * b.x + w2 * c.x;
    o.y = w0 * a.y + w1 * b.y + w2 * c.y;
    o.z = w0 * a.z + w1 * b.z + w2 * c.z;
    o.w = w0 * a.w + w1 * b.w + w2 * c.w;
    reinterpret_cast<float4*>(dst)[t] = o;
    bf162 h0(__float2bfloat16_rn(o.x), __float2bfloat16_rn(o.y));
    bf162 h1(__float2bfloat16_rn(o.z), __float2bfloat16_rn(o.w));
    dsth[t * 2] = h0; dsth[t * 2 + 1] = h1;
    dstl[t * 2] = splitlo2(o.x, o.y, h0);
    dstl[t * 2 + 1] = splitlo2(o.z, o.w, h1);
}

// ---------------- MLP layer 2: out = h @ W2 + b2 ---------------------------------------
__global__ void __launch_bounds__(256) kmlp2(
    const float* __restrict__ W2, const float* __restrict__ b2, float* __restrict__ out)
{
    const int b = blockIdx.x, t = threadIdx.x;
    float4 h = reinterpret_cast<const float4*>(g_h + (size_t)b * DDIM)[t];
    float4 w = reinterpret_cast<const float4*>(W2)[t];
    float s = h.x * w.x + h.y * w.y + h.z * w.z + h.w * w.w;
    #pragma unroll
    for (int off = 16; off > 0; off >>= 1) s += __shfl_down_sync(0xffffffffu, s, off);
    __shared__ float red[8];
    if ((t & 31) == 0) red[t >> 5] = s;
    __syncthreads();
    if (t == 0) {
        float tot = 0.f;
        #pragma unroll
        for (int wq = 0; wq < 8; wq++) tot += red[wq];
        out[b] = tot + b2[0];
    }
}

// ---------------- launch ----------------------------------------------------------------
extern "C" void kernel_launch(void* const* d_in, const int* in_sizes, int n_in,
                              void* d_out, int out_size) {
    const float* x[3]  = { (const float*)d_in[0], (const float*)d_in[1], (const float*)d_in[2] };
    const int* missing = (const int*)d_in[3];
    const float* W[3]  = { (const float*)d_in[4], (const float*)d_in[6], (const float*)d_in[8] };
    const float* bb[3] = { (const float*)d_in[5], (const float*)d_in[7], (const float*)d_in[9] };
    const float* W1 = (const float*)d_in[10];
    const float* b1 = (const float*)d_in[11];
    const float* W2 = (const float*)d_in[12];
    const float* b2 = (const float*)d_in[13];
    float* out = (float*)d_out;

    bf16 *wth, *wtl, *w1th, *w1tl;
    cudaGetSymbolAddress((void**)&wth, g_Wth);
    cudaGetSymbolAddress((void**)&wtl, g_Wtl);
    cudaGetSymbolAddress((void**)&w1th, g_W1th);
    cudaGetSymbolAddress((void**)&w1tl, g_W1tl);

    splitX<<<dim3(BSZ * FDIM / 1024, 3), 256>>>(x[0], x[1], x[2]);
    for (int m = 0; m < 3; m++)
        transW<<<dim3(32, FDIM / 32), 256>>>(W[m],
            wth + (size_t)m * DDIM * FDIM, wtl + (size_t)m * DDIM * FDIM, FDIM);
    transW<<<dim3(32, HDIM / 32), 256>>>(W1, w1th, w1tl, HDIM);
    setup_kernel<<<1, 1024>>>(missing);

    dim3 gp(DDIM / 128, BSZ / 128);                 // (8, 64)
    for (int m = 0; m < 3; m++)
        tgemm_bias<<<gp, 256>>>(m, bb[m]);

    dim3 gs(64, 64);                                // early-exit on runtime dims
    for (int m = 0; m < 3; m++) {
        knorm<<<BSZ, 256>>>(m);
        kzero<<<BSZ, 256>>>(missing, m);
        tgemm_sim<<<gs, 256>>>(m);
        ktopk<<<BSZ, 256>>>(m);
    }

    tgemm_bias<<<gp, 256>>>(3, b1);
    kmlp2<<<BSZ, 256>>>(W2, b2, out);
}

// round 11
// speedup vs baseline: 2.3284x; 1.0370x over previous
#include <cuda_runtime.h>
#include <cuda_bf16.h>
#include <math.h>
#include <float.h>
#include <stdint.h>

#define BSZ 8192
#define FDIM 2048
#define DDIM 1024
#define HDIM 3072

typedef __nv_bfloat16 bf16;
typedef __nv_bfloat162 bf162;

// ---------------- scratch ------------------------------------------------------
__device__ float g_proj[(size_t)3 * BSZ * DDIM];             // fp32 proj, filled in place
__device__ __align__(16) bf16 g_Pjh[(size_t)3 * BSZ * DDIM]; // proj hi limbs (kept coherent)
__device__ __align__(16) bf16 g_Pjl[(size_t)3 * BSZ * DDIM]; // proj lo limbs
__device__ __align__(16) bf16 g_Xh[(size_t)3 * BSZ * FDIM];
__device__ __align__(16) bf16 g_Xl[(size_t)3 * BSZ * FDIM];
__device__ __align__(16) bf16 g_Wth[(size_t)3 * DDIM * FDIM]; // W^T limbs [1024][2048]
__device__ __align__(16) bf16 g_Wtl[(size_t)3 * DDIM * FDIM];
__device__ __align__(16) bf16 g_W1th[(size_t)DDIM * HDIM];    // W1^T limbs [1024][3072]
__device__ __align__(16) bf16 g_W1tl[(size_t)DDIM * HDIM];
__device__ float g_S[16777216ull];
__device__ float g_h[(size_t)BSZ * DDIM];
__device__ float g_nrm[BSZ];
__device__ int   g_glist[3][BSZ];
__device__ int   g_qidx[3][BSZ];
__device__ int   g_qrow[3][BSZ];
__device__ int   g_cidx[3][BSZ];
__device__ int   g_crow[3][BSZ];
__device__ int   g_cnt[3][4];

// ---------------- PTX helpers ------------------------------------------------------
__device__ __forceinline__ uint32_t smem_u32(const void* p) {
    uint32_t a;
    asm("{ .reg .u64 t; cvta.to.shared.u64 t, %1; cvt.u32.u64 %0, t; }" : "=r"(a) : "l"(p));
    return a;
}
__device__ __forceinline__ void cpa16(uint32_t dst, const void* src) {
    asm volatile("cp.async.cg.shared.global [%0], [%1], 16;" :: "r"(dst), "l"(src));
}
#define CP_COMMIT() asm volatile("cp.async.commit_group;" ::: "memory")
#define CP_WAIT1()  asm volatile("cp.async.wait_group 1;" ::: "memory")
__device__ __forceinline__ void ldsm4(uint32_t* r, uint32_t addr) {
    asm volatile("ldmatrix.sync.aligned.m8n8.x4.shared.b16 {%0,%1,%2,%3}, [%4];"
                 : "=r"(r[0]), "=r"(r[1]), "=r"(r[2]), "=r"(r[3]) : "r"(addr));
}
__device__ __forceinline__ void mma16(float* d, const uint32_t* a, uint32_t b0, uint32_t b1) {
    asm("mma.sync.aligned.m16n8k16.row.col.f32.bf16.bf16.f32 "
        "{%0,%1,%2,%3}, {%4,%5,%6,%7}, {%8,%9}, {%0,%1,%2,%3};"
        : "+f"(d[0]), "+f"(d[1]), "+f"(d[2]), "+f"(d[3])
        : "r"(a[0]), "r"(a[1]), "r"(a[2]), "r"(a[3]), "r"(b0), "r"(b1));
}
__device__ __forceinline__ bf162 splitlo2(float x, float y, bf162 h) {
    return bf162(__float2bfloat16_rn(x - __bfloat162float(h.x)),
                 __float2bfloat16_rn(y - __bfloat162float(h.y)));
}

// swizzled granule byte offset for (row, 16B-chunk) in a 128row x 32B tile
__device__ __forceinline__ uint32_t gran(int row, int ch) {
    return (uint32_t)((row * 2 + (ch ^ ((row >> 2) & 1))) * 16);
}

// ---------------- GEMM core: CTA 128x128, 8 warps (warp 64x32), k-chunk 16 --------
// 3-stage cp.async pipeline, ONE __syncthreads per chunk, ldmatrix frags,
// 3-term bf16 limb emulation. Stage layout (16KB each):
//   +0 A-hi(4KB) +4096 A-lo +8192 B-hi +12288 B-lo.  Total smem = 48KB.
__device__ __forceinline__ void gemm_core(
    const char* aHi, const char* aLo, size_t aRowOff, int mlp1A,
    const char* bHi, const char* bLo,
    int K, float acc[4][4][4], uint32_t sm0)
{
    const int tid = threadIdx.x, lane = tid & 31, wid = tid >> 5;
    const int wr = wid & 1, wc = wid >> 1;
    const int sr = tid >> 1, sc = tid & 1;
    const uint32_t gOff = gran(sr, sc);
    const uint32_t cB = (uint32_t)sc * 16;
    const int sub = lane >> 3, rl = lane & 7;
    const int lch = sub >> 1, lr8 = (sub & 1) * 8;
    uint32_t ag[4], bg[2];
    #pragma unroll
    for (int i = 0; i < 4; i++) ag[i] = gran(wr * 64 + i * 16 + lr8 + rl, lch);
    #pragma unroll
    for (int g = 0; g < 2; g++) bg[g] = gran(wc * 32 + g * 16 + lr8 + rl, lch);

    const int nch = K / 16;
    auto issue = [&](int ic, uint32_t st) {
        const int kc = ic * 16;
        const char *pa0, *pa1;
        if (!mlp1A) {
            pa0 = aHi + (size_t)kc * 2 + cB;
            pa1 = aLo + (size_t)kc * 2 + cB;
        } else {
            const size_t off = ((size_t)(kc >> 10) * BSZ * DDIM + (size_t)(kc & 1023)) * 2
                             + aRowOff + cB;
            pa0 = aHi + off;
            pa1 = aLo + off;
        }
        cpa16(sm0 + st + gOff, pa0);
        cpa16(sm0 + st + 4096 + gOff, pa1);
        cpa16(sm0 + st + 8192 + gOff, bHi + (size_t)kc * 2 + cB);
        cpa16(sm0 + st + 12288 + gOff, bLo + (size_t)kc * 2 + cB);
        CP_COMMIT();
    };

    issue(0, 0);
    issue(1, 16384);
    int sCur = 0, sNxt = 2;
    for (int ic = 0; ic < nch; ic++) {
        const uint32_t st = (uint32_t)sCur * 16384;
        CP_WAIT1();
        __syncthreads();
        // prefetch chunk ic+2 into stage sNxt (== stage read at ic-1; barrier makes safe)
        if (ic + 2 < nch) issue(ic + 2, (uint32_t)sNxt * 16384);
        uint32_t A[4][4], B[2][4];
        // B-lo, A-hi -> term AhBl
        ldsm4(B[0], sm0 + st + 12288 + bg[0]);
        ldsm4(B[1], sm0 + st + 12288 + bg[1]);
        #pragma unroll
        for (int i = 0; i < 4; i++) ldsm4(A[i], sm0 + st + ag[i]);
        #pragma unroll
        for (int i = 0; i < 4; i++)
            #pragma unroll
            for (int j = 0; j < 4; j++)
                mma16(acc[i][j], A[i], B[j >> 1][j & 1], B[j >> 1][(j & 1) + 2]);
        // B-hi -> term AhBh
        ldsm4(B[0], sm0 + st + 8192 + bg[0]);
        ldsm4(B[1], sm0 + st + 8192 + bg[1]);
        #pragma unroll
        for (int i = 0; i < 4; i++)
            #pragma unroll
            for (int j = 0; j < 4; j++)
                mma16(acc[i][j], A[i], B[j >> 1][j & 1], B[j >> 1][(j & 1) + 2]);
        // A-lo -> term AlBh
        #pragma unroll
        for (int i = 0; i < 4; i++) ldsm4(A[i], sm0 + st + 4096 + ag[i]);
        #pragma unroll
        for (int i = 0; i < 4; i++)
            #pragma unroll
            for (int j = 0; j < 4; j++)
                mma16(acc[i][j], A[i], B[j >> 1][j & 1], B[j >> 1][(j & 1) + 2]);
        if (++sCur == 3) sCur = 0;
        if (++sNxt == 3) sNxt = 0;
    }
}

// ---------------- GEMM + bias(+relu): modes 0..2 = proj[m], 3 = mlp1 -------------
__global__ void __launch_bounds__(256, 2) tgemm_bias(
    int mode, const float* __restrict__ bias)
{
    __shared__ __align__(16) char smraw[49152];
    const uint32_t sm0 = smem_u32(smraw);
    const int m0 = blockIdx.y * 128, n0 = blockIdx.x * 128;
    const int sr = threadIdx.x >> 1;

    const char *aHi, *aLo, *bHi, *bLo;
    size_t aRowOff = 0;
    float* out;
    int K, mlp1A, relu;
    if (mode < 3) {
        const size_t xs = (size_t)mode * BSZ * FDIM + (size_t)(m0 + sr) * FDIM;
        aHi = (const char*)(g_Xh + xs);
        aLo = (const char*)(g_Xl + xs);
        const size_t ws = (size_t)mode * DDIM * FDIM + (size_t)(n0 + sr) * FDIM;
        bHi = (const char*)(g_Wth + ws);
        bLo = (const char*)(g_Wtl + ws);
        out = g_proj + (size_t)mode * BSZ * DDIM;
        K = FDIM; mlp1A = 0; relu = 0;
    } else {
        aHi = (const char*)g_Pjh;
        aLo = (const char*)g_Pjl;
        aRowOff = (size_t)(m0 + sr) * DDIM * 2;
        const size_t ws = (size_t)(n0 + sr) * HDIM;
        bHi = (const char*)(g_W1th + ws);
        bLo = (const char*)(g_W1tl + ws);
        out = g_h;
        K = HDIM; mlp1A = 1; relu = 1;
    }
    float acc[4][4][4] = {};
    gemm_core(aHi, aLo, aRowOff, mlp1A, bHi, bLo, K, acc, sm0);

    const int lane = threadIdx.x & 31, wid = threadIdx.x >> 5;
    const int wr = wid & 1, wc = wid >> 1;
    bf16* ph = g_Pjh + (size_t)mode * BSZ * DDIM;  // unused if mode==3
    bf16* pl = g_Pjl + (size_t)mode * BSZ * DDIM;
    #pragma unroll
    for (int i = 0; i < 4; i++) {
        const int r0 = m0 + wr * 64 + i * 16 + (lane >> 2);
        #pragma unroll
        for (int j = 0; j < 4; j++) {
            const int c = n0 + wc * 32 + j * 8 + (lane & 3) * 2;
            const float2 bv = *(const float2*)(bias + c);
            float2 o0 = make_float2(acc[i][j][0] + bv.x, acc[i][j][1] + bv.y);
            float2 o1 = make_float2(acc[i][j][2] + bv.x, acc[i][j][3] + bv.y);
            if (relu) {
                o0.x = fmaxf(o0.x, 0.f); o0.y = fmaxf(o0.y, 0.f);
                o1.x = fmaxf(o1.x, 0.f); o1.y = fmaxf(o1.y, 0.f);
            }
            *(float2*)(out + (size_t)r0 * DDIM + c) = o0;
            *(float2*)(out + (size_t)(r0 + 8) * DDIM + c) = o1;
            if (mode < 3) {
                bf162 h0(__float2bfloat16_rn(o0.x), __float2bfloat16_rn(o0.y));
                bf162 h1(__float2bfloat16_rn(o1.x), __float2bfloat16_rn(o1.y));
                *(bf162*)(ph + (size_t)r0 * DDIM + c) = h0;
                *(bf162*)(ph + (size_t)(r0 + 8) * DDIM + c) = h1;
                *(bf162*)(pl + (size_t)r0 * DDIM + c) = splitlo2(o0.x, o0.y, h0);
                *(bf162*)(pl + (size_t)(r0 + 8) * DDIM + c) = splitlo2(o1.x, o1.y, h1);
            }
        }
    }
}

// ---------------- sim GEMM: S = (Pq @ Pc^T) scaled by 1/(|q||c|) in epilogue -------
__global__ void __launch_bounds__(256, 2) tgemm_sim(int m) {
    const int M = g_cnt[m][1], N = g_cnt[m][2];
    const int m0 = blockIdx.y * 128, n0 = blockIdx.x * 128;
    if (m0 >= M || n0 >= N) return;
    __shared__ __align__(16) char smraw[49152];
    const uint32_t sm0 = smem_u32(smraw);
    const int tid = threadIdx.x;
    const int sr = tid >> 1;
    const size_t slab = (size_t)m * BSZ * DDIM;

    // per-thread gathered row pointers (OOB -> row 0 of slab; zeroed by scale later)
    const int qi = m0 + sr, ci = n0 + sr;
    const size_t ar = slab + ((qi < M) ? (size_t)g_qrow[m][qi] * DDIM : 0);
    const size_t br = slab + ((ci < N) ? (size_t)g_crow[m][ci] * DDIM : 0);

    float acc[4][4][4] = {};
    gemm_core((const char*)(g_Pjh + ar), (const char*)(g_Pjl + ar), 0, 0,
              (const char*)(g_Pjh + br), (const char*)(g_Pjl + br), DDIM, acc, sm0);

    const int lane = tid & 31, wid = tid >> 5;
    const int wr = wid & 1, wc = wid >> 1;
    // column scales for this thread's 8 columns (2 per j)
    float csc[8];
    #pragma unroll
    for (int j = 0; j < 4; j++) {
        const int c = n0 + wc * 32 + j * 8 + (lane & 3) * 2;
        csc[j * 2]     = (c < N)     ? __fdiv_rn(1.0f, g_nrm[g_cidx[m][c]])     : 0.0f;
        csc[j * 2 + 1] = (c + 1 < N) ? __fdiv_rn(1.0f, g_nrm[g_cidx[m][c + 1]]) : 0.0f;
    }
    #pragma unroll
    for (int i = 0; i < 4; i++) {
        const int r0 = m0 + wr * 64 + i * 16 + (lane >> 2);
        const int r1 = r0 + 8;
        const float s0 = (r0 < M) ? __fdiv_rn(1.0f, g_nrm[g_qidx[m][r0]]) : 0.0f;
        const float s1 = (r1 < M) ? __fdiv_rn(1.0f, g_nrm[g_qidx[m][r1]]) : 0.0f;
        #pragma unroll
        for (int j = 0; j < 4; j++) {
            const int c = n0 + wc * 32 + j * 8 + (lane & 3) * 2;
            if (r0 < M) {
                if (c < N)     g_S[(size_t)r0 * N + c]     = acc[i][j][0] * s0 * csc[j * 2];
                if (c + 1 < N) g_S[(size_t)r0 * N + c + 1] = acc[i][j][1] * s0 * csc[j * 2 + 1];
            }
            if (r1 < M) {
                if (c < N)     g_S[(size_t)r1 * N + c]     = acc[i][j][2] * s1 * csc[j * 2];
                if (c + 1 < N) g_S[(size_t)r1 * N + c + 1] = acc[i][j][3] * s1 * csc[j * 2 + 1];
            }
        }
    }
}

// ---------------- split X into bf16 hi/lo limbs ------------------------------------
__global__ void __launch_bounds__(256) splitX(
    const float* __restrict__ x0, const float* __restrict__ x1, const float* __restrict__ x2)
{
    const int m = blockIdx.y;
    const float* X = (m == 0) ? x0 : ((m == 1) ? x1 : x2);
    const size_t i = (size_t)blockIdx.x * 256 + threadIdx.x;   // float4 index
    float4 v = ((const float4*)X)[i];
    bf162 h0(__float2bfloat16_rn(v.x), __float2bfloat16_rn(v.y));
    bf162 h1(__float2bfloat16_rn(v.z), __float2bfloat16_rn(v.w));
    bf162 l0 = splitlo2(v.x, v.y, h0);
    bf162 l1 = splitlo2(v.z, v.w, h1);
    bf162* dh = (bf162*)(g_Xh + (size_t)m * BSZ * FDIM) + i * 2;
    bf162* dl = (bf162*)(g_Xl + (size_t)m * BSZ * FDIM) + i * 2;
    dh[0] = h0; dh[1] = h1;
    dl[0] = l0; dl[1] = l1;
}

// ---------------- transpose+split weights: W[K][1024] -> Wt limbs [1024][K] --------
__global__ void __launch_bounds__(256) transW(
    const float* __restrict__ W, bf16* __restrict__ Th, bf16* __restrict__ Tl, int K)
{
    __shared__ float t[32][33];
    const int n0 = blockIdx.x * 32, k0 = blockIdx.y * 32;
    const int tx = threadIdx.x & 31, ty = threadIdx.x >> 5;
    #pragma unroll
    for (int j = 0; j < 4; j++)
        t[ty + j * 8][tx] = W[(size_t)(k0 + ty + j * 8) * DDIM + n0 + tx];
    __syncthreads();
    #pragma unroll
    for (int j = 0; j < 4; j++) {
        const int row = ty + j * 8;
        const float v = t[tx][row];
        const bf16 h = __float2bfloat16_rn(v);
        Th[(size_t)(n0 + row) * K + k0 + tx] = h;
        Tl[(size_t)(n0 + row) * K + k0 + tx] =
            __float2bfloat16_rn(v - __bfloat162float(h));
    }
}

// ---------------- setup: masks, scans, compacted index lists -----------------------
__global__ void __launch_bounds__(1024) setup_kernel(const int* __restrict__ missing) {
    __shared__ int sh[1024];
    const int t = threadIdx.x;
    const int base = t * 8;
    for (int m = 0; m < 3; m++) {
        const int tag = m + 1;
        int a[8];
        int cnt = 0;
        #pragma unroll
        for (int j = 0; j < 8; j++) { a[j] = (missing[base + j] != tag) ? 1 : 0; cnt += a[j]; }
        sh[t] = cnt; __syncthreads();
        for (int off = 1; off < 1024; off <<= 1) {
            int v = (t >= off) ? sh[t - off] : 0; __syncthreads();
            sh[t] += v; __syncthreads();
        }
        const int Nb = sh[1023];
        int pos = sh[t] - cnt;
        #pragma unroll
        for (int j = 0; j < 8; j++) if (a[j]) g_glist[m][pos++] = base + j;
        if (t == 0) g_cnt[m][0] = Nb;
        __syncthreads();
        int qf[8]; cnt = 0;
        #pragma unroll
        for (int j = 0; j < 8; j++) {
            qf[j] = ((missing[base + j] == tag) && (base + j < Nb)) ? 1 : 0; cnt += qf[j];
        }
        sh[t] = cnt; __syncthreads();
        for (int off = 1; off < 1024; off <<= 1) {
            int v = (t >= off) ? sh[t - off] : 0; __syncthreads();
            sh[t] += v; __syncthreads();
        }
        const int nq = sh[1023];
        pos = sh[t] - cnt;
        #pragma unroll
        for (int j = 0; j < 8; j++) if (qf[j]) {
            g_qidx[m][pos] = base + j;
            g_qrow[m][pos] = g_glist[m][base + j];
            pos++;
        }
        if (t == 0) g_cnt[m][1] = nq;
        __syncthreads();
        int cf[8]; cnt = 0;
        #pragma unroll
        for (int j = 0; j < 8; j++) { cf[j] = (a[j] && (base + j < Nb)) ? 1 : 0; cnt += cf[j]; }
        sh[t] = cnt; __syncthreads();
        for (int off = 1; off < 1024; off <<= 1) {
            int v = (t >= off) ? sh[t - off] : 0; __syncthreads();
            sh[t] += v; __syncthreads();
        }
        const int nc = sh[1023];
        pos = sh[t] - cnt;
        #pragma unroll
        for (int j = 0; j < 8; j++) if (cf[j]) {
            g_cidx[m][pos] = base + j;
            g_crow[m][pos] = g_glist[m][base + j];
            pos++;
        }
        if (t == 0) g_cnt[m][2] = nc;
        __syncthreads();
    }
}

// ---------------- per-bank-row L2 norms ----------------------------------------------
__global__ void __launch_bounds__(256) knorm(int m) {
    const int i = blockIdx.x;
    if (i >= g_cnt[m][0]) return;
    const int row = g_glist[m][i];
    const float4* p = reinterpret_cast<const float4*>(
        g_proj + (size_t)m * BSZ * DDIM + (size_t)row * DDIM);
    float4 v = p[threadIdx.x];
    float s = v.x * v.x + v.y * v.y + v.z * v.z + v.w * v.w;
    #pragma unroll
    for (int off = 16; off > 0; off >>= 1) s += __shfl_down_sync(0xffffffffu, s, off);
    __shared__ float red[8];
    if ((threadIdx.x & 31) == 0) red[threadIdx.x >> 5] = s;
    __syncthreads();
    if (threadIdx.x == 0) {
        float tot = 0.f;
        #pragma unroll
        for (int w = 0; w < 8; w++) tot += red[w];
        g_nrm[i] = fmaxf(__fsqrt_rn(tot), 1e-8f);
    }
}

// ---------------- zero rows: missing && b >= Nb (fp32 + limbs) ------------------------
__global__ void __launch_bounds__(256) kzero(const int* __restrict__ missing, int m) {
    const int b = blockIdx.x;
    if (missing[b] != m + 1) return;
    if (b < g_cnt[m][0]) return;
    const size_t off = (size_t)m * BSZ * DDIM + (size_t)b * DDIM;
    const int t = threadIdx.x;
    reinterpret_cast<float4*>(g_proj + off)[t] = make_float4(0.f, 0.f, 0.f, 0.f);
    ((uint2*)(g_Pjh + off))[t] = make_uint2(0u, 0u);
    ((uint2*)(g_Pjl + off))[t] = make_uint2(0u, 0u);
}

// ---------------- top-3 + softmax + weighted gather fill (fp32 + limbs) ---------------
__global__ void __launch_bounds__(256) ktopk(int m) {
    const int q = blockIdx.x;
    const int nq = g_cnt[m][1];
    if (q >= nq) return;
    const int nc = g_cnt[m][2];
    const int t = threadIdx.x;
    const size_t slab = (size_t)m * BSZ * DDIM;
    float* __restrict__ projm = g_proj + slab;
    const int qb = g_qidx[m][q];
    float* __restrict__ dst = projm + (size_t)qb * DDIM;
    bf162* __restrict__ dsth = (bf162*)(g_Pjh + slab + (size_t)qb * DDIM);
    bf162* __restrict__ dstl = (bf162*)(g_Pjl + slab + (size_t)qb * DDIM);
    if (nc == 0) {
        reinterpret_cast<float4*>(dst)[t] = make_float4(0.f, 0.f, 0.f, 0.f);
        bf162 z(__float2bfloat16_rn(0.f), __float2bfloat16_rn(0.f));
        dsth[t * 2] = z; dsth[t * 2 + 1] = z;
        dstl[t * 2] = z; dstl[t * 2 + 1] = z;
        return;
    }
    const float NEGINF = -INFINITY;
    const float* __restrict__ Srow = g_S + (size_t)q * nc;
    float v0 = NEGINF, v1 = NEGINF, v2 = NEGINF;
    int   i0 = 0x7fffffff, i1 = 0x7fffffff, i2 = 0x7fffffff;
    for (int c = t; c < nc; c += 256) {
        float v = Srow[c];
        if (v > v2) {
            if (v > v1) {
                if (v > v0) { v2 = v1; i2 = i1; v1 = v0; i1 = i0; v0 = v; i0 = c; }
                else        { v2 = v1; i2 = i1; v1 = v;  i1 = c; }
            } else          { v2 = v;  i2 = c; }
        }
    }
    __shared__ float sv[768];
    __shared__ int   si[768];
    sv[t] = v0; sv[256 + t] = v1; sv[512 + t] = v2;
    si[t] = i0; si[256 + t] = i1; si[512 + t] = i2;
    __syncthreads();
    __shared__ float fw[3];
    __shared__ int   fr[3];
    if (t == 0) {
        float b0 = NEGINF, b1 = NEGINF, b2 = NEGINF;
        int   j0 = 0x7fffffff, j1 = 0x7fffffff, j2 = 0x7fffffff;
        for (int e = 0; e < 768; e++) {
            float v = sv[e]; int c = si[e];
            if ((v > b2) || (v == b2 && c < j2)) {
                if ((v > b1) || (v == b1 && c < j1)) {
                    if ((v > b0) || (v == b0 && c < j0)) {
                        b2 = b1; j2 = j1; b1 = b0; j1 = j0; b0 = v; j0 = c;
                    } else { b2 = b1; j2 = j1; b1 = v; j1 = c; }
                } else     { b2 = v; j2 = c; }
            }
        }
        float w0 = 1.0f;
        float w1 = (b1 == NEGINF) ? 0.f : expf(b1 - b0);
        float w2 = (b2 == NEGINF) ? 0.f : expf(b2 - b0);
        float ws = w0 + w1 + w2;
        fw[0] = __fdiv_rn(w0, ws); fw[1] = __fdiv_rn(w1, ws); fw[2] = __fdiv_rn(w2, ws);
        fr[0] = (j0 == 0x7fffffff) ? 0 : g_crow[m][j0];
        fr[1] = (j1 == 0x7fffffff) ? 0 : g_crow[m][j1];
        fr[2] = (j2 == 0x7fffffff) ? 0 : g_crow[m][j2];
    }
    __syncthreads();
    const float w0 = fw[0], w1 = fw[1], w2 = fw[2];
    float4 a = reinterpret_cast<const float4*>(projm + (size_t)fr[0] * DDIM)[t];
    float4 b = reinterpret_cast<const float4*>(projm + (size_t)fr[1] * DDIM)[t];
    float4 c = reinterpret_cast<const float4*>(projm + (size_t)fr[2] * DDIM)[t];
    float4 o;
    o.x = w0 * a.x + w1 * b.x + w2 * c.x;
    o.y = w0 * a.y + w1 * b.y + w2 * c.y;
    o.z = w0 * a.z + w1 * b.z + w2 * c.z;
    o.w = w0 * a.w + w1 * b.w + w2 * c.w;
    reinterpret_cast<float4*>(dst)[t] = o;
    bf162 h0(__float2bfloat16_rn(o.x), __float2bfloat16_rn(o.y));
    bf162 h1(__float2bfloat16_rn(o.z), __float2bfloat16_rn(o.w));
    dsth[t * 2] = h0; dsth[t * 2 + 1] = h1;
    dstl[t * 2] = splitlo2(o.x, o.y, h0);
    dstl[t * 2 + 1] = splitlo2(o.z, o.w, h1);
}

// ---------------- MLP layer 2: out = h @ W2 + b2 ---------------------------------------
__global__ void __launch_bounds__(256) kmlp2(
    const float* __restrict__ W2, const float* __restrict__ b2, float* __restrict__ out)
{
    const int b = blockIdx.x, t = threadIdx.x;
    float4 h = reinterpret_cast<const float4*>(g_h + (size_t)b * DDIM)[t];
    float4 w = reinterpret_cast<const float4*>(W2)[t];
    float s = h.x * w.x + h.y * w.y + h.z * w.z + h.w * w.w;
    #pragma unroll
    for (int off = 16; off > 0; off >>= 1) s += __shfl_down_sync(0xffffffffu, s, off);
    __shared__ float red[8];
    if ((t & 31) == 0) red[t >> 5] = s;
    __syncthreads();
    if (t == 0) {
        float tot = 0.f;
        #pragma unroll
        for (int wq = 0; wq < 8; wq++) tot += red[wq];
        out[b] = tot + b2[0];
    }
}

// ---------------- launch ----------------------------------------------------------------
extern "C" void kernel_launch(void* const* d_in, const int* in_sizes, int n_in,
                              void* d_out, int out_size) {
    const float* x[3]  = { (const float*)d_in[0], (const float*)d_in[1], (const float*)d_in[2] };
    const int* missing = (const int*)d_in[3];
    const float* W[3]  = { (const float*)d_in[4], (const float*)d_in[6], (const float*)d_in[8] };
    const float* bb[3] = { (const float*)d_in[5], (const float*)d_in[7], (const float*)d_in[9] };
    const float* W1 = (const float*)d_in[10];
    const float* b1 = (const float*)d_in[11];
    const float* W2 = (const float*)d_in[12];
    const float* b2 = (const float*)d_in[13];
    float* out = (float*)d_out;

    bf16 *wth, *wtl, *w1th, *w1tl;
    cudaGetSymbolAddress((void**)&wth, g_Wth);
    cudaGetSymbolAddress((void**)&wtl, g_Wtl);
    cudaGetSymbolAddress((void**)&w1th, g_W1th);
    cudaGetSymbolAddress((void**)&w1tl, g_W1tl);

    splitX<<<dim3(BSZ * FDIM / 1024, 3), 256>>>(x[0], x[1], x[2]);
    for (int m = 0; m < 3; m++)
        transW<<<dim3(32, FDIM / 32), 256>>>(W[m],
            wth + (size_t)m * DDIM * FDIM, wtl + (size_t)m * DDIM * FDIM, FDIM);
    transW<<<dim3(32, HDIM / 32), 256>>>(W1, w1th, w1tl, HDIM);
    setup_kernel<<<1, 1024>>>(missing);

    dim3 gp(DDIM / 128, BSZ / 128);                 // (8, 64)
    for (int m = 0; m < 3; m++)
        tgemm_bias<<<gp, 256>>>(m, bb[m]);

    dim3 gs(64, 64);                                // early-exit on runtime dims
    for (int m = 0; m < 3; m++) {
        knorm<<<BSZ, 256>>>(m);
        kzero<<<BSZ, 256>>>(missing, m);
        tgemm_sim<<<gs, 256>>>(m);
        ktopk<<<BSZ, 256>>>(m);
    }

    tgemm_bias<<<gp, 256>>>(3, b1);
    kmlp2<<<BSZ, 256>>>(W2, b2, out);
}

// round 15
// speedup vs baseline: 2.3906x; 1.0267x over previous
// R14 = R12 design, third resubmission (R12/R13 failed on harness extraction, not code).
// Theory: GEMMs pinned at ~1.9-2.0 ms (suspected quarter-rate legacy bf16 HMMA on
// sm_103a under the non-'a' PTX target). This round cuts the ~550 us non-GEMM budget:
//   1) eliminate fp32 g_proj entirely - all consumers use the bf16 limb pair
//      (h+l reconstructs to 2^-18 relative), saving ~120 MB DRAM traffic.
//   2) fuse per-modality small kernels (knorm/kzero/sim/ktopk) into single launches
//      with a modality grid axis; sim gets per-modality S slabs (g_S0/1/2) because
//      modalities now run concurrently.
//   3) launch order puts the first proj GEMM at launch #6 so ncu -s 5 -c 1 samples it.
// Prediction: dur_us 2539 -> ~2350-2450; rel_err ~1.6e-5; ncu shows tgemm_bias.
#include <cuda_runtime.h>
#include <cuda_bf16.h>
#include <math.h>
#include <float.h>
#include <stdint.h>

#define BSZ 8192
#define FDIM 2048
#define DDIM 1024
#define HDIM 3072

typedef __nv_bfloat16 bf16;
typedef __nv_bfloat162 bf162;

__device__ __align__(16) bf16 g_Pjh[(size_t)3 * BSZ * DDIM];
__device__ __align__(16) bf16 g_Pjl[(size_t)3 * BSZ * DDIM];
__device__ __align__(16) bf16 g_Xh[(size_t)3 * BSZ * FDIM];
__device__ __align__(16) bf16 g_Xl[(size_t)3 * BSZ * FDIM];
__device__ __align__(16) bf16 g_Wth[(size_t)3 * DDIM * FDIM];
__device__ __align__(16) bf16 g_Wtl[(size_t)3 * DDIM * FDIM];
__device__ __align__(16) bf16 g_W1th[(size_t)DDIM * HDIM];
__device__ __align__(16) bf16 g_W1tl[(size_t)DDIM * HDIM];
__device__ float g_S0[16777216ull];
__device__ float g_S1[16777216ull];
__device__ float g_S2[16777216ull];
__device__ float g_h[(size_t)BSZ * DDIM];
__device__ float g_nrm[3][BSZ];
__device__ int   g_glist[3][BSZ];
__device__ int   g_qidx[3][BSZ];
__device__ int   g_qrow[3][BSZ];
__device__ int   g_cidx[3][BSZ];
__device__ int   g_crow[3][BSZ];
__device__ int   g_cnt[3][4];

__device__ __forceinline__ float* Sslab(int m) {
    return (m == 0) ? g_S0 : ((m == 1) ? g_S1 : g_S2);
}

__device__ __forceinline__ uint32_t smem_u32(const void* p) {
    uint32_t a;
    asm("{ .reg .u64 t; cvta.to.shared.u64 t, %1; cvt.u32.u64 %0, t; }" : "=r"(a) : "l"(p));
    return a;
}
__device__ __forceinline__ void cpa16(uint32_t dst, const void* src) {
    asm volatile("cp.async.cg.shared.global [%0], [%1], 16;" :: "r"(dst), "l"(src));
}
#define CP_COMMIT() asm volatile("cp.async.commit_group;" ::: "memory")
#define CP_WAIT1()  asm volatile("cp.async.wait_group 1;" ::: "memory")
__device__ __forceinline__ void ldsm4(uint32_t* r, uint32_t addr) {
    asm volatile("ldmatrix.sync.aligned.m8n8.x4.shared.b16 {%0,%1,%2,%3}, [%4];"
                 : "=r"(r[0]), "=r"(r[1]), "=r"(r[2]), "=r"(r[3]) : "r"(addr));
}
__device__ __forceinline__ void mma16(float* d, const uint32_t* a, uint32_t b0, uint32_t b1) {
    asm("mma.sync.aligned.m16n8k16.row.col.f32.bf16.bf16.f32 "
        "{%0,%1,%2,%3}, {%4,%5,%6,%7}, {%8,%9}, {%0,%1,%2,%3};"
        : "+f"(d[0]), "+f"(d[1]), "+f"(d[2]), "+f"(d[3])
        : "r"(a[0]), "r"(a[1]), "r"(a[2]), "r"(a[3]), "r"(b0), "r"(b1));
}
__device__ __forceinline__ bf162 splitlo2(float x, float y, bf162 h) {
    return bf162(__float2bfloat16_rn(x - __bfloat162float(h.x)),
                 __float2bfloat16_rn(y - __bfloat162float(h.y)));
}
__device__ __forceinline__ void recon4(uint2 hh, uint2 ll, float* o) {
    bf162 h0 = *reinterpret_cast<bf162*>(&hh.x), h1 = *reinterpret_cast<bf162*>(&hh.y);
    bf162 l0 = *reinterpret_cast<bf162*>(&ll.x), l1 = *reinterpret_cast<bf162*>(&ll.y);
    o[0] = __bfloat162float(h0.x) + __bfloat162float(l0.x);
    o[1] = __bfloat162float(h0.y) + __bfloat162float(l0.y);
    o[2] = __bfloat162float(h1.x) + __bfloat162float(l1.x);
    o[3] = __bfloat162float(h1.y) + __bfloat162float(l1.y);
}
__device__ __forceinline__ uint32_t gran(int row, int ch) {
    return (uint32_t)((row * 2 + (ch ^ ((row >> 2) & 1))) * 16);
}

// GEMM core: CTA 128x128, 8 warps (warp 64x32), k-chunk 16, 3-stage cp.async,
// one __syncthreads per chunk, ldmatrix frags, 3-term bf16 limb emulation.
// Stage = 16KB {A-hi, A-lo, B-hi, B-lo}; smem total 48KB.
__device__ __forceinline__ void gemm_core(
    const char* aHi, const char* aLo, size_t aRowOff, int mlp1A,
    const char* bHi, const char* bLo,
    int K, float acc[4][4][4], uint32_t sm0)
{
    const int tid = threadIdx.x, lane = tid & 31, wid = tid >> 5;
    const int wr = wid & 1, wc = wid >> 1;
    const int sr = tid >> 1, sc = tid & 1;
    const uint32_t gOff = gran(sr, sc);
    const uint32_t cB = (uint32_t)sc * 16;
    const int sub = lane >> 3, rl = lane & 7;
    const int lch = sub >> 1, lr8 = (sub & 1) * 8;
    uint32_t ag[4], bg[2];
    #pragma unroll
    for (int i = 0; i < 4; i++) ag[i] = gran(wr * 64 + i * 16 + lr8 + rl, lch);
    #pragma unroll
    for (int g = 0; g < 2; g++) bg[g] = gran(wc * 32 + g * 16 + lr8 + rl, lch);

    const int nch = K / 16;
    auto issue = [&](int ic, uint32_t st) {
        const int kc = ic * 16;
        const char *pa0, *pa1;
        if (!mlp1A) {
            pa0 = aHi + (size_t)kc * 2 + cB;
            pa1 = aLo + (size_t)kc * 2 + cB;
        } else {
            const size_t off = ((size_t)(kc >> 10) * BSZ * DDIM + (size_t)(kc & 1023)) * 2
                             + aRowOff + cB;
            pa0 = aHi + off;
            pa1 = aLo + off;
        }
        cpa16(sm0 + st + gOff, pa0);
        cpa16(sm0 + st + 4096 + gOff, pa1);
        cpa16(sm0 + st + 8192 + gOff, bHi + (size_t)kc * 2 + cB);
        cpa16(sm0 + st + 12288 + gOff, bLo + (size_t)kc * 2 + cB);
        CP_COMMIT();
    };

    issue(0, 0);
    issue(1, 16384);
    int sCur = 0, sNxt = 2;
    for (int ic = 0; ic < nch; ic++) {
        const uint32_t st = (uint32_t)sCur * 16384;
        CP_WAIT1();
        __syncthreads();
        if (ic + 2 < nch) issue(ic + 2, (uint32_t)sNxt * 16384);
        uint32_t A[4][4], B[2][4];
        ldsm4(B[0], sm0 + st + 12288 + bg[0]);
        ldsm4(B[1], sm0 + st + 12288 + bg[1]);
        #pragma unroll
        for (int i = 0; i < 4; i++) ldsm4(A[i], sm0 + st + ag[i]);
        #pragma unroll
        for (int i = 0; i < 4; i++)
            #pragma unroll
            for (int j = 0; j < 4; j++)
                mma16(acc[i][j], A[i], B[j >> 1][j & 1], B[j >> 1][(j & 1) + 2]);
        ldsm4(B[0], sm0 + st + 8192 + bg[0]);
        ldsm4(B[1], sm0 + st + 8192 + bg[1]);
        #pragma unroll
        for (int i = 0; i < 4; i++)
            #pragma unroll
            for (int j = 0; j < 4; j++)
                mma16(acc[i][j], A[i], B[j >> 1][j & 1], B[j >> 1][(j & 1) + 2]);
        #pragma unroll
        for (int i = 0; i < 4; i++) ldsm4(A[i], sm0 + st + 4096 + ag[i]);
        #pragma unroll
        for (int i = 0; i < 4; i++)
            #pragma unroll
            for (int j = 0; j < 4; j++)
                mma16(acc[i][j], A[i], B[j >> 1][j & 1], B[j >> 1][(j & 1) + 2]);
        if (++sCur == 3) sCur = 0;
        if (++sNxt == 3) sNxt = 0;
    }
}

// GEMM + bias(+relu): modes 0..2 = proj[m] (writes limbs), 3 = mlp1 (writes g_h)
__global__ void __launch_bounds__(256, 2) tgemm_bias(
    int mode, const float* __restrict__ bias)
{
    __shared__ __align__(16) char smraw[49152];
    const uint32_t sm0 = smem_u32(smraw);
    const int m0 = blockIdx.y * 128, n0 = blockIdx.x * 128;
    const int sr = threadIdx.x >> 1;

    const char *aHi, *aLo, *bHi, *bLo;
    size_t aRowOff = 0;
    int K, mlp1A, relu;
    if (mode < 3) {
        const size_t xs = (size_t)mode * BSZ * FDIM + (size_t)(m0 + sr) * FDIM;
        aHi = (const char*)(g_Xh + xs);
        aLo = (const char*)(g_Xl + xs);
        const size_t ws = (size_t)mode * DDIM * FDIM + (size_t)(n0 + sr) * FDIM;
        bHi = (const char*)(g_Wth + ws);
        bLo = (const char*)(g_Wtl + ws);
        K = FDIM; mlp1A = 0; relu = 0;
    } else {
        aHi = (const char*)g_Pjh;
        aLo = (const char*)g_Pjl;
        aRowOff = (size_t)(m0 + sr) * DDIM * 2;
        const size_t ws = (size_t)(n0 + sr) * HDIM;
        bHi = (const char*)(g_W1th + ws);
        bLo = (const char*)(g_W1tl + ws);
        K = HDIM; mlp1A = 1; relu = 1;
    }
    float acc[4][4][4] = {};
    gemm_core(aHi, aLo, aRowOff, mlp1A, bHi, bLo, K, acc, sm0);

    const int lane = threadIdx.x & 31, wid = threadIdx.x >> 5;
    const int wr = wid & 1, wc = wid >> 1;
    bf16* ph = g_Pjh + (size_t)mode * BSZ * DDIM;
    bf16* pl = g_Pjl + (size_t)mode * BSZ * DDIM;
    #pragma unroll
    for (int i = 0; i < 4; i++) {
        const int r0 = m0 + wr * 64 + i * 16 + (lane >> 2);
        #pragma unroll
        for (int j = 0; j < 4; j++) {
            const int c = n0 + wc * 32 + j * 8 + (lane & 3) * 2;
            const float2 bv = *(const float2*)(bias + c);
            float2 o0 = make_float2(acc[i][j][0] + bv.x, acc[i][j][1] + bv.y);
            float2 o1 = make_float2(acc[i][j][2] + bv.x, acc[i][j][3] + bv.y);
            if (relu) {
                o0.x = fmaxf(o0.x, 0.f); o0.y = fmaxf(o0.y, 0.f);
                o1.x = fmaxf(o1.x, 0.f); o1.y = fmaxf(o1.y, 0.f);
                *(float2*)(g_h + (size_t)r0 * DDIM + c) = o0;
                *(float2*)(g_h + (size_t)(r0 + 8) * DDIM + c) = o1;
            } else {
                bf162 h0(__float2bfloat16_rn(o0.x), __float2bfloat16_rn(o0.y));
                bf162 h1(__float2bfloat16_rn(o1.x), __float2bfloat16_rn(o1.y));
                *(bf162*)(ph + (size_t)r0 * DDIM + c) = h0;
                *(bf162*)(ph + (size_t)(r0 + 8) * DDIM + c) = h1;
                *(bf162*)(pl + (size_t)r0 * DDIM + c) = splitlo2(o0.x, o0.y, h0);
                *(bf162*)(pl + (size_t)(r0 + 8) * DDIM + c) = splitlo2(o1.x, o1.y, h1);
            }
        }
    }
}

// sim GEMM (all modalities): cosine via epilogue scaling by 1/(|q||c|)
__global__ void __launch_bounds__(256, 2) tgemm_sim() {
    const int m = blockIdx.z;
    const int M = g_cnt[m][1], N = g_cnt[m][2];
    const int m0 = blockIdx.y * 128, n0 = blockIdx.x * 128;
    if (m0 >= M || n0 >= N) return;
    __shared__ __align__(16) char smraw[49152];
    const uint32_t sm0 = smem_u32(smraw);
    const int tid = threadIdx.x;
    const int sr = tid >> 1;
    const size_t slab = (size_t)m * BSZ * DDIM;

    const int qi = m0 + sr, ci = n0 + sr;
    const size_t ar = slab + ((qi < M) ? (size_t)g_qrow[m][qi] * DDIM : 0);
    const size_t br = slab + ((ci < N) ? (size_t)g_crow[m][ci] * DDIM : 0);

    float acc[4][4][4] = {};
    gemm_core((const char*)(g_Pjh + ar), (const char*)(g_Pjl + ar), 0, 0,
              (const char*)(g_Pjh + br), (const char*)(g_Pjl + br), DDIM, acc, sm0);

    const int lane = tid & 31, wid = tid >> 5;
    const int wr = wid & 1, wc = wid >> 1;
    float* __restrict__ Sp = Sslab(m);
    float csc[8];
    #pragma unroll
    for (int j = 0; j < 4; j++) {
        const int c = n0 + wc * 32 + j * 8 + (lane & 3) * 2;
        csc[j * 2]     = (c < N)     ? __fdiv_rn(1.0f, g_nrm[m][g_cidx[m][c]])     : 0.0f;
        csc[j * 2 + 1] = (c + 1 < N) ? __fdiv_rn(1.0f, g_nrm[m][g_cidx[m][c + 1]]) : 0.0f;
    }
    #pragma unroll
    for (int i = 0; i < 4; i++) {
        const int r0 = m0 + wr * 64 + i * 16 + (lane >> 2);
        const int r1 = r0 + 8;
        const float s0 = (r0 < M) ? __fdiv_rn(1.0f, g_nrm[m][g_qidx[m][r0]]) : 0.0f;
        const float s1 = (r1 < M) ? __fdiv_rn(1.0f, g_nrm[m][g_qidx[m][r1]]) : 0.0f;
        #pragma unroll
        for (int j = 0; j < 4; j++) {
            const int c = n0 + wc * 32 + j * 8 + (lane & 3) * 2;
            if (r0 < M) {
                if (c < N)     Sp[(size_t)r0 * N + c]     = acc[i][j][0] * s0 * csc[j * 2];
                if (c + 1 < N) Sp[(size_t)r0 * N + c + 1] = acc[i][j][1] * s0 * csc[j * 2 + 1];
            }
            if (r1 < M) {
                if (c < N)     Sp[(size_t)r1 * N + c]     = acc[i][j][2] * s1 * csc[j * 2];
                if (c + 1 < N) Sp[(size_t)r1 * N + c + 1] = acc[i][j][3] * s1 * csc[j * 2 + 1];
            }
        }
    }
}

__global__ void __launch_bounds__(256) splitX(
    const float* __restrict__ x0, const float* __restrict__ x1, const float* __restrict__ x2)
{
    const int m = blockIdx.y;
    const float* X = (m == 0) ? x0 : ((m == 1) ? x1 : x2);
    const size_t i = (size_t)blockIdx.x * 256 + threadIdx.x;
    float4 v = ((const float4*)X)[i];
    bf162 h0(__float2bfloat16_rn(v.x), __float2bfloat16_rn(v.y));
    bf162 h1(__float2bfloat16_rn(v.z), __float2bfloat16_rn(v.w));
    bf162 l0 = splitlo2(v.x, v.y, h0);
    bf162 l1 = splitlo2(v.z, v.w, h1);
    bf162* dh = (bf162*)(g_Xh + (size_t)m * BSZ * FDIM) + i * 2;
    bf162* dl = (bf162*)(g_Xl + (size_t)m * BSZ * FDIM) + i * 2;
    dh[0] = h0; dh[1] = h1;
    dl[0] = l0; dl[1] = l1;
}

__global__ void __launch_bounds__(256) transW(
    const float* __restrict__ W, bf16* __restrict__ Th, bf16* __restrict__ Tl, int K)
{
    __shared__ float t[32][33];
    const int n0 = blockIdx.x * 32, k0 = blockIdx.y * 32;
    const int tx = threadIdx.x & 31, ty = threadIdx.x >> 5;
    #pragma unroll
    for (int j = 0; j < 4; j++)
        t[ty + j * 8][tx] = W[(size_t)(k0 + ty + j * 8) * DDIM + n0 + tx];
    __syncthreads();
    #pragma unroll
    for (int j = 0; j < 4; j++) {
        const int row = ty + j * 8;
        const float v = t[tx][row];
        const bf16 h = __float2bfloat16_rn(v);
        Th[(size_t)(n0 + row) * K + k0 + tx] = h;
        Tl[(size_t)(n0 + row) * K + k0 + tx] =
            __float2bfloat16_rn(v - __bfloat162float(h));
    }
}

__global__ void __launch_bounds__(1024) setup_kernel(const int* __restrict__ missing) {
    __shared__ int sh[1024];
    const int t = threadIdx.x;
    const int base = t * 8;
    for (int m = 0; m < 3; m++) {
        const int tag = m + 1;
        int a[8];
        int cnt = 0;
        #pragma unroll
        for (int j = 0; j < 8; j++) { a[j] = (missing[base + j] != tag) ? 1 : 0; cnt += a[j]; }
        sh[t] = cnt; __syncthreads();
        for (int off = 1; off < 1024; off <<= 1) {
            int v = (t >= off) ? sh[t - off] : 0; __syncthreads();
            sh[t] += v; __syncthreads();
        }
        const int Nb = sh[1023];
        int pos = sh[t] - cnt;
        #pragma unroll
        for (int j = 0; j < 8; j++) if (a[j]) g_glist[m][pos++] = base + j;
        if (t == 0) g_cnt[m][0] = Nb;
        __syncthreads();
        int qf[8]; cnt = 0;
        #pragma unroll
        for (int j = 0; j < 8; j++) {
            qf[j] = ((missing[base + j] == tag) && (base + j < Nb)) ? 1 : 0; cnt += qf[j];
        }
        sh[t] = cnt; __syncthreads();
        for (int off = 1; off < 1024; off <<= 1) {
            int v = (t >= off) ? sh[t - off] : 0; __syncthreads();
            sh[t] += v; __syncthreads();
        }
        const int nq = sh[1023];
        pos = sh[t] - cnt;
        #pragma unroll
        for (int j = 0; j < 8; j++) if (qf[j]) {
            g_qidx[m][pos] = base + j;
            g_qrow[m][pos] = g_glist[m][base + j];
            pos++;
        }
        if (t == 0) g_cnt[m][1] = nq;
        __syncthreads();
        int cf[8]; cnt = 0;
        #pragma unroll
        for (int j = 0; j < 8; j++) { cf[j] = (a[j] && (base + j < Nb)) ? 1 : 0; cnt += cf[j]; }
        sh[t] = cnt; __syncthreads();
        for (int off = 1; off < 1024; off <<= 1) {
            int v = (t >= off) ? sh[t - off] : 0; __syncthreads();
            sh[t] += v; __syncthreads();
        }
        const int nc = sh[1023];
        pos = sh[t] - cnt;
        #pragma unroll
        for (int j = 0; j < 8; j++) if (cf[j]) {
            g_cidx[m][pos] = base + j;
            g_crow[m][pos] = g_glist[m][base + j];
            pos++;
        }
        if (t == 0) g_cnt[m][2] = nc;
        __syncthreads();
    }
}

__global__ void __launch_bounds__(256) knorm() {
    const int m = blockIdx.y, i = blockIdx.x;
    if (i >= g_cnt[m][0]) return;
    const int row = g_glist[m][i];
    const size_t base = (size_t)m * BSZ * DDIM + (size_t)row * DDIM;
    const int t = threadIdx.x;
    uint2 hh = ((const uint2*)(g_Pjh + base))[t];
    uint2 ll = ((const uint2*)(g_Pjl + base))[t];
    float v[4];
    recon4(hh, ll, v);
    float s = v[0] * v[0] + v[1] * v[1] + v[2] * v[2] + v[3] * v[3];
    #pragma unroll
    for (int off = 16; off > 0; off >>= 1) s += __shfl_down_sync(0xffffffffu, s, off);
    __shared__ float red[8];
    if ((t & 31) == 0) red[t >> 5] = s;
    __syncthreads();
    if (t == 0) {
        float tot = 0.f;
        #pragma unroll
        for (int w = 0; w < 8; w++) tot += red[w];
        g_nrm[m][i] = fmaxf(__fsqrt_rn(tot), 1e-8f);
    }
}

__global__ void __launch_bounds__(256) kzero(const int* __restrict__ missing) {
    const int m = blockIdx.y, b = blockIdx.x;
    if (missing[b] != m + 1) return;
    if (b < g_cnt[m][0]) return;
    const size_t off = (size_t)m * BSZ * DDIM + (size_t)b * DDIM;
    const int t = threadIdx.x;
    ((uint2*)(g_Pjh + off))[t] = make_uint2(0u, 0u);
    ((uint2*)(g_Pjl + off))[t] = make_uint2(0u, 0u);
}

__global__ void __launch_bounds__(256) ktopk() {
    const int m = blockIdx.y, q = blockIdx.x;
    const int nq = g_cnt[m][1];
    if (q >= nq) return;
    const int nc = g_cnt[m][2];
    const int t = threadIdx.x;
    const size_t slab = (size_t)m * BSZ * DDIM;
    const int qb = g_qidx[m][q];
    uint2* __restrict__ dsth = (uint2*)(g_Pjh + slab + (size_t)qb * DDIM);
    uint2* __restrict__ dstl = (uint2*)(g_Pjl + slab + (size_t)qb * DDIM);
    if (nc == 0) {
        dsth[t] = make_uint2(0u, 0u);
        dstl[t] = make_uint2(0u, 0u);
        return;
    }
    const float NEGINF = -INFINITY;
    const float* __restrict__ Srow = Sslab(m) + (size_t)q * nc;
    float v0 = NEGINF, v1 = NEGINF, v2 = NEGINF;
    int   i0 = 0x7fffffff, i1 = 0x7fffffff, i2 = 0x7fffffff;
    for (int c = t; c < nc; c += 256) {
        float v = Srow[c];
        if (v > v2) {
            if (v > v1) {
                if (v > v0) { v2 = v1; i2 = i1; v1 = v0; i1 = i0; v0 = v; i0 = c; }
                else        { v2 = v1; i2 = i1; v1 = v;  i1 = c; }
            } else          { v2 = v;  i2 = c; }
        }
    }
    __shared__ float sv[768];
    __shared__ int   si[768];
    sv[t] = v0; sv[256 + t] = v1; sv[512 + t] = v2;
    si[t] = i0; si[256 + t] = i1; si[512 + t] = i2;
    __syncthreads();
    __shared__ float fw[3];
    __shared__ int   fr[3];
    if (t == 0) {
        float b0 = NEGINF, b1 = NEGINF, b2 = NEGINF;
        int   j0 = 0x7fffffff, j1 = 0x7fffffff, j2 = 0x7fffffff;
        for (int e = 0; e < 768; e++) {
            float v = sv[e]; int c = si[e];
            if ((v > b2) || (v == b2 && c < j2)) {
                if ((v > b1) || (v == b1 && c < j1)) {
                    if ((v > b0) || (v == b0 && c < j0)) {
                        b2 = b1; j2 = j1; b1 = b0; j1 = j0; b0 = v; j0 = c;
                    } else { b2 = b1; j2 = j1; b1 = v; j1 = c; }
                } else     { b2 = v; j2 = c; }
            }
        }
        float w0 = 1.0f;
        float w1 = (b1 == NEGINF) ? 0.f : expf(b1 - b0);
        float w2 = (b2 == NEGINF) ? 0.f : expf(b2 - b0);
        float ws = w0 + w1 + w2;
        fw[0] = __fdiv_rn(w0, ws); fw[1] = __fdiv_rn(w1, ws); fw[2] = __fdiv_rn(w2, ws);
        fr[0] = (j0 == 0x7fffffff) ? 0 : g_crow[m][j0];
        fr[1] = (j1 == 0x7fffffff) ? 0 : g_crow[m][j1];
        fr[2] = (j2 == 0x7fffffff) ? 0 : g_crow[m][j2];
    }
    __syncthreads();
    const float w0 = fw[0], w1 = fw[1], w2 = fw[2];
    const bf16* ph = g_Pjh + slab;
    const bf16* pl = g_Pjl + slab;
    float a[4], b[4], c[4];
    recon4(((const uint2*)(ph + (size_t)fr[0] * DDIM))[t],
           ((const uint2*)(pl + (size_t)fr[0] * DDIM))[t], a);
    recon4(((const uint2*)(ph + (size_t)fr[1] * DDIM))[t],
           ((const uint2*)(pl + (size_t)fr[1] * DDIM))[t], b);
    recon4(((const uint2*)(ph + (size_t)fr[2] * DDIM))[t],
           ((const uint2*)(pl + (size_t)fr[2] * DDIM))[t], c);
    float o[4];
    #pragma unroll
    for (int e = 0; e < 4; e++) o[e] = w0 * a[e] + w1 * b[e] + w2 * c[e];
    bf162 h0(__float2bfloat16_rn(o[0]), __float2bfloat16_rn(o[1]));
    bf162 h1(__float2bfloat16_rn(o[2]), __float2bfloat16_rn(o[3]));
    bf162 l0 = splitlo2(o[0], o[1], h0);
    bf162 l1 = splitlo2(o[2], o[3], h1);
    uint2 oh, ol;
    oh.x = *reinterpret_cast<uint32_t*>(&h0); oh.y = *reinterpret_cast<uint32_t*>(&h1);
    ol.x = *reinterpret_cast<uint32_t*>(&l0); ol.y = *reinterpret_cast<uint32_t*>(&l1);
    dsth[t] = oh;
    dstl[t] = ol;
}

__global__ void __launch_bounds__(256) kmlp2(
    const float* __restrict__ W2, const float* __restrict__ b2, float* __restrict__ out)
{
    const int b = blockIdx.x, t = threadIdx.x;
    float4 h = reinterpret_cast<const float4*>(g_h + (size_t)b * DDIM)[t];
    float4 w = reinterpret_cast<const float4*>(W2)[t];
    float s = h.x * w.x + h.y * w.y + h.z * w.z + h.w * w.w;
    #pragma unroll
    for (int off = 16; off > 0; off >>= 1) s += __shfl_down_sync(0xffffffffu, s, off);
    __shared__ float red[8];
    if ((t & 31) == 0) red[t >> 5] = s;
    __syncthreads();
    if (t == 0) {
        float tot = 0.f;
        #pragma unroll
        for (int wq = 0; wq < 8; wq++) tot += red[wq];
        out[b] = tot + b2[0];
    }
}

extern "C" void kernel_launch(void* const* d_in, const int* in_sizes, int n_in,
                              void* d_out, int out_size) {
    const float* x[3]  = { (const float*)d_in[0], (const float*)d_in[1], (const float*)d_in[2] };
    const int* missing = (const int*)d_in[3];
    const float* W[3]  = { (const float*)d_in[4], (const float*)d_in[6], (const float*)d_in[8] };
    const float* bb[3] = { (const float*)d_in[5], (const float*)d_in[7], (const float*)d_in[9] };
    const float* W1 = (const float*)d_in[10];
    const float* b1 = (const float*)d_in[11];
    const float* W2 = (const float*)d_in[12];
    const float* b2 = (const float*)d_in[13];
    float* out = (float*)d_out;

    bf16 *wth, *wtl, *w1th, *w1tl;
    cudaGetSymbolAddress((void**)&wth, g_Wth);
    cudaGetSymbolAddress((void**)&wtl, g_Wtl);
    cudaGetSymbolAddress((void**)&w1th, g_W1th);
    cudaGetSymbolAddress((void**)&w1tl, g_W1tl);

    // launches 1-5 (ncu -s 5 -c 1 then captures launch 6 = first proj GEMM)
    splitX<<<dim3(BSZ * FDIM / 1024, 3), 256>>>(x[0], x[1], x[2]);
    for (int m = 0; m < 3; m++)
        transW<<<dim3(32, FDIM / 32), 256>>>(W[m],
            wth + (size_t)m * DDIM * FDIM, wtl + (size_t)m * DDIM * FDIM, FDIM);
    transW<<<dim3(32, HDIM / 32), 256>>>(W1, w1th, w1tl, HDIM);

    dim3 gp(DDIM / 128, BSZ / 128);
    for (int m = 0; m < 3; m++)
        tgemm_bias<<<gp, 256>>>(m, bb[m]);

    setup_kernel<<<1, 1024>>>(missing);
    knorm<<<dim3(BSZ, 3), 256>>>();
    kzero<<<dim3(BSZ, 3), 256>>>(missing);
    tgemm_sim<<<dim3(64, 64, 3), 256>>>();
    ktopk<<<dim3(BSZ, 3), 256>>>();

    tgemm_bias<<<gp, 256>>>(3, b1);
    kmlp2<<<BSZ, 256>>>(W2, b2, out);
}

// round 16
// speedup vs baseline: 2.6098x; 1.0917x over previous
// R16: R14 base + (1) proj GEMMs fused into one z=3 launch (wave-quantization fix),
// (2) ktopk two-level top-3 merge, (3) knorm+kzero fused. GEMM core unchanged
// (empirically pinned at ~240 TF/s of limb-work; no ncu evidence to justify surgery).
// Prediction: 2473 -> ~2390-2430 us, rel_err ~1.6e-5.
#include <cuda_runtime.h>
#include <cuda_bf16.h>
#include <math.h>
#include <float.h>
#include <stdint.h>

#define BSZ 8192
#define FDIM 2048
#define DDIM 1024
#define HDIM 3072

typedef __nv_bfloat16 bf16;
typedef __nv_bfloat162 bf162;

__device__ __align__(16) bf16 g_Pjh[(size_t)3 * BSZ * DDIM];
__device__ __align__(16) bf16 g_Pjl[(size_t)3 * BSZ * DDIM];
__device__ __align__(16) bf16 g_Xh[(size_t)3 * BSZ * FDIM];
__device__ __align__(16) bf16 g_Xl[(size_t)3 * BSZ * FDIM];
__device__ __align__(16) bf16 g_Wth[(size_t)3 * DDIM * FDIM];
__device__ __align__(16) bf16 g_Wtl[(size_t)3 * DDIM * FDIM];
__device__ __align__(16) bf16 g_W1th[(size_t)DDIM * HDIM];
__device__ __align__(16) bf16 g_W1tl[(size_t)DDIM * HDIM];
__device__ float g_S0[16777216ull];
__device__ float g_S1[16777216ull];
__device__ float g_S2[16777216ull];
__device__ float g_h[(size_t)BSZ * DDIM];
__device__ float g_nrm[3][BSZ];
__device__ int   g_glist[3][BSZ];
__device__ int   g_qidx[3][BSZ];
__device__ int   g_qrow[3][BSZ];
__device__ int   g_cidx[3][BSZ];
__device__ int   g_crow[3][BSZ];
__device__ int   g_cnt[3][4];

__device__ __forceinline__ float* Sslab(int m) {
    return (m == 0) ? g_S0 : ((m == 1) ? g_S1 : g_S2);
}

__device__ __forceinline__ uint32_t smem_u32(const void* p) {
    uint32_t a;
    asm("{ .reg .u64 t; cvta.to.shared.u64 t, %1; cvt.u32.u64 %0, t; }" : "=r"(a) : "l"(p));
    return a;
}
__device__ __forceinline__ void cpa16(uint32_t dst, const void* src) {
    asm volatile("cp.async.cg.shared.global [%0], [%1], 16;" :: "r"(dst), "l"(src));
}
#define CP_COMMIT() asm volatile("cp.async.commit_group;" ::: "memory")
#define CP_WAIT1()  asm volatile("cp.async.wait_group 1;" ::: "memory")
__device__ __forceinline__ void ldsm4(uint32_t* r, uint32_t addr) {
    asm volatile("ldmatrix.sync.aligned.m8n8.x4.shared.b16 {%0,%1,%2,%3}, [%4];"
                 : "=r"(r[0]), "=r"(r[1]), "=r"(r[2]), "=r"(r[3]) : "r"(addr));
}
__device__ __forceinline__ void mma16(float* d, const uint32_t* a, uint32_t b0, uint32_t b1) {
    asm("mma.sync.aligned.m16n8k16.row.col.f32.bf16.bf16.f32 "
        "{%0,%1,%2,%3}, {%4,%5,%6,%7}, {%8,%9}, {%0,%1,%2,%3};"
        : "+f"(d[0]), "+f"(d[1]), "+f"(d[2]), "+f"(d[3])
        : "r"(a[0]), "r"(a[1]), "r"(a[2]), "r"(a[3]), "r"(b0), "r"(b1));
}
__device__ __forceinline__ bf162 splitlo2(float x, float y, bf162 h) {
    return bf162(__float2bfloat16_rn(x - __bfloat162float(h.x)),
                 __float2bfloat16_rn(y - __bfloat162float(h.y)));
}
__device__ __forceinline__ void recon4(uint2 hh, uint2 ll, float* o) {
    bf162 h0 = *reinterpret_cast<bf162*>(&hh.x), h1 = *reinterpret_cast<bf162*>(&hh.y);
    bf162 l0 = *reinterpret_cast<bf162*>(&ll.x), l1 = *reinterpret_cast<bf162*>(&ll.y);
    o[0] = __bfloat162float(h0.x) + __bfloat162float(l0.x);
    o[1] = __bfloat162float(h0.y) + __bfloat162float(l0.y);
    o[2] = __bfloat162float(h1.x) + __bfloat162float(l1.x);
    o[3] = __bfloat162float(h1.y) + __bfloat162float(l1.y);
}
__device__ __forceinline__ uint32_t gran(int row, int ch) {
    return (uint32_t)((row * 2 + (ch ^ ((row >> 2) & 1))) * 16);
}

// GEMM core: CTA 128x128, 8 warps (warp 64x32), k-chunk 16, 3-stage cp.async,
// one __syncthreads per chunk, ldmatrix frags, 3-term bf16 limb emulation.
__device__ __forceinline__ void gemm_core(
    const char* aHi, const char* aLo, size_t aRowOff, int mlp1A,
    const char* bHi, const char* bLo,
    int K, float acc[4][4][4], uint32_t sm0)
{
    const int tid = threadIdx.x, lane = tid & 31, wid = tid >> 5;
    const int wr = wid & 1, wc = wid >> 1;
    const int sr = tid >> 1, sc = tid & 1;
    const uint32_t gOff = gran(sr, sc);
    const uint32_t cB = (uint32_t)sc * 16;
    const int sub = lane >> 3, rl = lane & 7;
    const int lch = sub >> 1, lr8 = (sub & 1) * 8;
    uint32_t ag[4], bg[2];
    #pragma unroll
    for (int i = 0; i < 4; i++) ag[i] = gran(wr * 64 + i * 16 + lr8 + rl, lch);
    #pragma unroll
    for (int g = 0; g < 2; g++) bg[g] = gran(wc * 32 + g * 16 + lr8 + rl, lch);

    const int nch = K / 16;
    auto issue = [&](int ic, uint32_t st) {
        const int kc = ic * 16;
        const char *pa0, *pa1;
        if (!mlp1A) {
            pa0 = aHi + (size_t)kc * 2 + cB;
            pa1 = aLo + (size_t)kc * 2 + cB;
        } else {
            const size_t off = ((size_t)(kc >> 10) * BSZ * DDIM + (size_t)(kc & 1023)) * 2
                             + aRowOff + cB;
            pa0 = aHi + off;
            pa1 = aLo + off;
        }
        cpa16(sm0 + st + gOff, pa0);
        cpa16(sm0 + st + 4096 + gOff, pa1);
        cpa16(sm0 + st + 8192 + gOff, bHi + (size_t)kc * 2 + cB);
        cpa16(sm0 + st + 12288 + gOff, bLo + (size_t)kc * 2 + cB);
        CP_COMMIT();
    };

    issue(0, 0);
    issue(1, 16384);
    int sCur = 0, sNxt = 2;
    for (int ic = 0; ic < nch; ic++) {
        const uint32_t st = (uint32_t)sCur * 16384;
        CP_WAIT1();
        __syncthreads();
        if (ic + 2 < nch) issue(ic + 2, (uint32_t)sNxt * 16384);
        uint32_t A[4][4], B[2][4];
        ldsm4(B[0], sm0 + st + 12288 + bg[0]);
        ldsm4(B[1], sm0 + st + 12288 + bg[1]);
        #pragma unroll
        for (int i = 0; i < 4; i++) ldsm4(A[i], sm0 + st + ag[i]);
        #pragma unroll
        for (int i = 0; i < 4; i++)
            #pragma unroll
            for (int j = 0; j < 4; j++)
                mma16(acc[i][j], A[i], B[j >> 1][j & 1], B[j >> 1][(j & 1) + 2]);
        ldsm4(B[0], sm0 + st + 8192 + bg[0]);
        ldsm4(B[1], sm0 + st + 8192 + bg[1]);
        #pragma unroll
        for (int i = 0; i < 4; i++)
            #pragma unroll
            for (int j = 0; j < 4; j++)
                mma16(acc[i][j], A[i], B[j >> 1][j & 1], B[j >> 1][(j & 1) + 2]);
        #pragma unroll
        for (int i = 0; i < 4; i++) ldsm4(A[i], sm0 + st + 4096 + ag[i]);
        #pragma unroll
        for (int i = 0; i < 4; i++)
            #pragma unroll
            for (int j = 0; j < 4; j++)
                mma16(acc[i][j], A[i], B[j >> 1][j & 1], B[j >> 1][(j & 1) + 2]);
        if (++sCur == 3) sCur = 0;
        if (++sNxt == 3) sNxt = 0;
    }
}

// proj GEMMs, all 3 modalities in one launch (blockIdx.z = modality)
__global__ void __launch_bounds__(256, 2) tgemm_proj(
    const float* __restrict__ b0, const float* __restrict__ b1m,
    const float* __restrict__ b2m)
{
    __shared__ __align__(16) char smraw[49152];
    const uint32_t sm0 = smem_u32(smraw);
    const int mode = blockIdx.z;
    const float* bias = (mode == 0) ? b0 : ((mode == 1) ? b1m : b2m);
    const int m0 = blockIdx.y * 128, n0 = blockIdx.x * 128;
    const int sr = threadIdx.x >> 1;

    const size_t xs = (size_t)mode * BSZ * FDIM + (size_t)(m0 + sr) * FDIM;
    const size_t ws = (size_t)mode * DDIM * FDIM + (size_t)(n0 + sr) * FDIM;
    float acc[4][4][4] = {};
    gemm_core((const char*)(g_Xh + xs), (const char*)(g_Xl + xs), 0, 0,
              (const char*)(g_Wth + ws), (const char*)(g_Wtl + ws), FDIM, acc, sm0);

    const int lane = threadIdx.x & 31, wid = threadIdx.x >> 5;
    const int wr = wid & 1, wc = wid >> 1;
    bf16* ph = g_Pjh + (size_t)mode * BSZ * DDIM;
    bf16* pl = g_Pjl + (size_t)mode * BSZ * DDIM;
    #pragma unroll
    for (int i = 0; i < 4; i++) {
        const int r0 = m0 + wr * 64 + i * 16 + (lane >> 2);
        #pragma unroll
        for (int j = 0; j < 4; j++) {
            const int c = n0 + wc * 32 + j * 8 + (lane & 3) * 2;
            const float2 bv = *(const float2*)(bias + c);
            float2 o0 = make_float2(acc[i][j][0] + bv.x, acc[i][j][1] + bv.y);
            float2 o1 = make_float2(acc[i][j][2] + bv.x, acc[i][j][3] + bv.y);
            bf162 h0(__float2bfloat16_rn(o0.x), __float2bfloat16_rn(o0.y));
            bf162 h1(__float2bfloat16_rn(o1.x), __float2bfloat16_rn(o1.y));
            *(bf162*)(ph + (size_t)r0 * DDIM + c) = h0;
            *(bf162*)(ph + (size_t)(r0 + 8) * DDIM + c) = h1;
            *(bf162*)(pl + (size_t)r0 * DDIM + c) = splitlo2(o0.x, o0.y, h0);
            *(bf162*)(pl + (size_t)(r0 + 8) * DDIM + c) = splitlo2(o1.x, o1.y, h1);
        }
    }
}

// mlp1 GEMM: h = relu(concat(projLimbs) @ W1 + b1)
__global__ void __launch_bounds__(256, 2) tgemm_mlp1(const float* __restrict__ bias)
{
    __shared__ __align__(16) char smraw[49152];
    const uint32_t sm0 = smem_u32(smraw);
    const int m0 = blockIdx.y * 128, n0 = blockIdx.x * 128;
    const int sr = threadIdx.x >> 1;

    const size_t ws = (size_t)(n0 + sr) * HDIM;
    float acc[4][4][4] = {};
    gemm_core((const char*)g_Pjh, (const char*)g_Pjl,
              (size_t)(m0 + sr) * DDIM * 2, 1,
              (const char*)(g_W1th + ws), (const char*)(g_W1tl + ws), HDIM, acc, sm0);

    const int lane = threadIdx.x & 31, wid = threadIdx.x >> 5;
    const int wr = wid & 1, wc = wid >> 1;
    #pragma unroll
    for (int i = 0; i < 4; i++) {
        const int r0 = m0 + wr * 64 + i * 16 + (lane >> 2);
        #pragma unroll
        for (int j = 0; j < 4; j++) {
            const int c = n0 + wc * 32 + j * 8 + (lane & 3) * 2;
            const float2 bv = *(const float2*)(bias + c);
            float2 o0 = make_float2(fmaxf(acc[i][j][0] + bv.x, 0.f),
                                    fmaxf(acc[i][j][1] + bv.y, 0.f));
            float2 o1 = make_float2(fmaxf(acc[i][j][2] + bv.x, 0.f),
                                    fmaxf(acc[i][j][3] + bv.y, 0.f));
            *(float2*)(g_h + (size_t)r0 * DDIM + c) = o0;
            *(float2*)(g_h + (size_t)(r0 + 8) * DDIM + c) = o1;
        }
    }
}

// sim GEMM (all modalities): cosine via epilogue scaling by 1/(|q||c|)
__global__ void __launch_bounds__(256, 2) tgemm_sim() {
    const int m = blockIdx.z;
    const int M = g_cnt[m][1], N = g_cnt[m][2];
    const int m0 = blockIdx.y * 128, n0 = blockIdx.x * 128;
    if (m0 >= M || n0 >= N) return;
    __shared__ __align__(16) char smraw[49152];
    const uint32_t sm0 = smem_u32(smraw);
    const int tid = threadIdx.x;
    const int sr = tid >> 1;
    const size_t slab = (size_t)m * BSZ * DDIM;

    const int qi = m0 + sr, ci = n0 + sr;
    const size_t ar = slab + ((qi < M) ? (size_t)g_qrow[m][qi] * DDIM : 0);
    const size_t br = slab + ((ci < N) ? (size_t)g_crow[m][ci] * DDIM : 0);

    float acc[4][4][4] = {};
    gemm_core((const char*)(g_Pjh + ar), (const char*)(g_Pjl + ar), 0, 0,
              (const char*)(g_Pjh + br), (const char*)(g_Pjl + br), DDIM, acc, sm0);

    const int lane = tid & 31, wid = tid >> 5;
    const int wr = wid & 1, wc = wid >> 1;
    float* __restrict__ Sp = Sslab(m);
    float csc[8];
    #pragma unroll
    for (int j = 0; j < 4; j++) {
        const int c = n0 + wc * 32 + j * 8 + (lane & 3) * 2;
        csc[j * 2]     = (c < N)     ? __fdiv_rn(1.0f, g_nrm[m][g_cidx[m][c]])     : 0.0f;
        csc[j * 2 + 1] = (c + 1 < N) ? __fdiv_rn(1.0f, g_nrm[m][g_cidx[m][c + 1]]) : 0.0f;
    }
    #pragma unroll
    for (int i = 0; i < 4; i++) {
        const int r0 = m0 + wr * 64 + i * 16 + (lane >> 2);
        const int r1 = r0 + 8;
        const float s0 = (r0 < M) ? __fdiv_rn(1.0f, g_nrm[m][g_qidx[m][r0]]) : 0.0f;
        const float s1 = (r1 < M) ? __fdiv_rn(1.0f, g_nrm[m][g_qidx[m][r1]]) : 0.0f;
        #pragma unroll
        for (int j = 0; j < 4; j++) {
            const int c = n0 + wc * 32 + j * 8 + (lane & 3) * 2;
            if (r0 < M) {
                if (c < N)     Sp[(size_t)r0 * N + c]     = acc[i][j][0] * s0 * csc[j * 2];
                if (c + 1 < N) Sp[(size_t)r0 * N + c + 1] = acc[i][j][1] * s0 * csc[j * 2 + 1];
            }
            if (r1 < M) {
                if (c < N)     Sp[(size_t)r1 * N + c]     = acc[i][j][2] * s1 * csc[j * 2];
                if (c + 1 < N) Sp[(size_t)r1 * N + c + 1] = acc[i][j][3] * s1 * csc[j * 2 + 1];
            }
        }
    }
}

__global__ void __launch_bounds__(256) splitX(
    const float* __restrict__ x0, const float* __restrict__ x1, const float* __restrict__ x2)
{
    const int m = blockIdx.y;
    const float* X = (m == 0) ? x0 : ((m == 1) ? x1 : x2);
    const size_t i = (size_t)blockIdx.x * 256 + threadIdx.x;
    float4 v = ((const float4*)X)[i];
    bf162 h0(__float2bfloat16_rn(v.x), __float2bfloat16_rn(v.y));
    bf162 h1(__float2bfloat16_rn(v.z), __float2bfloat16_rn(v.w));
    bf162 l0 = splitlo2(v.x, v.y, h0);
    bf162 l1 = splitlo2(v.z, v.w, h1);
    bf162* dh = (bf162*)(g_Xh + (size_t)m * BSZ * FDIM) + i * 2;
    bf162* dl = (bf162*)(g_Xl + (size_t)m * BSZ * FDIM) + i * 2;
    dh[0] = h0; dh[1] = h1;
    dl[0] = l0; dl[1] = l1;
}

__global__ void __launch_bounds__(256) transW(
    const float* __restrict__ W, bf16* __restrict__ Th, bf16* __restrict__ Tl, int K)
{
    __shared__ float t[32][33];
    const int n0 = blockIdx.x * 32, k0 = blockIdx.y * 32;
    const int tx = threadIdx.x & 31, ty = threadIdx.x >> 5;
    #pragma unroll
    for (int j = 0; j < 4; j++)
        t[ty + j * 8][tx] = W[(size_t)(k0 + ty + j * 8) * DDIM + n0 + tx];
    __syncthreads();
    #pragma unroll
    for (int j = 0; j < 4; j++) {
        const int row = ty + j * 8;
        const float v = t[tx][row];
        const bf16 h = __float2bfloat16_rn(v);
        Th[(size_t)(n0 + row) * K + k0 + tx] = h;
        Tl[(size_t)(n0 + row) * K + k0 + tx] =
            __float2bfloat16_rn(v - __bfloat162float(h));
    }
}

__global__ void __launch_bounds__(1024) setup_kernel(const int* __restrict__ missing) {
    __shared__ int sh[1024];
    const int t = threadIdx.x;
    const int base = t * 8;
    for (int m = 0; m < 3; m++) {
        const int tag = m + 1;
        int a[8];
        int cnt = 0;
        #pragma unroll
        for (int j = 0; j < 8; j++) { a[j] = (missing[base + j] != tag) ? 1 : 0; cnt += a[j]; }
        sh[t] = cnt; __syncthreads();
        for (int off = 1; off < 1024; off <<= 1) {
            int v = (t >= off) ? sh[t - off] : 0; __syncthreads();
            sh[t] += v; __syncthreads();
        }
        const int Nb = sh[1023];
        int pos = sh[t] - cnt;
        #pragma unroll
        for (int j = 0; j < 8; j++) if (a[j]) g_glist[m][pos++] = base + j;
        if (t == 0) g_cnt[m][0] = Nb;
        __syncthreads();
        int qf[8]; cnt = 0;
        #pragma unroll
        for (int j = 0; j < 8; j++) {
            qf[j] = ((missing[base + j] == tag) && (base + j < Nb)) ? 1 : 0; cnt += qf[j];
        }
        sh[t] = cnt; __syncthreads();
        for (int off = 1; off < 1024; off <<= 1) {
            int v = (t >= off) ? sh[t - off] : 0; __syncthreads();
            sh[t] += v; __syncthreads();
        }
        const int nq = sh[1023];
        pos = sh[t] - cnt;
        #pragma unroll
        for (int j = 0; j < 8; j++) if (qf[j]) {
            g_qidx[m][pos] = base + j;
            g_qrow[m][pos] = g_glist[m][base + j];
            pos++;
        }
        if (t == 0) g_cnt[m][1] = nq;
        __syncthreads();
        int cf[8]; cnt = 0;
        #pragma unroll
        for (int j = 0; j < 8; j++) { cf[j] = (a[j] && (base + j < Nb)) ? 1 : 0; cnt += cf[j]; }
        sh[t] = cnt; __syncthreads();
        for (int off = 1; off < 1024; off <<= 1) {
            int v = (t >= off) ? sh[t - off] : 0; __syncthreads();
            sh[t] += v; __syncthreads();
        }
        const int nc = sh[1023];
        pos = sh[t] - cnt;
        #pragma unroll
        for (int j = 0; j < 8; j++) if (cf[j]) {
            g_cidx[m][pos] = base + j;
            g_crow[m][pos] = g_glist[m][base + j];
            pos++;
        }
        if (t == 0) g_cnt[m][2] = nc;
        __syncthreads();
    }
}

// fused: per-bank-row L2 norms (bank index i) + zeroing of missing rows with b >= Nb.
// Disjoint row sets (norms read available rows; zeroing writes missing rows) -> safe.
__global__ void __launch_bounds__(256) knz(const int* __restrict__ missing) {
    const int m = blockIdx.y, i = blockIdx.x;
    const int t = threadIdx.x;
    const int Nb = g_cnt[m][0];
    if (i < Nb) {
        const int row = g_glist[m][i];
        const size_t base = (size_t)m * BSZ * DDIM + (size_t)row * DDIM;
        uint2 hh = ((const uint2*)(g_Pjh + base))[t];
        uint2 ll = ((const uint2*)(g_Pjl + base))[t];
        float v[4];
        recon4(hh, ll, v);
        float s = v[0] * v[0] + v[1] * v[1] + v[2] * v[2] + v[3] * v[3];
        #pragma unroll
        for (int off = 16; off > 0; off >>= 1) s += __shfl_down_sync(0xffffffffu, s, off);
        __shared__ float red[8];
        if ((t & 31) == 0) red[t >> 5] = s;
        __syncthreads();
        if (t == 0) {
            float tot = 0.f;
            #pragma unroll
            for (int w = 0; w < 8; w++) tot += red[w];
            g_nrm[m][i] = fmaxf(__fsqrt_rn(tot), 1e-8f);
        }
    }
    // zero role: batch row b == i
    if (missing[i] == m + 1 && i >= Nb) {
        const size_t off = (size_t)m * BSZ * DDIM + (size_t)i * DDIM;
        ((uint2*)(g_Pjh + off))[t] = make_uint2(0u, 0u);
        ((uint2*)(g_Pjl + off))[t] = make_uint2(0u, 0u);
    }
}

__global__ void __launch_bounds__(256) ktopk() {
    const int m = blockIdx.y, q = blockIdx.x;
    const int nq = g_cnt[m][1];
    if (q >= nq) return;
    const int nc = g_cnt[m][2];
    const int t = threadIdx.x;
    const size_t slab = (size_t)m * BSZ * DDIM;
    const int qb = g_qidx[m][q];
    uint2* __restrict__ dsth = (uint2*)(g_Pjh + slab + (size_t)qb * DDIM);
    uint2* __restrict__ dstl = (uint2*)(g_Pjl + slab + (size_t)qb * DDIM);
    if (nc == 0) {
        dsth[t] = make_uint2(0u, 0u);
        dstl[t] = make_uint2(0u, 0u);
        return;
    }
    const float NEGINF = -INFINITY;
    const float* __restrict__ Srow = Sslab(m) + (size_t)q * nc;
    float v0 = NEGINF, v1 = NEGINF, v2 = NEGINF;
    int   i0 = 0x7fffffff, i1 = 0x7fffffff, i2 = 0x7fffffff;
    for (int c = t; c < nc; c += 256) {
        float v = Srow[c];
        if (v > v2) {
            if (v > v1) {
                if (v > v0) { v2 = v1; i2 = i1; v1 = v0; i1 = i0; v0 = v; i0 = c; }
                else        { v2 = v1; i2 = i1; v1 = v;  i1 = c; }
            } else          { v2 = v;  i2 = c; }
        }
    }
    __shared__ float sv[768];
    __shared__ int   si[768];
    sv[t] = v0; sv[256 + t] = v1; sv[512 + t] = v2;
    si[t] = i0; si[256 + t] = i1; si[512 + t] = i2;
    __syncthreads();
    // two-level merge: 8 warps (lane 0) scan 96 entries each, then thread 0 merges 24.
    __shared__ float mv[24];
    __shared__ int   mi[24];
    const int wid = t >> 5, lane = t & 31;
    if (lane == 0) {
        float b0 = NEGINF, b1 = NEGINF, b2 = NEGINF;
        int   j0 = 0x7fffffff, j1 = 0x7fffffff, j2 = 0x7fffffff;
        for (int e = wid * 96; e < wid * 96 + 96; e++) {
            float v = sv[e]; int c = si[e];
            if ((v > b2) || (v == b2 && c < j2)) {
                if ((v > b1) || (v == b1 && c < j1)) {
                    if ((v > b0) || (v == b0 && c < j0)) {
                        b2 = b1; j2 = j1; b1 = b0; j1 = j0; b0 = v; j0 = c;
                    } else { b2 = b1; j2 = j1; b1 = v; j1 = c; }
                } else     { b2 = v; j2 = c; }
            }
        }
        mv[wid * 3]     = b0; mi[wid * 3]     = j0;
        mv[wid * 3 + 1] = b1; mi[wid * 3 + 1] = j1;
        mv[wid * 3 + 2] = b2; mi[wid * 3 + 2] = j2;
    }
    __syncthreads();
    __shared__ float fw[3];
    __shared__ int   fr[3];
    if (t == 0) {
        float b0 = NEGINF, b1 = NEGINF, b2 = NEGINF;
        int   j0 = 0x7fffffff, j1 = 0x7fffffff, j2 = 0x7fffffff;
        for (int e = 0; e < 24; e++) {
            float v = mv[e]; int c = mi[e];
            if ((v > b2) || (v == b2 && c < j2)) {
                if ((v > b1) || (v == b1 && c < j1)) {
                    if ((v > b0) || (v == b0 && c < j0)) {
                        b2 = b1; j2 = j1; b1 = b0; j1 = j0; b0 = v; j0 = c;
                    } else { b2 = b1; j2 = j1; b1 = v; j1 = c; }
                } else     { b2 = v; j2 = c; }
            }
        }
        float w0 = 1.0f;
        float w1 = (b1 == NEGINF) ? 0.f : expf(b1 - b0);
        float w2 = (b2 == NEGINF) ? 0.f : expf(b2 - b0);
        float ws = w0 + w1 + w2;
        fw[0] = __fdiv_rn(w0, ws); fw[1] = __fdiv_rn(w1, ws); fw[2] = __fdiv_rn(w2, ws);
        fr[0] = (j0 == 0x7fffffff) ? 0 : g_crow[m][j0];
        fr[1] = (j1 == 0x7fffffff) ? 0 : g_crow[m][j1];
        fr[2] = (j2 == 0x7fffffff) ? 0 : g_crow[m][j2];
    }
    __syncthreads();
    const float w0 = fw[0], w1 = fw[1], w2 = fw[2];
    const bf16* ph = g_Pjh + slab;
    const bf16* pl = g_Pjl + slab;
    float a[4], b[4], c[4];
    recon4(((const uint2*)(ph + (size_t)fr[0] * DDIM))[t],
           ((const uint2*)(pl + (size_t)fr[0] * DDIM))[t], a);
    recon4(((const uint2*)(ph + (size_t)fr[1] * DDIM))[t],
           ((const uint2*)(pl + (size_t)fr[1] * DDIM))[t], b);
    recon4(((const uint2*)(ph + (size_t)fr[2] * DDIM))[t],
           ((const uint2*)(pl + (size_t)fr[2] * DDIM))[t], c);
    float o[4];
    #pragma unroll
    for (int e = 0; e < 4; e++) o[e] = w0 * a[e] + w1 * b[e] + w2 * c[e];
    bf162 h0(__float2bfloat16_rn(o[0]), __float2bfloat16_rn(o[1]));
    bf162 h1(__float2bfloat16_rn(o[2]), __float2bfloat16_rn(o[3]));
    bf162 l0 = splitlo2(o[0], o[1], h0);
    bf162 l1 = splitlo2(o[2], o[3], h1);
    uint2 oh, ol;
    oh.x = *reinterpret_cast<uint32_t*>(&h0); oh.y = *reinterpret_cast<uint32_t*>(&h1);
    ol.x = *reinterpret_cast<uint32_t*>(&l0); ol.y = *reinterpret_cast<uint32_t*>(&l1);
    dsth[t] = oh;
    dstl[t] = ol;
}

__global__ void __launch_bounds__(256) kmlp2(
    const float* __restrict__ W2, const float* __restrict__ b2, float* __restrict__ out)
{
    const int b = blockIdx.x, t = threadIdx.x;
    float4 h = reinterpret_cast<const float4*>(g_h + (size_t)b * DDIM)[t];
    float4 w = reinterpret_cast<const float4*>(W2)[t];
    float s = h.x * w.x + h.y * w.y + h.z * w.z + h.w * w.w;
    #pragma unroll
    for (int off = 16; off > 0; off >>= 1) s += __shfl_down_sync(0xffffffffu, s, off);
    __shared__ float red[8];
    if ((t & 31) == 0) red[t >> 5] = s;
    __syncthreads();
    if (t == 0) {
        float tot = 0.f;
        #pragma unroll
        for (int wq = 0; wq < 8; wq++) tot += red[wq];
        out[b] = tot + b2[0];
    }
}

extern "C" void kernel_launch(void* const* d_in, const int* in_sizes, int n_in,
                              void* d_out, int out_size) {
    const float* x[3]  = { (const float*)d_in[0], (const float*)d_in[1], (const float*)d_in[2] };
    const int* missing = (const int*)d_in[3];
    const float* W[3]  = { (const float*)d_in[4], (const float*)d_in[6], (const float*)d_in[8] };
    const float* bb[3] = { (const float*)d_in[5], (const float*)d_in[7], (const float*)d_in[9] };
    const float* W1 = (const float*)d_in[10];
    const float* b1 = (const float*)d_in[11];
    const float* W2 = (const float*)d_in[12];
    const float* b2 = (const float*)d_in[13];
    float* out = (float*)d_out;

    bf16 *wth, *wtl, *w1th, *w1tl;
    cudaGetSymbolAddress((void**)&wth, g_Wth);
    cudaGetSymbolAddress((void**)&wtl, g_Wtl);
    cudaGetSymbolAddress((void**)&w1th, g_W1th);
    cudaGetSymbolAddress((void**)&w1tl, g_W1tl);

    splitX<<<dim3(BSZ * FDIM / 1024, 3), 256>>>(x[0], x[1], x[2]);
    for (int m = 0; m < 3; m++)
        transW<<<dim3(32, FDIM / 32), 256>>>(W[m],
            wth + (size_t)m * DDIM * FDIM, wtl + (size_t)m * DDIM * FDIM, FDIM);
    transW<<<dim3(32, HDIM / 32), 256>>>(W1, w1th, w1tl, HDIM);
    setup_kernel<<<1, 1024>>>(missing);

    tgemm_proj<<<dim3(DDIM / 128, BSZ / 128, 3), 256>>>(bb[0], bb[1], bb[2]);

    knz<<<dim3(BSZ, 3), 256>>>(missing);
    tgemm_sim<<<dim3(64, 64, 3), 256>>>();
    ktopk<<<dim3(BSZ, 3), 256>>>();

    tgemm_mlp1<<<dim3(DDIM / 128, BSZ / 128), 256>>>(b1);
    kmlp2<<<BSZ, 256>>>(W2, b2, out);
}